// round 1
// baseline (speedup 1.0000x reference)
#include <cuda_runtime.h>
#include <math.h>

// Problem constants
#define NBATCH 2
#define SEQ    2048
#define NHEAD  16
#define DHEAD  128
#define HID    2048
#define NTOK   4096   // NBATCH*SEQ

// Scratch (device globals — no runtime allocation allowed)
__device__ float g_Q[NBATCH*NHEAD*SEQ*DHEAD];
__device__ float g_K[NBATCH*NHEAD*SEQ*DHEAD];
__device__ float g_V[NBATCH*NHEAD*SEQ*DHEAD];
__device__ float g_ctx[(size_t)NTOK*HID];

// ---------------------------------------------------------------------------
// GEMM: C[m][n] = sum_k A[m][k] * W[n][k]   (A: [4096,2048], W: [2048,2048])
// sel 0/1/2 -> write bhsd layout into g_Q/g_K/g_V; sel 3 -> A = g_ctx, C row-major
// 128x128 tile, BK=16, 256 threads, 8x8 register tile per thread.
// ---------------------------------------------------------------------------
__global__ __launch_bounds__(256, 2)
void gemm_kernel(const float* __restrict__ Ain,
                 const float* __restrict__ W,
                 float* __restrict__ Cout,
                 int sel)
{
    __shared__ float As[16][132];
    __shared__ float Bs[16][132];

    const float* A = (sel == 3) ? (const float*)g_ctx : Ain;
    const int t  = threadIdx.x;
    const int ty = t >> 4;
    const int tx = t & 15;
    const int m0 = blockIdx.y << 7;
    const int n0 = blockIdx.x << 7;

    float acc[8][8];
    #pragma unroll
    for (int i = 0; i < 8; i++)
        #pragma unroll
        for (int j = 0; j < 8; j++)
            acc[i][j] = 0.f;

    for (int k0 = 0; k0 < HID; k0 += 16) {
        __syncthreads();
        #pragma unroll
        for (int rep = 0; rep < 2; rep++) {
            int u   = t + (rep << 8);
            int row = u >> 2;
            int kk  = (u & 3) << 2;
            float4 av = *(const float4*)(A + (size_t)(m0 + row) * HID + k0 + kk);
            As[kk+0][row] = av.x; As[kk+1][row] = av.y;
            As[kk+2][row] = av.z; As[kk+3][row] = av.w;
            float4 bv = *(const float4*)(W + (size_t)(n0 + row) * HID + k0 + kk);
            Bs[kk+0][row] = bv.x; Bs[kk+1][row] = bv.y;
            Bs[kk+2][row] = bv.z; Bs[kk+3][row] = bv.w;
        }
        __syncthreads();
        #pragma unroll
        for (int k = 0; k < 16; k++) {
            float4 a0 = *(const float4*)&As[k][ty*8];
            float4 a1 = *(const float4*)&As[k][ty*8+4];
            float4 b0 = *(const float4*)&Bs[k][tx*8];
            float4 b1 = *(const float4*)&Bs[k][tx*8+4];
            float ar[8] = {a0.x,a0.y,a0.z,a0.w,a1.x,a1.y,a1.z,a1.w};
            float br[8] = {b0.x,b0.y,b0.z,b0.w,b1.x,b1.y,b1.z,b1.w};
            #pragma unroll
            for (int i = 0; i < 8; i++)
                #pragma unroll
                for (int j = 0; j < 8; j++)
                    acc[i][j] = fmaf(ar[i], br[j], acc[i][j]);
        }
    }

    if (sel == 3) {
        #pragma unroll
        for (int i = 0; i < 8; i++) {
            size_t base = (size_t)(m0 + ty*8 + i) * HID + n0 + tx*8;
            *(float4*)&Cout[base]     = make_float4(acc[i][0],acc[i][1],acc[i][2],acc[i][3]);
            *(float4*)&Cout[base + 4] = make_float4(acc[i][4],acc[i][5],acc[i][6],acc[i][7]);
        }
    } else {
        float* outp = (sel == 0) ? g_Q : (sel == 1) ? g_K : g_V;
        const int h  = n0 >> 7;      // 128-wide tile == one head
        const int d0 = tx * 8;
        #pragma unroll
        for (int i = 0; i < 8; i++) {
            int m = m0 + ty*8 + i;
            int b = m >> 11;
            int s = m & (SEQ - 1);
            size_t base = (((size_t)(b*NHEAD + h))*SEQ + s)*DHEAD + d0;
            *(float4*)&outp[base]     = make_float4(acc[i][0],acc[i][1],acc[i][2],acc[i][3]);
            *(float4*)&outp[base + 4] = make_float4(acc[i][4],acc[i][5],acc[i][6],acc[i][7]);
        }
    }
}

// ---------------------------------------------------------------------------
// RoPE: q' = q*cos(f) + rotate_half(q)*sin(f), applied to Q and K in place.
// Each thread handles one (buf, b, h, s, d-pair) with d < 64 -> no races.
// ---------------------------------------------------------------------------
__global__ __launch_bounds__(256)
void rope_kernel(const float* __restrict__ freqs)
{
    int tid = blockIdx.x * 256 + threadIdx.x;   // 2 * 32 * 2048 * 64 = 2^23 threads
    float* buf = (tid >> 22) ? g_K : g_Q;
    int rem = tid & ((1 << 22) - 1);
    int d   = rem & 63;
    int s   = (rem >> 6) & (SEQ - 1);
    int bh  = rem >> 17;
    size_t base = ((size_t)bh * SEQ + s) * DHEAD;
    float f1 = freqs[s*DHEAD + d];
    float f2 = freqs[s*DHEAD + d + 64];
    float x1 = buf[base + d];
    float x2 = buf[base + d + 64];
    buf[base + d]      = x1 * cosf(f1) - x2 * sinf(f1);
    buf[base + d + 64] = x2 * cosf(f2) + x1 * sinf(f2);
}

// ---------------------------------------------------------------------------
// Flash attention: per (b,h), Bq=64 query rows per CTA, loop over Bk=64 key
// tiles, online softmax, O accumulators in registers.
// ---------------------------------------------------------------------------
#define FLASH_SMEM_FLOATS 30400
#define FLASH_SMEM_BYTES  (FLASH_SMEM_FLOATS * 4)

// Load a 64x128 tile transposed into dst[d][row] (stride 68). Mapping keeps
// gmem reads 64B-contiguous per row and smem stores at worst 2-way conflicted.
__device__ __forceinline__ void load_tile_T(const float* __restrict__ src,
                                            float* __restrict__ dst, int t)
{
    #pragma unroll
    for (int rep = 0; rep < 8; rep++) {
        int u   = t + rep * 256;
        int row = (u & 7) | (((u >> 5) & 7) << 3);
        int kf  = (((u >> 3) & 3) << 2) | ((u >> 8) << 4);
        float4 v = *(const float4*)(src + (size_t)row * DHEAD + kf);
        dst[(kf+0)*68 + row] = v.x;
        dst[(kf+1)*68 + row] = v.y;
        dst[(kf+2)*68 + row] = v.z;
        dst[(kf+3)*68 + row] = v.w;
    }
}

__global__ __launch_bounds__(256, 1)
void flash_kernel(const float* __restrict__ mask, const float* __restrict__ alibi)
{
    extern __shared__ float sm[];
    float* Qs  = sm;               // [128][68]  Q^T
    float* Ks  = sm + 8704;        // [128][68]  K^T
    float* Vs  = sm + 17408;       // [64][132]  V natural
    float* Ps  = sm + 25856;       // [64][68]   P^T
    float* m_s = sm + 30208;       // [64]
    float* l_s = m_s + 64;         // [64]
    float* c_s = l_s + 64;         // [64]

    const int t   = threadIdx.x;
    const int qb  = blockIdx.x;
    const int bh  = blockIdx.y;
    const int h   = bh & (NHEAD - 1);
    const int b   = bh >> 4;
    const int qi0 = qb * 64;

    const float* Qp = g_Q + (size_t)bh * SEQ * DHEAD + (size_t)qi0 * DHEAD;
    const float* Kp = g_K + (size_t)bh * SEQ * DHEAD;
    const float* Vp = g_V + (size_t)bh * SEQ * DHEAD;

    load_tile_T(Qp, Qs, t);
    if (t < 64) { m_s[t] = -1e30f; l_s[t] = 0.f; }

    const int ty = t >> 4, tx = t & 15;
    const int i0 = ty * 4, j0 = tx * 4;      // GEMM1 mapping (S tile 64x64)
    const int i2 = (t & 15) * 4;             // GEMM2 mapping (O tile 64x128)
    const int d2 = (t >> 4) * 8;

    float o[4][8];
    #pragma unroll
    for (int i = 0; i < 4; i++)
        #pragma unroll
        for (int dd = 0; dd < 8; dd++)
            o[i][dd] = 0.f;

    const float SCALE = 0.08838834764831845f;  // 1/sqrt(128)

    for (int kb = 0; kb < SEQ / 64; kb++) {
        const int kj0 = kb * 64;
        __syncthreads();   // previous iteration's smem consumers done
        load_tile_T(Kp + (size_t)kj0 * DHEAD, Ks, t);
        #pragma unroll
        for (int rep = 0; rep < 8; rep++) {
            int u = t + rep * 256;
            int row = u >> 5;
            int dk  = (u & 31) << 2;
            *(float4*)&Vs[row*132 + dk] =
                *(const float4*)(Vp + (size_t)(kj0 + row) * DHEAD + dk);
        }
        __syncthreads();

        // S = Q K^T (rank-1 over d)
        float acc[4][4];
        #pragma unroll
        for (int i = 0; i < 4; i++)
            #pragma unroll
            for (int j = 0; j < 4; j++)
                acc[i][j] = 0.f;
        #pragma unroll 4
        for (int d = 0; d < DHEAD; d++) {
            float4 qf = *(const float4*)&Qs[d*68 + i0];
            float4 kf = *(const float4*)&Ks[d*68 + j0];
            float qa[4] = {qf.x,qf.y,qf.z,qf.w};
            float ka[4] = {kf.x,kf.y,kf.z,kf.w};
            #pragma unroll
            for (int i = 0; i < 4; i++)
                #pragma unroll
                for (int j = 0; j < 4; j++)
                    acc[i][j] = fmaf(qa[i], ka[j], acc[i][j]);
        }

        // scores + mask + alibi, row max
        float al[4];
        {
            float4 av = *(const float4*)(alibi + (size_t)h * SEQ + kj0 + j0);
            al[0]=av.x; al[1]=av.y; al[2]=av.z; al[3]=av.w;
        }
        float p[4][4], rmax[4], rsum[4];
        #pragma unroll
        for (int i = 0; i < 4; i++) {
            float4 mv = *(const float4*)(mask + (size_t)(qi0 + i0 + i) * SEQ + kj0 + j0);
            float mr[4] = {mv.x, mv.y, mv.z, mv.w};
            float rm = -1e30f;
            #pragma unroll
            for (int j = 0; j < 4; j++) {
                float v = fmaf(acc[i][j], SCALE, mr[j] + al[j]);
                p[i][j] = v;
                rm = fmaxf(rm, v);
            }
            rmax[i] = rm;
        }
        #pragma unroll
        for (int off = 8; off; off >>= 1)
            #pragma unroll
            for (int i = 0; i < 4; i++)
                rmax[i] = fmaxf(rmax[i], __shfl_xor_sync(0xffffffffu, rmax[i], off));

        // online softmax update (readers/writer of m_s share a warp -> no race)
        float nm[4], cf[4];
        #pragma unroll
        for (int i = 0; i < 4; i++) {
            float om = m_s[i0 + i];
            nm[i] = fmaxf(om, rmax[i]);
            cf[i] = expf(om - nm[i]);
        }
        #pragma unroll
        for (int i = 0; i < 4; i++) {
            float srow = 0.f;
            #pragma unroll
            for (int j = 0; j < 4; j++) {
                float e = expf(p[i][j] - nm[i]);
                Ps[(j0 + j)*68 + i0 + i] = e;
                srow += e;
            }
            rsum[i] = srow;
        }
        #pragma unroll
        for (int off = 8; off; off >>= 1)
            #pragma unroll
            for (int i = 0; i < 4; i++)
                rsum[i] += __shfl_xor_sync(0xffffffffu, rsum[i], off);
        if (tx == 0) {
            #pragma unroll
            for (int i = 0; i < 4; i++) {
                m_s[i0+i] = nm[i];
                l_s[i0+i] = l_s[i0+i] * cf[i] + rsum[i];
                c_s[i0+i] = cf[i];
            }
        }
        __syncthreads();   // Ps + c_s visible

        // O = O*c + P V  (rank-1 over j)
        #pragma unroll
        for (int i = 0; i < 4; i++) {
            float cc = c_s[i2 + i];
            #pragma unroll
            for (int dd = 0; dd < 8; dd++) o[i][dd] *= cc;
        }
        #pragma unroll 2
        for (int j = 0; j < 64; j++) {
            float4 pv = *(const float4*)&Ps[j*68 + i2];
            float4 va = *(const float4*)&Vs[j*132 + d2];
            float4 vb = *(const float4*)&Vs[j*132 + d2 + 4];
            float pa[4] = {pv.x,pv.y,pv.z,pv.w};
            float vr[8] = {va.x,va.y,va.z,va.w,vb.x,vb.y,vb.z,vb.w};
            #pragma unroll
            for (int i = 0; i < 4; i++)
                #pragma unroll
                for (int dd = 0; dd < 8; dd++)
                    o[i][dd] = fmaf(pa[i], vr[dd], o[i][dd]);
        }
    }

    // normalize and write ctx in [tok][h*128+d] layout for the final GEMM
    #pragma unroll
    for (int i = 0; i < 4; i++) {
        float inv = 1.f / l_s[i2 + i];
        int qg = qi0 + i2 + i;
        size_t base = ((size_t)(b*SEQ + qg))*HID + h*DHEAD + d2;
        *(float4*)&g_ctx[base]     = make_float4(o[i][0]*inv, o[i][1]*inv, o[i][2]*inv, o[i][3]*inv);
        *(float4*)&g_ctx[base + 4] = make_float4(o[i][4]*inv, o[i][5]*inv, o[i][6]*inv, o[i][7]*inv);
    }
}

// ---------------------------------------------------------------------------
extern "C" void kernel_launch(void* const* d_in, const int* in_sizes, int n_in,
                              void* d_out, int out_size)
{
    const float* x     = (const float*)d_in[0];
    const float* mask  = (const float*)d_in[1];
    const float* alibi = (const float*)d_in[2];
    const float* freqs = (const float*)d_in[3];
    const float* Wq    = (const float*)d_in[4];
    const float* Wk    = (const float*)d_in[5];
    const float* Wv    = (const float*)d_in[6];
    const float* Wo    = (const float*)d_in[7];
    float* out = (float*)d_out;
    (void)in_sizes; (void)n_in; (void)out_size;

    dim3 gg(HID / 128, NTOK / 128);

    gemm_kernel<<<gg, 256>>>(x, Wq, nullptr, 0);
    gemm_kernel<<<gg, 256>>>(x, Wk, nullptr, 1);
    gemm_kernel<<<gg, 256>>>(x, Wv, nullptr, 2);

    rope_kernel<<<(2*NBATCH*NHEAD*SEQ*64) / 256, 256>>>(freqs);

    cudaFuncSetAttribute(flash_kernel,
                         cudaFuncAttributeMaxDynamicSharedMemorySize,
                         FLASH_SMEM_BYTES);
    flash_kernel<<<dim3(SEQ/64, NBATCH*NHEAD), 256, FLASH_SMEM_BYTES>>>(mask, alibi);

    gemm_kernel<<<gg, 256>>>(nullptr, Wo, out, 3);
}

// round 2
// speedup vs baseline: 1.0598x; 1.0598x over previous
#include <cuda_runtime.h>
#include <math.h>

// Problem constants
#define NBATCH 2
#define SEQ    2048
#define NHEAD  16
#define DHEAD  128
#define HID    2048
#define NTOK   4096   // NBATCH*SEQ

// Scratch (device globals — no runtime allocation allowed)
__device__ float g_Q[NBATCH*NHEAD*SEQ*DHEAD];
__device__ float g_K[NBATCH*NHEAD*SEQ*DHEAD];
__device__ float g_V[NBATCH*NHEAD*SEQ*DHEAD];
__device__ float g_ctx[(size_t)NTOK*HID];

// ---------------------------------------------------------------------------
// Packed f32x2 helpers (sm_103a): dual-rate fp32 FMA, only reachable via PTX.
// ---------------------------------------------------------------------------
typedef unsigned long long u64;

__device__ __forceinline__ u64 f2pack(float lo, float hi) {
    u64 r; asm("mov.b64 %0,{%1,%2};" : "=l"(r) : "f"(lo), "f"(hi)); return r;
}
__device__ __forceinline__ u64 f2bcast(float x) { return f2pack(x, x); }
__device__ __forceinline__ void f2unpack(u64 v, float& lo, float& hi) {
    asm("mov.b64 {%0,%1},%2;" : "=f"(lo), "=f"(hi) : "l"(v));
}
__device__ __forceinline__ u64 f2fma(u64 a, u64 b, u64 c) {
    u64 d; asm("fma.rn.f32x2 %0,%1,%2,%3;" : "=l"(d) : "l"(a), "l"(b), "l"(c));
    return d;
}
__device__ __forceinline__ u64 f2mul(u64 a, u64 b) {
    u64 d; asm("mul.rn.f32x2 %0,%1,%2;" : "=l"(d) : "l"(a), "l"(b));
    return d;
}

// ---------------------------------------------------------------------------
// GEMM: C[m][n] = sum_k A[m][k] * W[n][k]   (A: [4096,2048], W: [2048,2048])
// sel 0/1/2 -> write bhsd layout into g_Q/g_K/g_V; sel 3 -> A = g_ctx, C row-major
// 128x128 tile, BK=16, 256 threads, 8x8 register tile (packed f32x2 along n).
// Global loads for the next K-tile are prefetched into registers during compute.
// ---------------------------------------------------------------------------
__global__ __launch_bounds__(256, 2)
void gemm_kernel(const float* __restrict__ Ain,
                 const float* __restrict__ W,
                 float* __restrict__ Cout,
                 int sel)
{
    __shared__ float As[16][132];
    __shared__ float Bs[16][132];

    const float* A = (sel == 3) ? (const float*)g_ctx : Ain;
    const int t  = threadIdx.x;
    const int ty = t >> 4;
    const int tx = t & 15;
    const int m0 = blockIdx.y << 7;
    const int n0 = blockIdx.x << 7;

    // per-thread gmem load coords (2 reps of 256 threads)
    int rowL[2], kkL[2];
    #pragma unroll
    for (int rep = 0; rep < 2; rep++) {
        int u = t + (rep << 8);
        rowL[rep] = u >> 2;
        kkL[rep]  = (u & 3) << 2;
    }

    u64 accp[8][4];
    #pragma unroll
    for (int i = 0; i < 8; i++)
        #pragma unroll
        for (int j = 0; j < 4; j++)
            accp[i][j] = 0ull;

    // prefetch tile k0=0
    float4 pav[2], pbv[2];
    #pragma unroll
    for (int rep = 0; rep < 2; rep++) {
        pav[rep] = *(const float4*)(A + (size_t)(m0 + rowL[rep]) * HID + kkL[rep]);
        pbv[rep] = *(const float4*)(W + (size_t)(n0 + rowL[rep]) * HID + kkL[rep]);
    }

    for (int k0 = 0; k0 < HID; k0 += 16) {
        // store prefetched tile to smem (transposed)
        #pragma unroll
        for (int rep = 0; rep < 2; rep++) {
            int row = rowL[rep], kk = kkL[rep];
            As[kk+0][row] = pav[rep].x; As[kk+1][row] = pav[rep].y;
            As[kk+2][row] = pav[rep].z; As[kk+3][row] = pav[rep].w;
            Bs[kk+0][row] = pbv[rep].x; Bs[kk+1][row] = pbv[rep].y;
            Bs[kk+2][row] = pbv[rep].z; Bs[kk+3][row] = pbv[rep].w;
        }
        __syncthreads();

        // issue next tile's global loads (overlap with compute)
        if (k0 + 16 < HID) {
            #pragma unroll
            for (int rep = 0; rep < 2; rep++) {
                pav[rep] = *(const float4*)(A + (size_t)(m0 + rowL[rep]) * HID + k0 + 16 + kkL[rep]);
                pbv[rep] = *(const float4*)(W + (size_t)(n0 + rowL[rep]) * HID + k0 + 16 + kkL[rep]);
            }
        }

        #pragma unroll
        for (int k = 0; k < 16; k++) {
            float4 a0 = *(const float4*)&As[k][ty*8];
            float4 a1 = *(const float4*)&As[k][ty*8+4];
            const u64* bq = (const u64*)&Bs[k][tx*8];
            u64 b0 = bq[0], b1 = bq[1], b2 = bq[2], b3 = bq[3];
            u64 ap[8] = { f2bcast(a0.x), f2bcast(a0.y), f2bcast(a0.z), f2bcast(a0.w),
                          f2bcast(a1.x), f2bcast(a1.y), f2bcast(a1.z), f2bcast(a1.w) };
            #pragma unroll
            for (int i = 0; i < 8; i++) {
                accp[i][0] = f2fma(ap[i], b0, accp[i][0]);
                accp[i][1] = f2fma(ap[i], b1, accp[i][1]);
                accp[i][2] = f2fma(ap[i], b2, accp[i][2]);
                accp[i][3] = f2fma(ap[i], b3, accp[i][3]);
            }
        }
        __syncthreads();
    }

    // unpack accumulators
    float acc[8][8];
    #pragma unroll
    for (int i = 0; i < 8; i++)
        #pragma unroll
        for (int j = 0; j < 4; j++)
            f2unpack(accp[i][j], acc[i][2*j], acc[i][2*j+1]);

    if (sel == 3) {
        #pragma unroll
        for (int i = 0; i < 8; i++) {
            size_t base = (size_t)(m0 + ty*8 + i) * HID + n0 + tx*8;
            *(float4*)&Cout[base]     = make_float4(acc[i][0],acc[i][1],acc[i][2],acc[i][3]);
            *(float4*)&Cout[base + 4] = make_float4(acc[i][4],acc[i][5],acc[i][6],acc[i][7]);
        }
    } else {
        float* outp = (sel == 0) ? g_Q : (sel == 1) ? g_K : g_V;
        const int h  = n0 >> 7;      // 128-wide tile == one head
        const int d0 = tx * 8;
        #pragma unroll
        for (int i = 0; i < 8; i++) {
            int m = m0 + ty*8 + i;
            int b = m >> 11;
            int s = m & (SEQ - 1);
            size_t base = (((size_t)(b*NHEAD + h))*SEQ + s)*DHEAD + d0;
            *(float4*)&outp[base]     = make_float4(acc[i][0],acc[i][1],acc[i][2],acc[i][3]);
            *(float4*)&outp[base + 4] = make_float4(acc[i][4],acc[i][5],acc[i][6],acc[i][7]);
        }
    }
}

// ---------------------------------------------------------------------------
// RoPE: q' = q*cos(f) + rotate_half(q)*sin(f), applied to Q and K in place.
// ---------------------------------------------------------------------------
__global__ __launch_bounds__(256)
void rope_kernel(const float* __restrict__ freqs)
{
    int tid = blockIdx.x * 256 + threadIdx.x;
    float* buf = (tid >> 22) ? g_K : g_Q;
    int rem = tid & ((1 << 22) - 1);
    int d   = rem & 63;
    int s   = (rem >> 6) & (SEQ - 1);
    int bh  = rem >> 17;
    size_t base = ((size_t)bh * SEQ + s) * DHEAD;
    float f1 = freqs[s*DHEAD + d];
    float f2 = freqs[s*DHEAD + d + 64];
    float x1 = buf[base + d];
    float x2 = buf[base + d + 64];
    buf[base + d]      = x1 * cosf(f1) - x2 * sinf(f1);
    buf[base + d + 64] = x2 * cosf(f2) + x1 * sinf(f2);
}

// ---------------------------------------------------------------------------
// Flash attention: per (b,h), Bq=64 query rows per CTA, Bk=64 key tiles,
// online softmax, O accumulators in packed f32x2 registers.
// ---------------------------------------------------------------------------
#define FLASH_SMEM_FLOATS 30400
#define FLASH_SMEM_BYTES  (FLASH_SMEM_FLOATS * 4)

__device__ __forceinline__ void load_tile_T(const float* __restrict__ src,
                                            float* __restrict__ dst, int t)
{
    #pragma unroll
    for (int rep = 0; rep < 8; rep++) {
        int u   = t + rep * 256;
        int row = (u & 7) | (((u >> 5) & 7) << 3);
        int kf  = (((u >> 3) & 3) << 2) | ((u >> 8) << 4);
        float4 v = *(const float4*)(src + (size_t)row * DHEAD + kf);
        dst[(kf+0)*68 + row] = v.x;
        dst[(kf+1)*68 + row] = v.y;
        dst[(kf+2)*68 + row] = v.z;
        dst[(kf+3)*68 + row] = v.w;
    }
}

__global__ __launch_bounds__(256, 1)
void flash_kernel(const float* __restrict__ mask, const float* __restrict__ alibi)
{
    extern __shared__ float sm[];
    float* Qs  = sm;               // [128][68]  Q^T
    float* Ks  = sm + 8704;        // [128][68]  K^T
    float* Vs  = sm + 17408;       // [64][132]  V natural
    float* Ps  = sm + 25856;       // [64][68]   P^T
    float* m_s = sm + 30208;       // [64]
    float* l_s = m_s + 64;         // [64]
    float* c_s = l_s + 64;         // [64]

    const int t   = threadIdx.x;
    const int qb  = blockIdx.x;
    const int bh  = blockIdx.y;
    const int h   = bh & (NHEAD - 1);
    const int b   = bh >> 4;
    const int qi0 = qb * 64;

    const float* Qp = g_Q + (size_t)bh * SEQ * DHEAD + (size_t)qi0 * DHEAD;
    const float* Kp = g_K + (size_t)bh * SEQ * DHEAD;
    const float* Vp = g_V + (size_t)bh * SEQ * DHEAD;

    load_tile_T(Qp, Qs, t);
    if (t < 64) { m_s[t] = -1e30f; l_s[t] = 0.f; }

    const int ty = t >> 4, tx = t & 15;
    const int i0 = ty * 4, j0 = tx * 4;      // GEMM1 mapping (S tile 64x64)
    const int i2 = (t & 15) * 4;             // GEMM2 mapping (O tile 64x128)
    const int d2 = (t >> 4) * 8;

    u64 op[4][4];                            // O accumulators packed along d
    #pragma unroll
    for (int i = 0; i < 4; i++)
        #pragma unroll
        for (int dp = 0; dp < 4; dp++)
            op[i][dp] = 0ull;

    const float SCALE = 0.08838834764831845f;  // 1/sqrt(128)

    for (int kb = 0; kb < SEQ / 64; kb++) {
        const int kj0 = kb * 64;
        __syncthreads();   // previous iteration's smem consumers done
        load_tile_T(Kp + (size_t)kj0 * DHEAD, Ks, t);
        #pragma unroll
        for (int rep = 0; rep < 8; rep++) {
            int u = t + rep * 256;
            int row = u >> 5;
            int dk  = (u & 31) << 2;
            *(float4*)&Vs[row*132 + dk] =
                *(const float4*)(Vp + (size_t)(kj0 + row) * DHEAD + dk);
        }
        __syncthreads();

        // S = Q K^T  (packed along j: 2 pairs)
        u64 accp[4][2];
        #pragma unroll
        for (int i = 0; i < 4; i++) { accp[i][0] = 0ull; accp[i][1] = 0ull; }
        #pragma unroll 4
        for (int d = 0; d < DHEAD; d++) {
            float4 qf = *(const float4*)&Qs[d*68 + i0];
            const u64* kq = (const u64*)&Ks[d*68 + j0];
            u64 k0 = kq[0], k1 = kq[1];
            u64 qa[4] = { f2bcast(qf.x), f2bcast(qf.y), f2bcast(qf.z), f2bcast(qf.w) };
            #pragma unroll
            for (int i = 0; i < 4; i++) {
                accp[i][0] = f2fma(qa[i], k0, accp[i][0]);
                accp[i][1] = f2fma(qa[i], k1, accp[i][1]);
            }
        }
        float acc[4][4];
        #pragma unroll
        for (int i = 0; i < 4; i++) {
            f2unpack(accp[i][0], acc[i][0], acc[i][1]);
            f2unpack(accp[i][1], acc[i][2], acc[i][3]);
        }

        // scores + mask + alibi, row max
        float al[4];
        {
            float4 av = *(const float4*)(alibi + (size_t)h * SEQ + kj0 + j0);
            al[0]=av.x; al[1]=av.y; al[2]=av.z; al[3]=av.w;
        }
        float p[4][4], rmax[4], rsum[4];
        #pragma unroll
        for (int i = 0; i < 4; i++) {
            float4 mv = *(const float4*)(mask + (size_t)(qi0 + i0 + i) * SEQ + kj0 + j0);
            float mr[4] = {mv.x, mv.y, mv.z, mv.w};
            float rm = -1e30f;
            #pragma unroll
            for (int j = 0; j < 4; j++) {
                float v = fmaf(acc[i][j], SCALE, mr[j] + al[j]);
                p[i][j] = v;
                rm = fmaxf(rm, v);
            }
            rmax[i] = rm;
        }
        #pragma unroll
        for (int off = 8; off; off >>= 1)
            #pragma unroll
            for (int i = 0; i < 4; i++)
                rmax[i] = fmaxf(rmax[i], __shfl_xor_sync(0xffffffffu, rmax[i], off));

        // online softmax update
        float nm[4], cf[4];
        #pragma unroll
        for (int i = 0; i < 4; i++) {
            float om = m_s[i0 + i];
            nm[i] = fmaxf(om, rmax[i]);
            cf[i] = __expf(om - nm[i]);
        }
        #pragma unroll
        for (int i = 0; i < 4; i++) {
            float srow = 0.f;
            #pragma unroll
            for (int j = 0; j < 4; j++) {
                float e = __expf(p[i][j] - nm[i]);
                Ps[(j0 + j)*68 + i0 + i] = e;
                srow += e;
            }
            rsum[i] = srow;
        }
        #pragma unroll
        for (int off = 8; off; off >>= 1)
            #pragma unroll
            for (int i = 0; i < 4; i++)
                rsum[i] += __shfl_xor_sync(0xffffffffu, rsum[i], off);
        if (tx == 0) {
            #pragma unroll
            for (int i = 0; i < 4; i++) {
                m_s[i0+i] = nm[i];
                l_s[i0+i] = l_s[i0+i] * cf[i] + rsum[i];
                c_s[i0+i] = cf[i];
            }
        }
        __syncthreads();   // Ps + c_s visible

        // O = O*c + P V  (packed along d: 4 pairs)
        #pragma unroll
        for (int i = 0; i < 4; i++) {
            u64 cc = f2bcast(c_s[i2 + i]);
            #pragma unroll
            for (int dp = 0; dp < 4; dp++)
                op[i][dp] = f2mul(op[i][dp], cc);
        }
        #pragma unroll 2
        for (int j = 0; j < 64; j++) {
            float4 pv = *(const float4*)&Ps[j*68 + i2];
            const u64* vq = (const u64*)&Vs[j*132 + d2];
            u64 v0 = vq[0], v1 = vq[1], v2 = vq[2], v3 = vq[3];
            u64 pa[4] = { f2bcast(pv.x), f2bcast(pv.y), f2bcast(pv.z), f2bcast(pv.w) };
            #pragma unroll
            for (int i = 0; i < 4; i++) {
                op[i][0] = f2fma(pa[i], v0, op[i][0]);
                op[i][1] = f2fma(pa[i], v1, op[i][1]);
                op[i][2] = f2fma(pa[i], v2, op[i][2]);
                op[i][3] = f2fma(pa[i], v3, op[i][3]);
            }
        }
    }

    // normalize and write ctx in [tok][h*128+d] layout for the final GEMM
    #pragma unroll
    for (int i = 0; i < 4; i++) {
        float inv = 1.f / l_s[i2 + i];
        float o[8];
        #pragma unroll
        for (int dp = 0; dp < 4; dp++)
            f2unpack(op[i][dp], o[2*dp], o[2*dp+1]);
        int qg = qi0 + i2 + i;
        size_t base = ((size_t)(b*SEQ + qg))*HID + h*DHEAD + d2;
        *(float4*)&g_ctx[base]     = make_float4(o[0]*inv, o[1]*inv, o[2]*inv, o[3]*inv);
        *(float4*)&g_ctx[base + 4] = make_float4(o[4]*inv, o[5]*inv, o[6]*inv, o[7]*inv);
    }
}

// ---------------------------------------------------------------------------
extern "C" void kernel_launch(void* const* d_in, const int* in_sizes, int n_in,
                              void* d_out, int out_size)
{
    const float* x     = (const float*)d_in[0];
    const float* mask  = (const float*)d_in[1];
    const float* alibi = (const float*)d_in[2];
    const float* freqs = (const float*)d_in[3];
    const float* Wq    = (const float*)d_in[4];
    const float* Wk    = (const float*)d_in[5];
    const float* Wv    = (const float*)d_in[6];
    const float* Wo    = (const float*)d_in[7];
    float* out = (float*)d_out;
    (void)in_sizes; (void)n_in; (void)out_size;

    dim3 gg(HID / 128, NTOK / 128);

    gemm_kernel<<<gg, 256>>>(x, Wq, nullptr, 0);
    gemm_kernel<<<gg, 256>>>(x, Wk, nullptr, 1);
    gemm_kernel<<<gg, 256>>>(x, Wv, nullptr, 2);

    rope_kernel<<<(2*NBATCH*NHEAD*SEQ*64) / 256, 256>>>(freqs);

    cudaFuncSetAttribute(flash_kernel,
                         cudaFuncAttributeMaxDynamicSharedMemorySize,
                         FLASH_SMEM_BYTES);
    flash_kernel<<<dim3(SEQ/64, NBATCH*NHEAD), 256, FLASH_SMEM_BYTES>>>(mask, alibi);

    gemm_kernel<<<gg, 256>>>(nullptr, Wo, out, 3);
}

// round 4
// speedup vs baseline: 1.4431x; 1.3616x over previous
#include <cuda_runtime.h>
#include <cuda_bf16.h>
#include <math.h>
#include <cstdint>

typedef __nv_bfloat16 bf16;
typedef unsigned long long u64;

// Problem constants
#define NBATCH 2
#define SEQ    2048
#define NHEAD  16
#define DHEAD  128
#define HID    2048
#define NTOK   4096   // NBATCH*SEQ

// Scratch (device globals — no runtime allocation allowed)
__device__ float g_Q[NBATCH*NHEAD*SEQ*DHEAD];
__device__ float g_K[NBATCH*NHEAD*SEQ*DHEAD];
__device__ float g_V[NBATCH*NHEAD*SEQ*DHEAD];
__device__ float g_ctx[(size_t)NTOK*HID];

// bf16 hi/lo split operands
__device__ bf16 g_xh[(size_t)NTOK*HID];
__device__ bf16 g_xl[(size_t)NTOK*HID];
__device__ bf16 g_ch[(size_t)NTOK*HID];
__device__ bf16 g_cl[(size_t)NTOK*HID];
__device__ bf16 g_wh[4][(size_t)HID*HID];
__device__ bf16 g_wl[4][(size_t)HID*HID];

// ---------------------------------------------------------------------------
// Split: fp32 -> bf16 hi + bf16 lo   (x = hi + lo to ~16 mantissa bits)
// ---------------------------------------------------------------------------
__global__ __launch_bounds__(256)
void split_kernel(const float* __restrict__ src,
                  bf16* __restrict__ h, bf16* __restrict__ l, int n4)
{
    int i = blockIdx.x * 256 + threadIdx.x;
    if (i >= n4) return;
    float4 v = ((const float4*)src)[i];
    float vv[4] = {v.x, v.y, v.z, v.w};
    unsigned short hu[4], lu[4];
    #pragma unroll
    for (int j = 0; j < 4; j++) {
        bf16 hb = __float2bfloat16_rn(vv[j]);
        bf16 lb = __float2bfloat16_rn(vv[j] - __bfloat162float(hb));
        hu[j] = __bfloat16_as_ushort(hb);
        lu[j] = __bfloat16_as_ushort(lb);
    }
    uint2 hp = make_uint2(((uint32_t)hu[1] << 16) | hu[0], ((uint32_t)hu[3] << 16) | hu[2]);
    uint2 lp = make_uint2(((uint32_t)lu[1] << 16) | lu[0], ((uint32_t)lu[3] << 16) | lu[2]);
    ((uint2*)h)[i] = hp;
    ((uint2*)l)[i] = lp;
}

// ---------------------------------------------------------------------------
// mma.sync helpers
// ---------------------------------------------------------------------------
__device__ __forceinline__ uint32_t smem_u32(const void* p) {
    uint32_t a;
    asm("{ .reg .u64 t; cvta.to.shared.u64 t, %1; cvt.u32.u64 %0, t; }"
        : "=r"(a) : "l"(p));
    return a;
}
__device__ __forceinline__ void ldm4(uint32_t* r, uint32_t addr) {
    asm volatile("ldmatrix.sync.aligned.m8n8.x4.shared.b16 {%0,%1,%2,%3},[%4];"
                 : "=r"(r[0]), "=r"(r[1]), "=r"(r[2]), "=r"(r[3]) : "r"(addr));
}
__device__ __forceinline__ void mma16816(float* d, const uint32_t* a,
                                         uint32_t b0, uint32_t b1) {
    asm volatile(
        "mma.sync.aligned.m16n8k16.row.col.f32.bf16.bf16.f32 "
        "{%0,%1,%2,%3},{%4,%5,%6,%7},{%8,%9},{%0,%1,%2,%3};"
        : "+f"(d[0]), "+f"(d[1]), "+f"(d[2]), "+f"(d[3])
        : "r"(a[0]), "r"(a[1]), "r"(a[2]), "r"(a[3]), "r"(b0), "r"(b1));
}

// ---------------------------------------------------------------------------
// Tensor-core GEMM: C[m][n] = sum_k A[m][k]*W[n][k], A/W pre-split bf16 hi/lo.
// 128x128 CTA tile, 256 threads (2x4 warps, each 64x32), K-chunk 32.
// 3-product bf16 emulation of fp32: Ah*Bh + Ah*Bl + Al*Bh.
// sel 0/1/2 -> scatter bhsd into g_Q/g_K/g_V; sel 3 -> C row-major to Cout.
// ---------------------------------------------------------------------------
#define SPAD 40   // bf16 row stride in smem (80B, conflict-free for ldmatrix)

__global__ __launch_bounds__(256)
void mma_gemm(const bf16* __restrict__ Ah, const bf16* __restrict__ Al,
              const bf16* __restrict__ Bh, const bf16* __restrict__ Bl,
              float* __restrict__ Cout, int sel)
{
    __shared__ bf16 sAh[128*SPAD], sAl[128*SPAD], sBh[128*SPAD], sBl[128*SPAD];

    const int t    = threadIdx.x;
    const int wid  = t >> 5;
    const int lane = t & 31;
    const int m0   = blockIdx.y << 7;
    const int n0   = blockIdx.x << 7;
    const int wm   = wid & 1;        // 0..1 : 64-row half
    const int wn   = wid >> 1;       // 0..3 : 32-col quarter

    // global load coords: 2 reps, each thread one 16B quad
    int rowL[2], qdL[2];
    #pragma unroll
    for (int r = 0; r < 2; r++) {
        int u = t + (r << 8);
        rowL[r] = u >> 2;
        qdL[r]  = u & 3;
    }

    const bf16* pAh = Ah + (size_t)m0 * HID;
    const bf16* pAl = Al + (size_t)m0 * HID;
    const bf16* pBh = Bh + (size_t)n0 * HID;
    const bf16* pBl = Bl + (size_t)n0 * HID;

    float acc[4][4][4];
    #pragma unroll
    for (int i = 0; i < 4; i++)
        #pragma unroll
        for (int j = 0; j < 4; j++)
            #pragma unroll
            for (int q = 0; q < 4; q++)
                acc[i][j][q] = 0.f;

    // prefetch chunk 0
    uint4 fAh[2], fAl[2], fBh[2], fBl[2];
    #pragma unroll
    for (int r = 0; r < 2; r++) {
        size_t go = (size_t)rowL[r] * HID + qdL[r] * 8;
        fAh[r] = *(const uint4*)(pAh + go);
        fAl[r] = *(const uint4*)(pAl + go);
        fBh[r] = *(const uint4*)(pBh + go);
        fBl[r] = *(const uint4*)(pBl + go);
    }

    const uint32_t uAh = smem_u32(sAh), uAl = smem_u32(sAl);
    const uint32_t uBh = smem_u32(sBh), uBl = smem_u32(sBl);
    const int lrow = lane & 15, lcol = lane >> 4;

    for (int k0 = 0; k0 < HID; k0 += 32) {
        // store prefetched chunk
        #pragma unroll
        for (int r = 0; r < 2; r++) {
            int so = rowL[r] * SPAD + qdL[r] * 8;
            *(uint4*)&sAh[so] = fAh[r];
            *(uint4*)&sAl[so] = fAl[r];
            *(uint4*)&sBh[so] = fBh[r];
            *(uint4*)&sBl[so] = fBl[r];
        }
        __syncthreads();

        // prefetch next chunk
        if (k0 + 32 < HID) {
            #pragma unroll
            for (int r = 0; r < 2; r++) {
                size_t go = (size_t)rowL[r] * HID + k0 + 32 + qdL[r] * 8;
                fAh[r] = *(const uint4*)(pAh + go);
                fAl[r] = *(const uint4*)(pAl + go);
                fBh[r] = *(const uint4*)(pBh + go);
                fBl[r] = *(const uint4*)(pBl + go);
            }
        }

        #pragma unroll
        for (int kh = 0; kh < 2; kh++) {
            uint32_t ah[4][4], al[4][4], bh[2][4], bl[2][4];
            #pragma unroll
            for (int mt = 0; mt < 4; mt++) {
                uint32_t off = (uint32_t)((wm*64 + mt*16 + lrow) * SPAD + kh*16 + lcol*8) * 2;
                ldm4(ah[mt], uAh + off);
                ldm4(al[mt], uAl + off);
            }
            #pragma unroll
            for (int n2 = 0; n2 < 2; n2++) {
                uint32_t off = (uint32_t)((wn*32 + n2*16 + lrow) * SPAD + kh*16 + lcol*8) * 2;
                ldm4(bh[n2], uBh + off);
                ldm4(bl[n2], uBl + off);
            }
            #pragma unroll
            for (int mt = 0; mt < 4; mt++)
                #pragma unroll
                for (int nt = 0; nt < 4; nt++) {
                    int n2 = nt >> 1, hb = nt & 1;
                    mma16816(acc[mt][nt], ah[mt], bh[n2][hb], bh[n2][hb+2]);
                    mma16816(acc[mt][nt], ah[mt], bl[n2][hb], bl[n2][hb+2]);
                    mma16816(acc[mt][nt], al[mt], bh[n2][hb], bh[n2][hb+2]);
                }
        }
        __syncthreads();
    }

    // epilogue
    const int rbase = wm*64 + (lane >> 2);
    const int cbase = wn*32 + 2*(lane & 3);
    if (sel == 3) {
        #pragma unroll
        for (int mt = 0; mt < 4; mt++)
            #pragma unroll
            for (int nt = 0; nt < 4; nt++) {
                int r0 = m0 + rbase + mt*16;
                int cc = n0 + cbase + nt*8;
                *(float2*)&Cout[(size_t)r0 * HID + cc]       = make_float2(acc[mt][nt][0], acc[mt][nt][1]);
                *(float2*)&Cout[(size_t)(r0 + 8) * HID + cc] = make_float2(acc[mt][nt][2], acc[mt][nt][3]);
            }
    } else {
        float* outp = (sel == 0) ? g_Q : (sel == 1) ? g_K : g_V;
        const int h = n0 >> 7;
        #pragma unroll
        for (int mt = 0; mt < 4; mt++)
            #pragma unroll
            for (int nt = 0; nt < 4; nt++) {
                int r0 = m0 + rbase + mt*16;
                int b  = r0 >> 11;
                int s  = r0 & (SEQ - 1);
                int d  = cbase + nt*8;
                size_t base = (((size_t)(b*NHEAD + h))*SEQ + s)*DHEAD + d;
                *(float2*)&outp[base]             = make_float2(acc[mt][nt][0], acc[mt][nt][1]);
                *(float2*)&outp[base + 8*DHEAD]   = make_float2(acc[mt][nt][2], acc[mt][nt][3]);
            }
    }
}

// ---------------------------------------------------------------------------
// Packed f32x2 helpers (flash kernel)
// ---------------------------------------------------------------------------
__device__ __forceinline__ u64 f2pack(float lo, float hi) {
    u64 r; asm("mov.b64 %0,{%1,%2};" : "=l"(r) : "f"(lo), "f"(hi)); return r;
}
__device__ __forceinline__ u64 f2bcast(float x) { return f2pack(x, x); }
__device__ __forceinline__ void f2unpack(u64 v, float& lo, float& hi) {
    asm("mov.b64 {%0,%1},%2;" : "=f"(lo), "=f"(hi) : "l"(v));
}
__device__ __forceinline__ u64 f2fma(u64 a, u64 b, u64 c) {
    u64 d; asm("fma.rn.f32x2 %0,%1,%2,%3;" : "=l"(d) : "l"(a), "l"(b), "l"(c));
    return d;
}
__device__ __forceinline__ u64 f2mul(u64 a, u64 b) {
    u64 d; asm("mul.rn.f32x2 %0,%1,%2;" : "=l"(d) : "l"(a), "l"(b));
    return d;
}

// ---------------------------------------------------------------------------
// RoPE
// ---------------------------------------------------------------------------
__global__ __launch_bounds__(256)
void rope_kernel(const float* __restrict__ freqs)
{
    int tid = blockIdx.x * 256 + threadIdx.x;
    float* buf = (tid >> 22) ? g_K : g_Q;
    int rem = tid & ((1 << 22) - 1);
    int d   = rem & 63;
    int s   = (rem >> 6) & (SEQ - 1);
    int bh  = rem >> 17;
    size_t base = ((size_t)bh * SEQ + s) * DHEAD;
    float f1 = freqs[s*DHEAD + d];
    float f2 = freqs[s*DHEAD + d + 64];
    float x1 = buf[base + d];
    float x2 = buf[base + d + 64];
    buf[base + d]      = x1 * cosf(f1) - x2 * sinf(f1);
    buf[base + d + 64] = x2 * cosf(f2) + x1 * sinf(f2);
}

// ---------------------------------------------------------------------------
// Flash attention (R2 version, passing)
// ---------------------------------------------------------------------------
#define FLASH_SMEM_FLOATS 30400
#define FLASH_SMEM_BYTES  (FLASH_SMEM_FLOATS * 4)

__device__ __forceinline__ void load_tile_T(const float* __restrict__ src,
                                            float* __restrict__ dst, int t)
{
    #pragma unroll
    for (int rep = 0; rep < 8; rep++) {
        int u   = t + rep * 256;
        int row = (u & 7) | (((u >> 5) & 7) << 3);
        int kf  = (((u >> 3) & 3) << 2) | ((u >> 8) << 4);
        float4 v = *(const float4*)(src + (size_t)row * DHEAD + kf);
        dst[(kf+0)*68 + row] = v.x;
        dst[(kf+1)*68 + row] = v.y;
        dst[(kf+2)*68 + row] = v.z;
        dst[(kf+3)*68 + row] = v.w;
    }
}

__global__ __launch_bounds__(256, 1)
void flash_kernel(const float* __restrict__ mask, const float* __restrict__ alibi)
{
    extern __shared__ float sm[];
    float* Qs  = sm;               // [128][68]  Q^T
    float* Ks  = sm + 8704;        // [128][68]  K^T
    float* Vs  = sm + 17408;       // [64][132]  V natural
    float* Ps  = sm + 25856;       // [64][68]   P^T
    float* m_s = sm + 30208;       // [64]
    float* l_s = m_s + 64;         // [64]
    float* c_s = l_s + 64;         // [64]

    const int t   = threadIdx.x;
    const int qb  = blockIdx.x;
    const int bh  = blockIdx.y;
    const int h   = bh & (NHEAD - 1);
    const int b   = bh >> 4;
    const int qi0 = qb * 64;

    const float* Qp = g_Q + (size_t)bh * SEQ * DHEAD + (size_t)qi0 * DHEAD;
    const float* Kp = g_K + (size_t)bh * SEQ * DHEAD;
    const float* Vp = g_V + (size_t)bh * SEQ * DHEAD;

    load_tile_T(Qp, Qs, t);
    if (t < 64) { m_s[t] = -1e30f; l_s[t] = 0.f; }

    const int ty = t >> 4, tx = t & 15;
    const int i0 = ty * 4, j0 = tx * 4;
    const int i2 = (t & 15) * 4;
    const int d2 = (t >> 4) * 8;

    u64 op[4][4];
    #pragma unroll
    for (int i = 0; i < 4; i++)
        #pragma unroll
        for (int dp = 0; dp < 4; dp++)
            op[i][dp] = 0ull;

    const float SCALE = 0.08838834764831845f;  // 1/sqrt(128)

    for (int kb = 0; kb < SEQ / 64; kb++) {
        const int kj0 = kb * 64;
        __syncthreads();
        load_tile_T(Kp + (size_t)kj0 * DHEAD, Ks, t);
        #pragma unroll
        for (int rep = 0; rep < 8; rep++) {
            int u = t + rep * 256;
            int row = u >> 5;
            int dk  = (u & 31) << 2;
            *(float4*)&Vs[row*132 + dk] =
                *(const float4*)(Vp + (size_t)(kj0 + row) * DHEAD + dk);
        }
        __syncthreads();

        u64 accp[4][2];
        #pragma unroll
        for (int i = 0; i < 4; i++) { accp[i][0] = 0ull; accp[i][1] = 0ull; }
        #pragma unroll 4
        for (int d = 0; d < DHEAD; d++) {
            float4 qf = *(const float4*)&Qs[d*68 + i0];
            const u64* kq = (const u64*)&Ks[d*68 + j0];
            u64 k0 = kq[0], k1 = kq[1];
            u64 qa[4] = { f2bcast(qf.x), f2bcast(qf.y), f2bcast(qf.z), f2bcast(qf.w) };
            #pragma unroll
            for (int i = 0; i < 4; i++) {
                accp[i][0] = f2fma(qa[i], k0, accp[i][0]);
                accp[i][1] = f2fma(qa[i], k1, accp[i][1]);
            }
        }
        float acc[4][4];
        #pragma unroll
        for (int i = 0; i < 4; i++) {
            f2unpack(accp[i][0], acc[i][0], acc[i][1]);
            f2unpack(accp[i][1], acc[i][2], acc[i][3]);
        }

        float al[4];
        {
            float4 av = *(const float4*)(alibi + (size_t)h * SEQ + kj0 + j0);
            al[0]=av.x; al[1]=av.y; al[2]=av.z; al[3]=av.w;
        }
        float p[4][4], rmax[4], rsum[4];
        #pragma unroll
        for (int i = 0; i < 4; i++) {
            float4 mv = *(const float4*)(mask + (size_t)(qi0 + i0 + i) * SEQ + kj0 + j0);
            float mr[4] = {mv.x, mv.y, mv.z, mv.w};
            float rm = -1e30f;
            #pragma unroll
            for (int j = 0; j < 4; j++) {
                float v = fmaf(acc[i][j], SCALE, mr[j] + al[j]);
                p[i][j] = v;
                rm = fmaxf(rm, v);
            }
            rmax[i] = rm;
        }
        #pragma unroll
        for (int off = 8; off; off >>= 1)
            #pragma unroll
            for (int i = 0; i < 4; i++)
                rmax[i] = fmaxf(rmax[i], __shfl_xor_sync(0xffffffffu, rmax[i], off));

        float nm[4], cf[4];
        #pragma unroll
        for (int i = 0; i < 4; i++) {
            float om = m_s[i0 + i];
            nm[i] = fmaxf(om, rmax[i]);
            cf[i] = __expf(om - nm[i]);
        }
        #pragma unroll
        for (int i = 0; i < 4; i++) {
            float srow = 0.f;
            #pragma unroll
            for (int j = 0; j < 4; j++) {
                float e = __expf(p[i][j] - nm[i]);
                Ps[(j0 + j)*68 + i0 + i] = e;
                srow += e;
            }
            rsum[i] = srow;
        }
        #pragma unroll
        for (int off = 8; off; off >>= 1)
            #pragma unroll
            for (int i = 0; i < 4; i++)
                rsum[i] += __shfl_xor_sync(0xffffffffu, rsum[i], off);
        if (tx == 0) {
            #pragma unroll
            for (int i = 0; i < 4; i++) {
                m_s[i0+i] = nm[i];
                l_s[i0+i] = l_s[i0+i] * cf[i] + rsum[i];
                c_s[i0+i] = cf[i];
            }
        }
        __syncthreads();

        #pragma unroll
        for (int i = 0; i < 4; i++) {
            u64 cc = f2bcast(c_s[i2 + i]);
            #pragma unroll
            for (int dp = 0; dp < 4; dp++)
                op[i][dp] = f2mul(op[i][dp], cc);
        }
        #pragma unroll 2
        for (int j = 0; j < 64; j++) {
            float4 pv = *(const float4*)&Ps[j*68 + i2];
            const u64* vq = (const u64*)&Vs[j*132 + d2];
            u64 v0 = vq[0], v1 = vq[1], v2 = vq[2], v3 = vq[3];
            u64 pa[4] = { f2bcast(pv.x), f2bcast(pv.y), f2bcast(pv.z), f2bcast(pv.w) };
            #pragma unroll
            for (int i = 0; i < 4; i++) {
                op[i][0] = f2fma(pa[i], v0, op[i][0]);
                op[i][1] = f2fma(pa[i], v1, op[i][1]);
                op[i][2] = f2fma(pa[i], v2, op[i][2]);
                op[i][3] = f2fma(pa[i], v3, op[i][3]);
            }
        }
    }

    #pragma unroll
    for (int i = 0; i < 4; i++) {
        float inv = 1.f / l_s[i2 + i];
        float o[8];
        #pragma unroll
        for (int dp = 0; dp < 4; dp++)
            f2unpack(op[i][dp], o[2*dp], o[2*dp+1]);
        int qg = qi0 + i2 + i;
        size_t base = ((size_t)(b*SEQ + qg))*HID + h*DHEAD + d2;
        *(float4*)&g_ctx[base]     = make_float4(o[0]*inv, o[1]*inv, o[2]*inv, o[3]*inv);
        *(float4*)&g_ctx[base + 4] = make_float4(o[4]*inv, o[5]*inv, o[6]*inv, o[7]*inv);
    }
}

// ---------------------------------------------------------------------------
extern "C" void kernel_launch(void* const* d_in, const int* in_sizes, int n_in,
                              void* d_out, int out_size)
{
    const float* x     = (const float*)d_in[0];
    const float* mask  = (const float*)d_in[1];
    const float* alibi = (const float*)d_in[2];
    const float* freqs = (const float*)d_in[3];
    const float* W[4]  = { (const float*)d_in[4], (const float*)d_in[5],
                           (const float*)d_in[6], (const float*)d_in[7] };
    float* out = (float*)d_out;
    (void)in_sizes; (void)n_in; (void)out_size;

    cudaFuncSetAttribute(flash_kernel,
                         cudaFuncAttributeMaxDynamicSharedMemorySize, FLASH_SMEM_BYTES);

    // resolve device-global addresses (host side, graph-capturable)
    bf16 *xh, *xl, *ch, *cl, *wh[4], *wl[4];
    float *ctx;
    cudaGetSymbolAddress((void**)&xh, g_xh);
    cudaGetSymbolAddress((void**)&xl, g_xl);
    cudaGetSymbolAddress((void**)&ch, g_ch);
    cudaGetSymbolAddress((void**)&cl, g_cl);
    cudaGetSymbolAddress((void**)&ctx, g_ctx);
    {
        bf16 *p;
        cudaGetSymbolAddress((void**)&p, g_wh); wh[0]=p; wh[1]=p+(size_t)HID*HID; wh[2]=p+2*(size_t)HID*HID; wh[3]=p+3*(size_t)HID*HID;
        cudaGetSymbolAddress((void**)&p, g_wl); wl[0]=p; wl[1]=p+(size_t)HID*HID; wl[2]=p+2*(size_t)HID*HID; wl[3]=p+3*(size_t)HID*HID;
    }

    // splits
    {
        int n4 = NTOK * HID / 4;
        split_kernel<<<(n4 + 255) / 256, 256>>>(x, xh, xl, n4);
        int w4 = HID * HID / 4;
        for (int i = 0; i < 4; i++)
            split_kernel<<<(w4 + 255) / 256, 256>>>(W[i], wh[i], wl[i], w4);
    }

    dim3 gg(HID / 128, NTOK / 128);

    mma_gemm<<<gg, 256>>>(xh, xl, wh[0], wl[0], nullptr, 0);
    mma_gemm<<<gg, 256>>>(xh, xl, wh[1], wl[1], nullptr, 1);
    mma_gemm<<<gg, 256>>>(xh, xl, wh[2], wl[2], nullptr, 2);

    rope_kernel<<<(2*NBATCH*NHEAD*SEQ*64) / 256, 256>>>(freqs);

    flash_kernel<<<dim3(SEQ/64, NBATCH*NHEAD), 256, FLASH_SMEM_BYTES>>>(mask, alibi);

    {
        int n4 = NTOK * HID / 4;
        split_kernel<<<(n4 + 255) / 256, 256>>>(ctx, ch, cl, n4);
    }
    mma_gemm<<<gg, 256>>>(ch, cl, wh[3], wl[3], out, 3);
}

// round 5
// speedup vs baseline: 2.1559x; 1.4939x over previous
#include <cuda_runtime.h>
#include <cuda_bf16.h>
#include <math.h>
#include <cstdint>

typedef __nv_bfloat16 bf16;

// Problem constants
#define NBATCH 2
#define SEQ    2048
#define NHEAD  16
#define DHEAD  128
#define HID    2048
#define NTOK   4096   // NBATCH*SEQ

// Scratch (device globals — no runtime allocation allowed)
__device__ float g_Q[NBATCH*NHEAD*SEQ*DHEAD];   // fp32, pre-RoPE
__device__ float g_K[NBATCH*NHEAD*SEQ*DHEAD];

__device__ bf16 g_Qh[NBATCH*NHEAD*SEQ*DHEAD];   // post-RoPE hi/lo
__device__ bf16 g_Ql[NBATCH*NHEAD*SEQ*DHEAD];
__device__ bf16 g_Kh[NBATCH*NHEAD*SEQ*DHEAD];
__device__ bf16 g_Kl[NBATCH*NHEAD*SEQ*DHEAD];
__device__ bf16 g_Vh[NBATCH*NHEAD*SEQ*DHEAD];
__device__ bf16 g_Vl[NBATCH*NHEAD*SEQ*DHEAD];

__device__ bf16 g_xh[(size_t)NTOK*HID];
__device__ bf16 g_xl[(size_t)NTOK*HID];
__device__ bf16 g_ch[(size_t)NTOK*HID];         // ctx hi/lo (flash output)
__device__ bf16 g_cl[(size_t)NTOK*HID];
__device__ bf16 g_wh[4][(size_t)HID*HID];
__device__ bf16 g_wl[4][(size_t)HID*HID];

// ---------------------------------------------------------------------------
// helpers
// ---------------------------------------------------------------------------
__device__ __forceinline__ uint32_t smem_u32(const void* p) {
    uint32_t a;
    asm("{ .reg .u64 t; cvta.to.shared.u64 t, %1; cvt.u32.u64 %0, t; }"
        : "=r"(a) : "l"(p));
    return a;
}
__device__ __forceinline__ void ldm4(uint32_t* r, uint32_t addr) {
    asm volatile("ldmatrix.sync.aligned.m8n8.x4.shared.b16 {%0,%1,%2,%3},[%4];"
                 : "=r"(r[0]), "=r"(r[1]), "=r"(r[2]), "=r"(r[3]) : "r"(addr));
}
__device__ __forceinline__ void ldm4t(uint32_t* r, uint32_t addr) {
    asm volatile("ldmatrix.sync.aligned.m8n8.x4.trans.shared.b16 {%0,%1,%2,%3},[%4];"
                 : "=r"(r[0]), "=r"(r[1]), "=r"(r[2]), "=r"(r[3]) : "r"(addr));
}
__device__ __forceinline__ void mma16816(float* d, const uint32_t* a,
                                         uint32_t b0, uint32_t b1) {
    asm volatile(
        "mma.sync.aligned.m16n8k16.row.col.f32.bf16.bf16.f32 "
        "{%0,%1,%2,%3},{%4,%5,%6,%7},{%8,%9},{%0,%1,%2,%3};"
        : "+f"(d[0]), "+f"(d[1]), "+f"(d[2]), "+f"(d[3])
        : "r"(a[0]), "r"(a[1]), "r"(a[2]), "r"(a[3]), "r"(b0), "r"(b1));
}
__device__ __forceinline__ uint32_t pack2bf(float a, float b) {
    return ((uint32_t)__bfloat16_as_ushort(__float2bfloat16_rn(b)) << 16)
         | (uint32_t)__bfloat16_as_ushort(__float2bfloat16_rn(a));
}
__device__ __forceinline__ void split1(float v, bf16& h, bf16& l) {
    h = __float2bfloat16_rn(v);
    l = __float2bfloat16_rn(v - __bfloat162float(h));
}

// ---------------------------------------------------------------------------
// Split: fp32 -> bf16 hi + bf16 lo
// ---------------------------------------------------------------------------
__global__ __launch_bounds__(256)
void split_kernel(const float* __restrict__ src,
                  bf16* __restrict__ h, bf16* __restrict__ l, int n4)
{
    int i = blockIdx.x * 256 + threadIdx.x;
    if (i >= n4) return;
    float4 v = ((const float4*)src)[i];
    float vv[4] = {v.x, v.y, v.z, v.w};
    unsigned short hu[4], lu[4];
    #pragma unroll
    for (int j = 0; j < 4; j++) {
        bf16 hb, lb; split1(vv[j], hb, lb);
        hu[j] = __bfloat16_as_ushort(hb);
        lu[j] = __bfloat16_as_ushort(lb);
    }
    ((uint2*)h)[i] = make_uint2(((uint32_t)hu[1] << 16) | hu[0], ((uint32_t)hu[3] << 16) | hu[2]);
    ((uint2*)l)[i] = make_uint2(((uint32_t)lu[1] << 16) | lu[0], ((uint32_t)lu[3] << 16) | lu[2]);
}

// ---------------------------------------------------------------------------
// Tensor-core GEMM (R4): C[m][n] = sum_k A[m][k]*W[n][k]; A/W bf16 hi/lo.
// sel 0/1 -> fp32 bhsd into g_Q/g_K; sel 2 -> bf16 hi/lo bhsd into g_Vh/g_Vl;
// sel 3 -> fp32 row-major to Cout.
// ---------------------------------------------------------------------------
#define SPAD 40

__global__ __launch_bounds__(256)
void mma_gemm(const bf16* __restrict__ Ah, const bf16* __restrict__ Al,
              const bf16* __restrict__ Bh, const bf16* __restrict__ Bl,
              float* __restrict__ Cout, int sel)
{
    __shared__ bf16 sAh[128*SPAD], sAl[128*SPAD], sBh[128*SPAD], sBl[128*SPAD];

    const int t    = threadIdx.x;
    const int wid  = t >> 5;
    const int lane = t & 31;
    const int m0   = blockIdx.y << 7;
    const int n0   = blockIdx.x << 7;
    const int wm   = wid & 1;
    const int wn   = wid >> 1;

    int rowL[2], qdL[2];
    #pragma unroll
    for (int r = 0; r < 2; r++) {
        int u = t + (r << 8);
        rowL[r] = u >> 2;
        qdL[r]  = u & 3;
    }

    const bf16* pAh = Ah + (size_t)m0 * HID;
    const bf16* pAl = Al + (size_t)m0 * HID;
    const bf16* pBh = Bh + (size_t)n0 * HID;
    const bf16* pBl = Bl + (size_t)n0 * HID;

    float acc[4][4][4];
    #pragma unroll
    for (int i = 0; i < 4; i++)
        #pragma unroll
        for (int j = 0; j < 4; j++)
            #pragma unroll
            for (int q = 0; q < 4; q++)
                acc[i][j][q] = 0.f;

    uint4 fAh[2], fAl[2], fBh[2], fBl[2];
    #pragma unroll
    for (int r = 0; r < 2; r++) {
        size_t go = (size_t)rowL[r] * HID + qdL[r] * 8;
        fAh[r] = *(const uint4*)(pAh + go);
        fAl[r] = *(const uint4*)(pAl + go);
        fBh[r] = *(const uint4*)(pBh + go);
        fBl[r] = *(const uint4*)(pBl + go);
    }

    const uint32_t uAh = smem_u32(sAh), uAl = smem_u32(sAl);
    const uint32_t uBh = smem_u32(sBh), uBl = smem_u32(sBl);
    const int lrow = lane & 15, lcol = lane >> 4;

    for (int k0 = 0; k0 < HID; k0 += 32) {
        #pragma unroll
        for (int r = 0; r < 2; r++) {
            int so = rowL[r] * SPAD + qdL[r] * 8;
            *(uint4*)&sAh[so] = fAh[r];
            *(uint4*)&sAl[so] = fAl[r];
            *(uint4*)&sBh[so] = fBh[r];
            *(uint4*)&sBl[so] = fBl[r];
        }
        __syncthreads();

        if (k0 + 32 < HID) {
            #pragma unroll
            for (int r = 0; r < 2; r++) {
                size_t go = (size_t)rowL[r] * HID + k0 + 32 + qdL[r] * 8;
                fAh[r] = *(const uint4*)(pAh + go);
                fAl[r] = *(const uint4*)(pAl + go);
                fBh[r] = *(const uint4*)(pBh + go);
                fBl[r] = *(const uint4*)(pBl + go);
            }
        }

        #pragma unroll
        for (int kh = 0; kh < 2; kh++) {
            uint32_t ah[4][4], al[4][4], bh[2][4], bl[2][4];
            #pragma unroll
            for (int mt = 0; mt < 4; mt++) {
                uint32_t off = (uint32_t)((wm*64 + mt*16 + lrow) * SPAD + kh*16 + lcol*8) * 2;
                ldm4(ah[mt], uAh + off);
                ldm4(al[mt], uAl + off);
            }
            #pragma unroll
            for (int n2 = 0; n2 < 2; n2++) {
                uint32_t off = (uint32_t)((wn*32 + n2*16 + lrow) * SPAD + kh*16 + lcol*8) * 2;
                ldm4(bh[n2], uBh + off);
                ldm4(bl[n2], uBl + off);
            }
            #pragma unroll
            for (int mt = 0; mt < 4; mt++)
                #pragma unroll
                for (int nt = 0; nt < 4; nt++) {
                    int n2 = nt >> 1, hb = nt & 1;
                    mma16816(acc[mt][nt], ah[mt], bh[n2][hb], bh[n2][hb+2]);
                    mma16816(acc[mt][nt], ah[mt], bl[n2][hb], bl[n2][hb+2]);
                    mma16816(acc[mt][nt], al[mt], bh[n2][hb], bh[n2][hb+2]);
                }
        }
        __syncthreads();
    }

    const int rbase = wm*64 + (lane >> 2);
    const int cbase = wn*32 + 2*(lane & 3);
    if (sel == 3) {
        #pragma unroll
        for (int mt = 0; mt < 4; mt++)
            #pragma unroll
            for (int nt = 0; nt < 4; nt++) {
                int r0 = m0 + rbase + mt*16;
                int cc = n0 + cbase + nt*8;
                *(float2*)&Cout[(size_t)r0 * HID + cc]       = make_float2(acc[mt][nt][0], acc[mt][nt][1]);
                *(float2*)&Cout[(size_t)(r0 + 8) * HID + cc] = make_float2(acc[mt][nt][2], acc[mt][nt][3]);
            }
    } else if (sel == 2) {
        const int h = n0 >> 7;
        #pragma unroll
        for (int mt = 0; mt < 4; mt++)
            #pragma unroll
            for (int nt = 0; nt < 4; nt++) {
                int r0 = m0 + rbase + mt*16;
                int b  = r0 >> 11;
                int s  = r0 & (SEQ - 1);
                int d  = cbase + nt*8;
                size_t base = (((size_t)(b*NHEAD + h))*SEQ + s)*DHEAD + d;
                bf16 h0,l0,h1,l1;
                split1(acc[mt][nt][0], h0, l0); split1(acc[mt][nt][1], h1, l1);
                *(uint32_t*)&g_Vh[base] = ((uint32_t)__bfloat16_as_ushort(h1)<<16)|__bfloat16_as_ushort(h0);
                *(uint32_t*)&g_Vl[base] = ((uint32_t)__bfloat16_as_ushort(l1)<<16)|__bfloat16_as_ushort(l0);
                split1(acc[mt][nt][2], h0, l0); split1(acc[mt][nt][3], h1, l1);
                *(uint32_t*)&g_Vh[base + 8*DHEAD] = ((uint32_t)__bfloat16_as_ushort(h1)<<16)|__bfloat16_as_ushort(h0);
                *(uint32_t*)&g_Vl[base + 8*DHEAD] = ((uint32_t)__bfloat16_as_ushort(l1)<<16)|__bfloat16_as_ushort(l0);
            }
    } else {
        float* outp = (sel == 0) ? g_Q : g_K;
        const int h = n0 >> 7;
        #pragma unroll
        for (int mt = 0; mt < 4; mt++)
            #pragma unroll
            for (int nt = 0; nt < 4; nt++) {
                int r0 = m0 + rbase + mt*16;
                int b  = r0 >> 11;
                int s  = r0 & (SEQ - 1);
                int d  = cbase + nt*8;
                size_t base = (((size_t)(b*NHEAD + h))*SEQ + s)*DHEAD + d;
                *(float2*)&outp[base]           = make_float2(acc[mt][nt][0], acc[mt][nt][1]);
                *(float2*)&outp[base + 8*DHEAD] = make_float2(acc[mt][nt][2], acc[mt][nt][3]);
            }
    }
}

// ---------------------------------------------------------------------------
// RoPE + split: read fp32 g_Q/g_K, rotate, write bf16 hi/lo.
// ---------------------------------------------------------------------------
__global__ __launch_bounds__(256)
void rope_split(const float* __restrict__ freqs)
{
    int tid = blockIdx.x * 256 + threadIdx.x;
    bool isK = (tid >> 22) != 0;
    const float* src = isK ? g_K : g_Q;
    bf16* dh = isK ? g_Kh : g_Qh;
    bf16* dl = isK ? g_Kl : g_Ql;
    int rem = tid & ((1 << 22) - 1);
    int d   = rem & 63;
    int s   = (rem >> 6) & (SEQ - 1);
    int bh  = rem >> 17;
    size_t base = ((size_t)bh * SEQ + s) * DHEAD;
    float f1 = freqs[s*DHEAD + d];
    float f2 = freqs[s*DHEAD + d + 64];
    float x1 = src[base + d];
    float x2 = src[base + d + 64];
    float y1 = x1 * cosf(f1) - x2 * sinf(f1);
    float y2 = x2 * cosf(f2) + x1 * sinf(f2);
    bf16 h, l;
    split1(y1, h, l); dh[base + d]      = h; dl[base + d]      = l;
    split1(y2, h, l); dh[base + d + 64] = h; dl[base + d + 64] = l;
}

// ---------------------------------------------------------------------------
// Flash attention, mma.sync bf16 3-product.
// CTA: Bq=128 q rows, full d=128; loop Bk=64 key tiles; 8 warps (4 row x 2 col).
// ---------------------------------------------------------------------------
#define BQ 128
#define BK 64
#define QSTR 136
#define KSTR 136
#define PSTR 72

#define OFF_QH 0
#define OFF_QL (OFF_QH + 128*QSTR*2)
#define OFF_KH (OFF_QL + 128*QSTR*2)
#define OFF_KL (OFF_KH + 64*KSTR*2)
#define OFF_VH (OFF_KL + 64*KSTR*2)
#define OFF_VL (OFF_VH + 64*KSTR*2)
#define OFF_PH (OFF_VL + 64*KSTR*2)
#define OFF_PL (OFF_PH + 128*PSTR*2)
#define OFF_F32 (OFF_PL + 128*PSTR*2)
#define FLASH_SMEM (OFF_F32 + (128*3 + 256*2)*4)

__global__ __launch_bounds__(256, 1)
void flash_mma(const float* __restrict__ mask, const float* __restrict__ alibi)
{
    extern __shared__ char sm[];
    bf16* sQh = (bf16*)(sm + OFF_QH);
    bf16* sQl = (bf16*)(sm + OFF_QL);
    bf16* sKh = (bf16*)(sm + OFF_KH);
    bf16* sKl = (bf16*)(sm + OFF_KL);
    bf16* sVh = (bf16*)(sm + OFF_VH);
    bf16* sVl = (bf16*)(sm + OFF_VL);
    bf16* sPh = (bf16*)(sm + OFF_PH);
    bf16* sPl = (bf16*)(sm + OFF_PL);
    float* m_s = (float*)(sm + OFF_F32);
    float* l_s = m_s + 128;
    float* c_s = l_s + 128;
    float* redmax = c_s + 128;     // [128][2]
    float* redsum = redmax + 256;  // [128][2]

    const int t    = threadIdx.x;
    const int lane = t & 31;
    const int wid  = t >> 5;
    const int rm   = wid >> 1;      // 0..3 : 32-row group
    const int cn   = wid & 1;       // 0..1 : col half
    const int qb   = blockIdx.x;
    const int bh   = blockIdx.y;
    const int h    = bh & (NHEAD - 1);
    const int b    = bh >> 4;
    const int qi0  = qb * BQ;
    const size_t hbase = (size_t)bh * SEQ * DHEAD;

    // load Q tiles (hi/lo)
    #pragma unroll
    for (int rep = 0; rep < 8; rep++) {
        int u = t + rep * 256;
        int row = u >> 4, c8 = (u & 15) * 8;
        size_t go = hbase + (size_t)(qi0 + row) * DHEAD + c8;
        *(uint4*)&sQh[row*QSTR + c8] = *(const uint4*)(g_Qh + go);
        *(uint4*)&sQl[row*QSTR + c8] = *(const uint4*)(g_Ql + go);
    }
    if (t < 128) { m_s[t] = -1e30f; l_s[t] = 0.f; }

    const int lrow = lane & 15, lcol = lane >> 4;
    const int g = lane >> 2, tq = lane & 3;
    const float SCALE = 0.08838834764831845f;  // 1/sqrt(128)

    const uint32_t uQh = smem_u32(sQh), uQl = smem_u32(sQl);
    const uint32_t uKh = smem_u32(sKh), uKl = smem_u32(sKl);
    const uint32_t uVh = smem_u32(sVh), uVl = smem_u32(sVl);
    const uint32_t uPh = smem_u32(sPh), uPl = smem_u32(sPl);

    float o[2][8][4];
    #pragma unroll
    for (int mt = 0; mt < 2; mt++)
        #pragma unroll
        for (int nt = 0; nt < 8; nt++)
            #pragma unroll
            for (int q = 0; q < 4; q++)
                o[mt][nt][q] = 0.f;

    for (int kt = 0; kt < SEQ / BK; kt++) {
        const int kj0 = kt * BK;
        __syncthreads();
        // load K/V tiles (hi/lo)
        #pragma unroll
        for (int rep = 0; rep < 4; rep++) {
            int u = t + rep * 256;
            int row = u >> 4, c8 = (u & 15) * 8;
            size_t go = hbase + (size_t)(kj0 + row) * DHEAD + c8;
            *(uint4*)&sKh[row*KSTR + c8] = *(const uint4*)(g_Kh + go);
            *(uint4*)&sKl[row*KSTR + c8] = *(const uint4*)(g_Kl + go);
            *(uint4*)&sVh[row*KSTR + c8] = *(const uint4*)(g_Vh + go);
            *(uint4*)&sVl[row*KSTR + c8] = *(const uint4*)(g_Vl + go);
        }
        __syncthreads();

        // S = Q K^T (3-product), warp tile 32x32
        float sacc[2][4][4];
        #pragma unroll
        for (int mt = 0; mt < 2; mt++)
            #pragma unroll
            for (int nt = 0; nt < 4; nt++)
                #pragma unroll
                for (int q = 0; q < 4; q++)
                    sacc[mt][nt][q] = 0.f;
        #pragma unroll
        for (int kk = 0; kk < 8; kk++) {
            uint32_t ah[2][4], al[2][4], kbh[2][4], kbl[2][4];
            #pragma unroll
            for (int mt = 0; mt < 2; mt++) {
                uint32_t off = (uint32_t)((rm*32 + mt*16 + lrow)*QSTR + kk*16 + lcol*8) * 2;
                ldm4(ah[mt], uQh + off);
                ldm4(al[mt], uQl + off);
            }
            #pragma unroll
            for (int n2 = 0; n2 < 2; n2++) {
                uint32_t off = (uint32_t)((cn*32 + n2*16 + lrow)*KSTR + kk*16 + lcol*8) * 2;
                ldm4(kbh[n2], uKh + off);
                ldm4(kbl[n2], uKl + off);
            }
            #pragma unroll
            for (int mt = 0; mt < 2; mt++)
                #pragma unroll
                for (int nt = 0; nt < 4; nt++) {
                    int n2 = nt >> 1, hb = nt & 1;
                    mma16816(sacc[mt][nt], ah[mt], kbh[n2][hb], kbh[n2][hb+2]);
                    mma16816(sacc[mt][nt], ah[mt], kbl[n2][hb], kbl[n2][hb+2]);
                    mma16816(sacc[mt][nt], al[mt], kbh[n2][hb], kbh[n2][hb+2]);
                }
        }

        // scale + mask + alibi, local row max
        float rmax[4] = {-1e30f, -1e30f, -1e30f, -1e30f};
        #pragma unroll
        for (int mt = 0; mt < 2; mt++)
            #pragma unroll
            for (int nt = 0; nt < 4; nt++) {
                int col = kj0 + cn*32 + nt*8 + 2*tq;
                float2 av = *(const float2*)(alibi + (size_t)h * SEQ + col);
                int r0 = qi0 + rm*32 + mt*16 + g;
                float2 mv0 = *(const float2*)(mask + (size_t)r0 * SEQ + col);
                float2 mv1 = *(const float2*)(mask + (size_t)(r0 + 8) * SEQ + col);
                sacc[mt][nt][0] = fmaf(sacc[mt][nt][0], SCALE, mv0.x + av.x);
                sacc[mt][nt][1] = fmaf(sacc[mt][nt][1], SCALE, mv0.y + av.y);
                sacc[mt][nt][2] = fmaf(sacc[mt][nt][2], SCALE, mv1.x + av.x);
                sacc[mt][nt][3] = fmaf(sacc[mt][nt][3], SCALE, mv1.y + av.y);
                rmax[mt*2+0] = fmaxf(rmax[mt*2+0], fmaxf(sacc[mt][nt][0], sacc[mt][nt][1]));
                rmax[mt*2+1] = fmaxf(rmax[mt*2+1], fmaxf(sacc[mt][nt][2], sacc[mt][nt][3]));
            }
        #pragma unroll
        for (int off = 1; off <= 2; off <<= 1)
            #pragma unroll
            for (int i = 0; i < 4; i++)
                rmax[i] = fmaxf(rmax[i], __shfl_xor_sync(0xffffffffu, rmax[i], off));
        if (tq == 0) {
            #pragma unroll
            for (int mt = 0; mt < 2; mt++)
                #pragma unroll
                for (int hf = 0; hf < 2; hf++)
                    redmax[(rm*32 + mt*16 + hf*8 + g)*2 + cn] = rmax[mt*2+hf];
        }
        __syncthreads();
        if (t < 128) {
            float nm = fmaxf(m_s[t], fmaxf(redmax[t*2], redmax[t*2+1]));
            c_s[t] = __expf(m_s[t] - nm);
            m_s[t] = nm;
        }
        __syncthreads();

        // exp, write P hi/lo to smem, row sums
        float rsum[4] = {0.f, 0.f, 0.f, 0.f};
        #pragma unroll
        for (int mt = 0; mt < 2; mt++)
            #pragma unroll
            for (int hf = 0; hf < 2; hf++) {
                int row = rm*32 + mt*16 + hf*8 + g;
                float rowm = m_s[row];
                #pragma unroll
                for (int nt = 0; nt < 4; nt++) {
                    float p0 = __expf(sacc[mt][nt][hf*2+0] - rowm);
                    float p1 = __expf(sacc[mt][nt][hf*2+1] - rowm);
                    rsum[mt*2+hf] += p0 + p1;
                    int pc = cn*32 + nt*8 + 2*tq;
                    bf16 h0, l0, h1, l1;
                    split1(p0, h0, l0); split1(p1, h1, l1);
                    *(uint32_t*)&sPh[row*PSTR + pc] =
                        ((uint32_t)__bfloat16_as_ushort(h1)<<16)|__bfloat16_as_ushort(h0);
                    *(uint32_t*)&sPl[row*PSTR + pc] =
                        ((uint32_t)__bfloat16_as_ushort(l1)<<16)|__bfloat16_as_ushort(l0);
                }
            }
        #pragma unroll
        for (int off = 1; off <= 2; off <<= 1)
            #pragma unroll
            for (int i = 0; i < 4; i++)
                rsum[i] += __shfl_xor_sync(0xffffffffu, rsum[i], off);
        if (tq == 0) {
            #pragma unroll
            for (int mt = 0; mt < 2; mt++)
                #pragma unroll
                for (int hf = 0; hf < 2; hf++)
                    redsum[(rm*32 + mt*16 + hf*8 + g)*2 + cn] = rsum[mt*2+hf];
        }
        __syncthreads();
        if (t < 128) l_s[t] = l_s[t] * c_s[t] + redsum[t*2] + redsum[t*2+1];

        // rescale O by c
        #pragma unroll
        for (int mt = 0; mt < 2; mt++) {
            float c0 = c_s[rm*32 + mt*16 + g];
            float c1 = c_s[rm*32 + mt*16 + 8 + g];
            #pragma unroll
            for (int nt = 0; nt < 8; nt++) {
                o[mt][nt][0] *= c0; o[mt][nt][1] *= c0;
                o[mt][nt][2] *= c1; o[mt][nt][3] *= c1;
            }
        }

        // O += P V (3-product), warp O tile 32x64
        #pragma unroll
        for (int kk = 0; kk < 4; kk++) {
            uint32_t ph[2][4], pl[2][4];
            #pragma unroll
            for (int mt = 0; mt < 2; mt++) {
                uint32_t off = (uint32_t)((rm*32 + mt*16 + lrow)*PSTR + kk*16 + lcol*8) * 2;
                ldm4(ph[mt], uPh + off);
                ldm4(pl[mt], uPl + off);
            }
            #pragma unroll
            for (int dd = 0; dd < 4; dd++) {
                uint32_t vh_[4], vl_[4];
                uint32_t off = (uint32_t)((kk*16 + lrow)*KSTR + cn*64 + dd*16 + lcol*8) * 2;
                ldm4t(vh_, uVh + off);
                ldm4t(vl_, uVl + off);
                #pragma unroll
                for (int mt = 0; mt < 2; mt++) {
                    mma16816(o[mt][dd*2+0], ph[mt], vh_[0], vh_[1]);
                    mma16816(o[mt][dd*2+0], ph[mt], vl_[0], vl_[1]);
                    mma16816(o[mt][dd*2+0], pl[mt], vh_[0], vh_[1]);
                    mma16816(o[mt][dd*2+1], ph[mt], vh_[2], vh_[3]);
                    mma16816(o[mt][dd*2+1], ph[mt], vl_[2], vl_[3]);
                    mma16816(o[mt][dd*2+1], pl[mt], vh_[2], vh_[3]);
                }
            }
        }
    }

    __syncthreads();

    // epilogue: normalize, split to bf16 hi/lo ctx [tok][h*128+d]
    #pragma unroll
    for (int mt = 0; mt < 2; mt++)
        #pragma unroll
        for (int hf = 0; hf < 2; hf++) {
            int row = rm*32 + mt*16 + hf*8 + g;
            float inv = 1.f / l_s[row];
            size_t tokbase = ((size_t)(b*SEQ + qi0 + row)) * HID + h * DHEAD;
            #pragma unroll
            for (int nt = 0; nt < 8; nt++) {
                int d = cn*64 + nt*8 + 2*tq;
                float v0 = o[mt][nt][hf*2+0] * inv;
                float v1 = o[mt][nt][hf*2+1] * inv;
                bf16 h0, l0, h1, l1;
                split1(v0, h0, l0); split1(v1, h1, l1);
                *(uint32_t*)&g_ch[tokbase + d] =
                    ((uint32_t)__bfloat16_as_ushort(h1)<<16)|__bfloat16_as_ushort(h0);
                *(uint32_t*)&g_cl[tokbase + d] =
                    ((uint32_t)__bfloat16_as_ushort(l1)<<16)|__bfloat16_as_ushort(l0);
            }
        }
}

// ---------------------------------------------------------------------------
extern "C" void kernel_launch(void* const* d_in, const int* in_sizes, int n_in,
                              void* d_out, int out_size)
{
    const float* x     = (const float*)d_in[0];
    const float* mask  = (const float*)d_in[1];
    const float* alibi = (const float*)d_in[2];
    const float* freqs = (const float*)d_in[3];
    const float* W[4]  = { (const float*)d_in[4], (const float*)d_in[5],
                           (const float*)d_in[6], (const float*)d_in[7] };
    float* out = (float*)d_out;
    (void)in_sizes; (void)n_in; (void)out_size;

    cudaFuncSetAttribute(flash_mma,
                         cudaFuncAttributeMaxDynamicSharedMemorySize, FLASH_SMEM);

    bf16 *xh, *xl, *ch, *cl, *wh[4], *wl[4];
    cudaGetSymbolAddress((void**)&xh, g_xh);
    cudaGetSymbolAddress((void**)&xl, g_xl);
    cudaGetSymbolAddress((void**)&ch, g_ch);
    cudaGetSymbolAddress((void**)&cl, g_cl);
    {
        bf16 *p;
        cudaGetSymbolAddress((void**)&p, g_wh);
        wh[0]=p; wh[1]=p+(size_t)HID*HID; wh[2]=p+2*(size_t)HID*HID; wh[3]=p+3*(size_t)HID*HID;
        cudaGetSymbolAddress((void**)&p, g_wl);
        wl[0]=p; wl[1]=p+(size_t)HID*HID; wl[2]=p+2*(size_t)HID*HID; wl[3]=p+3*(size_t)HID*HID;
    }

    {
        int n4 = NTOK * HID / 4;
        split_kernel<<<(n4 + 255) / 256, 256>>>(x, xh, xl, n4);
        int w4 = HID * HID / 4;
        for (int i = 0; i < 4; i++)
            split_kernel<<<(w4 + 255) / 256, 256>>>(W[i], wh[i], wl[i], w4);
    }

    dim3 gg(HID / 128, NTOK / 128);

    mma_gemm<<<gg, 256>>>(xh, xl, wh[0], wl[0], nullptr, 0);
    mma_gemm<<<gg, 256>>>(xh, xl, wh[1], wl[1], nullptr, 1);
    mma_gemm<<<gg, 256>>>(xh, xl, wh[2], wl[2], nullptr, 2);

    rope_split<<<(2*NBATCH*NHEAD*SEQ*64) / 256, 256>>>(freqs);

    flash_mma<<<dim3(SEQ/BQ, NBATCH*NHEAD), 256, FLASH_SMEM>>>(mask, alibi);

    mma_gemm<<<gg, 256>>>(ch, cl, wh[3], wl[3], out, 3);
}

// round 6
// speedup vs baseline: 2.3469x; 1.0886x over previous
#include <cuda_runtime.h>
#include <cuda_bf16.h>
#include <math.h>
#include <cstdint>

typedef __nv_bfloat16 bf16;

// Problem constants
#define NBATCH 2
#define SEQ    2048
#define NHEAD  16
#define DHEAD  128
#define HID    2048
#define NTOK   4096   // NBATCH*SEQ

// Scratch (device globals — no runtime allocation allowed)
__device__ float g_Q[NBATCH*NHEAD*SEQ*DHEAD];   // fp32, pre-RoPE
__device__ float g_K[NBATCH*NHEAD*SEQ*DHEAD];

__device__ bf16 g_Qh[NBATCH*NHEAD*SEQ*DHEAD];   // post-RoPE hi/lo
__device__ bf16 g_Ql[NBATCH*NHEAD*SEQ*DHEAD];
__device__ bf16 g_Kh[NBATCH*NHEAD*SEQ*DHEAD];
__device__ bf16 g_Kl[NBATCH*NHEAD*SEQ*DHEAD];
__device__ bf16 g_Vh[NBATCH*NHEAD*SEQ*DHEAD];
__device__ bf16 g_Vl[NBATCH*NHEAD*SEQ*DHEAD];

__device__ bf16 g_xh[(size_t)NTOK*HID];
__device__ bf16 g_xl[(size_t)NTOK*HID];
__device__ bf16 g_ch[(size_t)NTOK*HID];         // ctx hi/lo (flash output)
__device__ bf16 g_cl[(size_t)NTOK*HID];
__device__ bf16 g_wh[4][(size_t)HID*HID];
__device__ bf16 g_wl[4][(size_t)HID*HID];

// ---------------------------------------------------------------------------
// helpers
// ---------------------------------------------------------------------------
__device__ __forceinline__ uint32_t smem_u32(const void* p) {
    uint32_t a;
    asm("{ .reg .u64 t; cvta.to.shared.u64 t, %1; cvt.u32.u64 %0, t; }"
        : "=r"(a) : "l"(p));
    return a;
}
__device__ __forceinline__ void ldm4(uint32_t* r, uint32_t addr) {
    asm volatile("ldmatrix.sync.aligned.m8n8.x4.shared.b16 {%0,%1,%2,%3},[%4];"
                 : "=r"(r[0]), "=r"(r[1]), "=r"(r[2]), "=r"(r[3]) : "r"(addr));
}
__device__ __forceinline__ void ldm4t(uint32_t* r, uint32_t addr) {
    asm volatile("ldmatrix.sync.aligned.m8n8.x4.trans.shared.b16 {%0,%1,%2,%3},[%4];"
                 : "=r"(r[0]), "=r"(r[1]), "=r"(r[2]), "=r"(r[3]) : "r"(addr));
}
__device__ __forceinline__ void mma16816(float* d, const uint32_t* a,
                                         uint32_t b0, uint32_t b1) {
    asm volatile(
        "mma.sync.aligned.m16n8k16.row.col.f32.bf16.bf16.f32 "
        "{%0,%1,%2,%3},{%4,%5,%6,%7},{%8,%9},{%0,%1,%2,%3};"
        : "+f"(d[0]), "+f"(d[1]), "+f"(d[2]), "+f"(d[3])
        : "r"(a[0]), "r"(a[1]), "r"(a[2]), "r"(a[3]), "r"(b0), "r"(b1));
}
__device__ __forceinline__ void split1(float v, bf16& h, bf16& l) {
    h = __float2bfloat16_rn(v);
    l = __float2bfloat16_rn(v - __bfloat162float(h));
}
__device__ __forceinline__ void cpa16(uint32_t s, const void* g) {
    asm volatile("cp.async.cg.shared.global [%0], [%1], 16;" :: "r"(s), "l"(g));
}
#define CP_COMMIT() asm volatile("cp.async.commit_group;" ::: "memory")
#define CP_WAIT0()  asm volatile("cp.async.wait_group 0;" ::: "memory")

// ---------------------------------------------------------------------------
// Split: fp32 -> bf16 hi + bf16 lo
// ---------------------------------------------------------------------------
__global__ __launch_bounds__(256)
void split_kernel(const float* __restrict__ src,
                  bf16* __restrict__ h, bf16* __restrict__ l, int n4)
{
    int i = blockIdx.x * 256 + threadIdx.x;
    if (i >= n4) return;
    float4 v = ((const float4*)src)[i];
    float vv[4] = {v.x, v.y, v.z, v.w};
    unsigned short hu[4], lu[4];
    #pragma unroll
    for (int j = 0; j < 4; j++) {
        bf16 hb, lb; split1(vv[j], hb, lb);
        hu[j] = __bfloat16_as_ushort(hb);
        lu[j] = __bfloat16_as_ushort(lb);
    }
    ((uint2*)h)[i] = make_uint2(((uint32_t)hu[1] << 16) | hu[0], ((uint32_t)hu[3] << 16) | hu[2]);
    ((uint2*)l)[i] = make_uint2(((uint32_t)lu[1] << 16) | lu[0], ((uint32_t)lu[3] << 16) | lu[2]);
}

// ---------------------------------------------------------------------------
// Tensor-core GEMM with cp.async 2-stage pipeline.
// C[m][n] = sum_k A[m][k]*W[n][k]; A/W bf16 hi/lo, 3-product emulation.
// sel 0/1 -> fp32 bhsd into g_Q/g_K; sel 2 -> bf16 hi/lo bhsd into g_Vh/g_Vl;
// sel 3 -> fp32 row-major to Cout.
// ---------------------------------------------------------------------------
#define SPAD 40
#define ARR_B   (128*SPAD*2)          // bytes per operand array (10240)
#define STAGE_B (4*ARR_B)             // 40960
#define GEMM_SMEM (2*STAGE_B)         // 81920

__global__ __launch_bounds__(256)
void mma_gemm(const bf16* __restrict__ Ah, const bf16* __restrict__ Al,
              const bf16* __restrict__ Bh, const bf16* __restrict__ Bl,
              float* __restrict__ Cout, int sel)
{
    extern __shared__ char dsm[];
    const uint32_t ub = smem_u32(dsm);

    const int t    = threadIdx.x;
    const int wid  = t >> 5;
    const int lane = t & 31;
    const int m0   = blockIdx.y << 7;
    const int n0   = blockIdx.x << 7;
    const int wm   = wid & 1;
    const int wn   = wid >> 1;

    int rowL[2], qdL[2];
    #pragma unroll
    for (int r = 0; r < 2; r++) {
        int u = t + (r << 8);
        rowL[r] = u >> 2;
        qdL[r]  = u & 3;
    }

    const bf16* pAh = Ah + (size_t)m0 * HID;
    const bf16* pAl = Al + (size_t)m0 * HID;
    const bf16* pBh = Bh + (size_t)n0 * HID;
    const bf16* pBl = Bl + (size_t)n0 * HID;

    float acc[4][4][4];
    #pragma unroll
    for (int i = 0; i < 4; i++)
        #pragma unroll
        for (int j = 0; j < 4; j++)
            #pragma unroll
            for (int q = 0; q < 4; q++)
                acc[i][j][q] = 0.f;

    const int lrow = lane & 15, lcol = lane >> 4;
    const int NCH = HID / 32;   // 64 chunks

    // issue async loads for chunk c into buffer buf
    auto issue = [&](int c, int buf) {
        uint32_t sb = ub + buf * STAGE_B;
        #pragma unroll
        for (int r = 0; r < 2; r++) {
            int row = rowL[r], qd = qdL[r];
            uint32_t so = (uint32_t)(row * SPAD + qd * 8) * 2;
            size_t   go = (size_t)row * HID + (size_t)c * 32 + qd * 8;
            cpa16(sb + so,             pAh + go);
            cpa16(sb + ARR_B + so,     pAl + go);
            cpa16(sb + 2*ARR_B + so,   pBh + go);
            cpa16(sb + 3*ARR_B + so,   pBl + go);
        }
        CP_COMMIT();
    };

    issue(0, 0);

    for (int c = 0; c < NCH; c++) {
        CP_WAIT0();
        __syncthreads();
        if (c + 1 < NCH) issue(c + 1, (c + 1) & 1);

        const uint32_t sb  = ub + (c & 1) * STAGE_B;
        const uint32_t uAh = sb;
        const uint32_t uAl = sb + ARR_B;
        const uint32_t uBh = sb + 2*ARR_B;
        const uint32_t uBl = sb + 3*ARR_B;

        #pragma unroll
        for (int kh = 0; kh < 2; kh++) {
            uint32_t ah[4][4], al[4][4], bh[2][4], bl[2][4];
            #pragma unroll
            for (int mt = 0; mt < 4; mt++) {
                uint32_t off = (uint32_t)((wm*64 + mt*16 + lrow) * SPAD + kh*16 + lcol*8) * 2;
                ldm4(ah[mt], uAh + off);
                ldm4(al[mt], uAl + off);
            }
            #pragma unroll
            for (int n2 = 0; n2 < 2; n2++) {
                uint32_t off = (uint32_t)((wn*32 + n2*16 + lrow) * SPAD + kh*16 + lcol*8) * 2;
                ldm4(bh[n2], uBh + off);
                ldm4(bl[n2], uBl + off);
            }
            #pragma unroll
            for (int mt = 0; mt < 4; mt++)
                #pragma unroll
                for (int nt = 0; nt < 4; nt++) {
                    int n2 = nt >> 1, hb = nt & 1;
                    mma16816(acc[mt][nt], ah[mt], bh[n2][hb], bh[n2][hb+2]);
                    mma16816(acc[mt][nt], ah[mt], bl[n2][hb], bl[n2][hb+2]);
                    mma16816(acc[mt][nt], al[mt], bh[n2][hb], bh[n2][hb+2]);
                }
        }
    }

    const int rbase = wm*64 + (lane >> 2);
    const int cbase = wn*32 + 2*(lane & 3);
    if (sel == 3) {
        #pragma unroll
        for (int mt = 0; mt < 4; mt++)
            #pragma unroll
            for (int nt = 0; nt < 4; nt++) {
                int r0 = m0 + rbase + mt*16;
                int cc = n0 + cbase + nt*8;
                *(float2*)&Cout[(size_t)r0 * HID + cc]       = make_float2(acc[mt][nt][0], acc[mt][nt][1]);
                *(float2*)&Cout[(size_t)(r0 + 8) * HID + cc] = make_float2(acc[mt][nt][2], acc[mt][nt][3]);
            }
    } else if (sel == 2) {
        const int h = n0 >> 7;
        #pragma unroll
        for (int mt = 0; mt < 4; mt++)
            #pragma unroll
            for (int nt = 0; nt < 4; nt++) {
                int r0 = m0 + rbase + mt*16;
                int b  = r0 >> 11;
                int s  = r0 & (SEQ - 1);
                int d  = cbase + nt*8;
                size_t base = (((size_t)(b*NHEAD + h))*SEQ + s)*DHEAD + d;
                bf16 h0,l0,h1,l1;
                split1(acc[mt][nt][0], h0, l0); split1(acc[mt][nt][1], h1, l1);
                *(uint32_t*)&g_Vh[base] = ((uint32_t)__bfloat16_as_ushort(h1)<<16)|__bfloat16_as_ushort(h0);
                *(uint32_t*)&g_Vl[base] = ((uint32_t)__bfloat16_as_ushort(l1)<<16)|__bfloat16_as_ushort(l0);
                split1(acc[mt][nt][2], h0, l0); split1(acc[mt][nt][3], h1, l1);
                *(uint32_t*)&g_Vh[base + 8*DHEAD] = ((uint32_t)__bfloat16_as_ushort(h1)<<16)|__bfloat16_as_ushort(h0);
                *(uint32_t*)&g_Vl[base + 8*DHEAD] = ((uint32_t)__bfloat16_as_ushort(l1)<<16)|__bfloat16_as_ushort(l0);
            }
    } else {
        float* outp = (sel == 0) ? g_Q : g_K;
        const int h = n0 >> 7;
        #pragma unroll
        for (int mt = 0; mt < 4; mt++)
            #pragma unroll
            for (int nt = 0; nt < 4; nt++) {
                int r0 = m0 + rbase + mt*16;
                int b  = r0 >> 11;
                int s  = r0 & (SEQ - 1);
                int d  = cbase + nt*8;
                size_t base = (((size_t)(b*NHEAD + h))*SEQ + s)*DHEAD + d;
                *(float2*)&outp[base]           = make_float2(acc[mt][nt][0], acc[mt][nt][1]);
                *(float2*)&outp[base + 8*DHEAD] = make_float2(acc[mt][nt][2], acc[mt][nt][3]);
            }
    }
}

// ---------------------------------------------------------------------------
// RoPE + split: read fp32 g_Q/g_K, rotate, write bf16 hi/lo.
// ---------------------------------------------------------------------------
__global__ __launch_bounds__(256)
void rope_split(const float* __restrict__ freqs)
{
    int tid = blockIdx.x * 256 + threadIdx.x;
    bool isK = (tid >> 22) != 0;
    const float* src = isK ? g_K : g_Q;
    bf16* dh = isK ? g_Kh : g_Qh;
    bf16* dl = isK ? g_Kl : g_Ql;
    int rem = tid & ((1 << 22) - 1);
    int d   = rem & 63;
    int s   = (rem >> 6) & (SEQ - 1);
    int bh  = rem >> 17;
    size_t base = ((size_t)bh * SEQ + s) * DHEAD;
    float f1 = freqs[s*DHEAD + d];
    float f2 = freqs[s*DHEAD + d + 64];
    float x1 = src[base + d];
    float x2 = src[base + d + 64];
    float y1 = x1 * cosf(f1) - x2 * sinf(f1);
    float y2 = x2 * cosf(f2) + x1 * sinf(f2);
    bf16 h, l;
    split1(y1, h, l); dh[base + d]      = h; dl[base + d]      = l;
    split1(y2, h, l); dh[base + d + 64] = h; dl[base + d + 64] = l;
}

// ---------------------------------------------------------------------------
// Flash attention, mma.sync bf16 3-product (R5, passing).
// ---------------------------------------------------------------------------
#define BQ 128
#define BK 64
#define QSTR 136
#define KSTR 136
#define PSTR 72

#define OFF_QH 0
#define OFF_QL (OFF_QH + 128*QSTR*2)
#define OFF_KH (OFF_QL + 128*QSTR*2)
#define OFF_KL (OFF_KH + 64*KSTR*2)
#define OFF_VH (OFF_KL + 64*KSTR*2)
#define OFF_VL (OFF_VH + 64*KSTR*2)
#define OFF_PH (OFF_VL + 64*KSTR*2)
#define OFF_PL (OFF_PH + 128*PSTR*2)
#define OFF_F32 (OFF_PL + 128*PSTR*2)
#define FLASH_SMEM (OFF_F32 + (128*3 + 256*2)*4)

__global__ __launch_bounds__(256, 1)
void flash_mma(const float* __restrict__ mask, const float* __restrict__ alibi)
{
    extern __shared__ char sm[];
    bf16* sQh = (bf16*)(sm + OFF_QH);
    bf16* sQl = (bf16*)(sm + OFF_QL);
    bf16* sKh = (bf16*)(sm + OFF_KH);
    bf16* sKl = (bf16*)(sm + OFF_KL);
    bf16* sVh = (bf16*)(sm + OFF_VH);
    bf16* sVl = (bf16*)(sm + OFF_VL);
    bf16* sPh = (bf16*)(sm + OFF_PH);
    bf16* sPl = (bf16*)(sm + OFF_PL);
    float* m_s = (float*)(sm + OFF_F32);
    float* l_s = m_s + 128;
    float* c_s = l_s + 128;
    float* redmax = c_s + 128;     // [128][2]
    float* redsum = redmax + 256;  // [128][2]

    const int t    = threadIdx.x;
    const int lane = t & 31;
    const int wid  = t >> 5;
    const int rm   = wid >> 1;
    const int cn   = wid & 1;
    const int qb   = blockIdx.x;
    const int bh   = blockIdx.y;
    const int h    = bh & (NHEAD - 1);
    const int b    = bh >> 4;
    const int qi0  = qb * BQ;
    const size_t hbase = (size_t)bh * SEQ * DHEAD;

    #pragma unroll
    for (int rep = 0; rep < 8; rep++) {
        int u = t + rep * 256;
        int row = u >> 4, c8 = (u & 15) * 8;
        size_t go = hbase + (size_t)(qi0 + row) * DHEAD + c8;
        *(uint4*)&sQh[row*QSTR + c8] = *(const uint4*)(g_Qh + go);
        *(uint4*)&sQl[row*QSTR + c8] = *(const uint4*)(g_Ql + go);
    }
    if (t < 128) { m_s[t] = -1e30f; l_s[t] = 0.f; }

    const int lrow = lane & 15, lcol = lane >> 4;
    const int g = lane >> 2, tq = lane & 3;
    const float SCALE = 0.08838834764831845f;  // 1/sqrt(128)

    const uint32_t uQh = smem_u32(sQh), uQl = smem_u32(sQl);
    const uint32_t uKh = smem_u32(sKh), uKl = smem_u32(sKl);
    const uint32_t uVh = smem_u32(sVh), uVl = smem_u32(sVl);
    const uint32_t uPh = smem_u32(sPh), uPl = smem_u32(sPl);

    float o[2][8][4];
    #pragma unroll
    for (int mt = 0; mt < 2; mt++)
        #pragma unroll
        for (int nt = 0; nt < 8; nt++)
            #pragma unroll
            for (int q = 0; q < 4; q++)
                o[mt][nt][q] = 0.f;

    for (int kt = 0; kt < SEQ / BK; kt++) {
        const int kj0 = kt * BK;
        __syncthreads();
        #pragma unroll
        for (int rep = 0; rep < 4; rep++) {
            int u = t + rep * 256;
            int row = u >> 4, c8 = (u & 15) * 8;
            size_t go = hbase + (size_t)(kj0 + row) * DHEAD + c8;
            *(uint4*)&sKh[row*KSTR + c8] = *(const uint4*)(g_Kh + go);
            *(uint4*)&sKl[row*KSTR + c8] = *(const uint4*)(g_Kl + go);
            *(uint4*)&sVh[row*KSTR + c8] = *(const uint4*)(g_Vh + go);
            *(uint4*)&sVl[row*KSTR + c8] = *(const uint4*)(g_Vl + go);
        }
        __syncthreads();

        float sacc[2][4][4];
        #pragma unroll
        for (int mt = 0; mt < 2; mt++)
            #pragma unroll
            for (int nt = 0; nt < 4; nt++)
                #pragma unroll
                for (int q = 0; q < 4; q++)
                    sacc[mt][nt][q] = 0.f;
        #pragma unroll
        for (int kk = 0; kk < 8; kk++) {
            uint32_t ah[2][4], al[2][4], kbh[2][4], kbl[2][4];
            #pragma unroll
            for (int mt = 0; mt < 2; mt++) {
                uint32_t off = (uint32_t)((rm*32 + mt*16 + lrow)*QSTR + kk*16 + lcol*8) * 2;
                ldm4(ah[mt], uQh + off);
                ldm4(al[mt], uQl + off);
            }
            #pragma unroll
            for (int n2 = 0; n2 < 2; n2++) {
                uint32_t off = (uint32_t)((cn*32 + n2*16 + lrow)*KSTR + kk*16 + lcol*8) * 2;
                ldm4(kbh[n2], uKh + off);
                ldm4(kbl[n2], uKl + off);
            }
            #pragma unroll
            for (int mt = 0; mt < 2; mt++)
                #pragma unroll
                for (int nt = 0; nt < 4; nt++) {
                    int n2 = nt >> 1, hb = nt & 1;
                    mma16816(sacc[mt][nt], ah[mt], kbh[n2][hb], kbh[n2][hb+2]);
                    mma16816(sacc[mt][nt], ah[mt], kbl[n2][hb], kbl[n2][hb+2]);
                    mma16816(sacc[mt][nt], al[mt], kbh[n2][hb], kbh[n2][hb+2]);
                }
        }

        float rmax[4] = {-1e30f, -1e30f, -1e30f, -1e30f};
        #pragma unroll
        for (int mt = 0; mt < 2; mt++)
            #pragma unroll
            for (int nt = 0; nt < 4; nt++) {
                int col = kj0 + cn*32 + nt*8 + 2*tq;
                float2 av = *(const float2*)(alibi + (size_t)h * SEQ + col);
                int r0 = qi0 + rm*32 + mt*16 + g;
                float2 mv0 = *(const float2*)(mask + (size_t)r0 * SEQ + col);
                float2 mv1 = *(const float2*)(mask + (size_t)(r0 + 8) * SEQ + col);
                sacc[mt][nt][0] = fmaf(sacc[mt][nt][0], SCALE, mv0.x + av.x);
                sacc[mt][nt][1] = fmaf(sacc[mt][nt][1], SCALE, mv0.y + av.y);
                sacc[mt][nt][2] = fmaf(sacc[mt][nt][2], SCALE, mv1.x + av.x);
                sacc[mt][nt][3] = fmaf(sacc[mt][nt][3], SCALE, mv1.y + av.y);
                rmax[mt*2+0] = fmaxf(rmax[mt*2+0], fmaxf(sacc[mt][nt][0], sacc[mt][nt][1]));
                rmax[mt*2+1] = fmaxf(rmax[mt*2+1], fmaxf(sacc[mt][nt][2], sacc[mt][nt][3]));
            }
        #pragma unroll
        for (int off = 1; off <= 2; off <<= 1)
            #pragma unroll
            for (int i = 0; i < 4; i++)
                rmax[i] = fmaxf(rmax[i], __shfl_xor_sync(0xffffffffu, rmax[i], off));
        if (tq == 0) {
            #pragma unroll
            for (int mt = 0; mt < 2; mt++)
                #pragma unroll
                for (int hf = 0; hf < 2; hf++)
                    redmax[(rm*32 + mt*16 + hf*8 + g)*2 + cn] = rmax[mt*2+hf];
        }
        __syncthreads();
        if (t < 128) {
            float nm = fmaxf(m_s[t], fmaxf(redmax[t*2], redmax[t*2+1]));
            c_s[t] = __expf(m_s[t] - nm);
            m_s[t] = nm;
        }
        __syncthreads();

        float rsum[4] = {0.f, 0.f, 0.f, 0.f};
        #pragma unroll
        for (int mt = 0; mt < 2; mt++)
            #pragma unroll
            for (int hf = 0; hf < 2; hf++) {
                int row = rm*32 + mt*16 + hf*8 + g;
                float rowm = m_s[row];
                #pragma unroll
                for (int nt = 0; nt < 4; nt++) {
                    float p0 = __expf(sacc[mt][nt][hf*2+0] - rowm);
                    float p1 = __expf(sacc[mt][nt][hf*2+1] - rowm);
                    rsum[mt*2+hf] += p0 + p1;
                    int pc = cn*32 + nt*8 + 2*tq;
                    bf16 h0, l0, h1, l1;
                    split1(p0, h0, l0); split1(p1, h1, l1);
                    *(uint32_t*)&sPh[row*PSTR + pc] =
                        ((uint32_t)__bfloat16_as_ushort(h1)<<16)|__bfloat16_as_ushort(h0);
                    *(uint32_t*)&sPl[row*PSTR + pc] =
                        ((uint32_t)__bfloat16_as_ushort(l1)<<16)|__bfloat16_as_ushort(l0);
                }
            }
        #pragma unroll
        for (int off = 1; off <= 2; off <<= 1)
            #pragma unroll
            for (int i = 0; i < 4; i++)
                rsum[i] += __shfl_xor_sync(0xffffffffu, rsum[i], off);
        if (tq == 0) {
            #pragma unroll
            for (int mt = 0; mt < 2; mt++)
                #pragma unroll
                for (int hf = 0; hf < 2; hf++)
                    redsum[(rm*32 + mt*16 + hf*8 + g)*2 + cn] = rsum[mt*2+hf];
        }
        __syncthreads();
        if (t < 128) l_s[t] = l_s[t] * c_s[t] + redsum[t*2] + redsum[t*2+1];

        #pragma unroll
        for (int mt = 0; mt < 2; mt++) {
            float c0 = c_s[rm*32 + mt*16 + g];
            float c1 = c_s[rm*32 + mt*16 + 8 + g];
            #pragma unroll
            for (int nt = 0; nt < 8; nt++) {
                o[mt][nt][0] *= c0; o[mt][nt][1] *= c0;
                o[mt][nt][2] *= c1; o[mt][nt][3] *= c1;
            }
        }

        #pragma unroll
        for (int kk = 0; kk < 4; kk++) {
            uint32_t ph[2][4], pl[2][4];
            #pragma unroll
            for (int mt = 0; mt < 2; mt++) {
                uint32_t off = (uint32_t)((rm*32 + mt*16 + lrow)*PSTR + kk*16 + lcol*8) * 2;
                ldm4(ph[mt], uPh + off);
                ldm4(pl[mt], uPl + off);
            }
            #pragma unroll
            for (int dd = 0; dd < 4; dd++) {
                uint32_t vh_[4], vl_[4];
                uint32_t off = (uint32_t)((kk*16 + lrow)*KSTR + cn*64 + dd*16 + lcol*8) * 2;
                ldm4t(vh_, uVh + off);
                ldm4t(vl_, uVl + off);
                #pragma unroll
                for (int mt = 0; mt < 2; mt++) {
                    mma16816(o[mt][dd*2+0], ph[mt], vh_[0], vh_[1]);
                    mma16816(o[mt][dd*2+0], ph[mt], vl_[0], vl_[1]);
                    mma16816(o[mt][dd*2+0], pl[mt], vh_[0], vh_[1]);
                    mma16816(o[mt][dd*2+1], ph[mt], vh_[2], vh_[3]);
                    mma16816(o[mt][dd*2+1], ph[mt], vl_[2], vl_[3]);
                    mma16816(o[mt][dd*2+1], pl[mt], vh_[2], vh_[3]);
                }
            }
        }
    }

    __syncthreads();

    #pragma unroll
    for (int mt = 0; mt < 2; mt++)
        #pragma unroll
        for (int hf = 0; hf < 2; hf++) {
            int row = rm*32 + mt*16 + hf*8 + g;
            float inv = 1.f / l_s[row];
            size_t tokbase = ((size_t)(b*SEQ + qi0 + row)) * HID + h * DHEAD;
            #pragma unroll
            for (int nt = 0; nt < 8; nt++) {
                int d = cn*64 + nt*8 + 2*tq;
                float v0 = o[mt][nt][hf*2+0] * inv;
                float v1 = o[mt][nt][hf*2+1] * inv;
                bf16 h0, l0, h1, l1;
                split1(v0, h0, l0); split1(v1, h1, l1);
                *(uint32_t*)&g_ch[tokbase + d] =
                    ((uint32_t)__bfloat16_as_ushort(h1)<<16)|__bfloat16_as_ushort(h0);
                *(uint32_t*)&g_cl[tokbase + d] =
                    ((uint32_t)__bfloat16_as_ushort(l1)<<16)|__bfloat16_as_ushort(l0);
            }
        }
}

// ---------------------------------------------------------------------------
extern "C" void kernel_launch(void* const* d_in, const int* in_sizes, int n_in,
                              void* d_out, int out_size)
{
    const float* x     = (const float*)d_in[0];
    const float* mask  = (const float*)d_in[1];
    const float* alibi = (const float*)d_in[2];
    const float* freqs = (const float*)d_in[3];
    const float* W[4]  = { (const float*)d_in[4], (const float*)d_in[5],
                           (const float*)d_in[6], (const float*)d_in[7] };
    float* out = (float*)d_out;
    (void)in_sizes; (void)n_in; (void)out_size;

    cudaFuncSetAttribute(flash_mma,
                         cudaFuncAttributeMaxDynamicSharedMemorySize, FLASH_SMEM);
    cudaFuncSetAttribute(mma_gemm,
                         cudaFuncAttributeMaxDynamicSharedMemorySize, GEMM_SMEM);

    bf16 *xh, *xl, *ch, *cl, *wh[4], *wl[4];
    cudaGetSymbolAddress((void**)&xh, g_xh);
    cudaGetSymbolAddress((void**)&xl, g_xl);
    cudaGetSymbolAddress((void**)&ch, g_ch);
    cudaGetSymbolAddress((void**)&cl, g_cl);
    {
        bf16 *p;
        cudaGetSymbolAddress((void**)&p, g_wh);
        wh[0]=p; wh[1]=p+(size_t)HID*HID; wh[2]=p+2*(size_t)HID*HID; wh[3]=p+3*(size_t)HID*HID;
        cudaGetSymbolAddress((void**)&p, g_wl);
        wl[0]=p; wl[1]=p+(size_t)HID*HID; wl[2]=p+2*(size_t)HID*HID; wl[3]=p+3*(size_t)HID*HID;
    }

    {
        int n4 = NTOK * HID / 4;
        split_kernel<<<(n4 + 255) / 256, 256>>>(x, xh, xl, n4);
        int w4 = HID * HID / 4;
        for (int i = 0; i < 4; i++)
            split_kernel<<<(w4 + 255) / 256, 256>>>(W[i], wh[i], wl[i], w4);
    }

    dim3 gg(HID / 128, NTOK / 128);

    mma_gemm<<<gg, 256, GEMM_SMEM>>>(xh, xl, wh[0], wl[0], nullptr, 0);
    mma_gemm<<<gg, 256, GEMM_SMEM>>>(xh, xl, wh[1], wl[1], nullptr, 1);
    mma_gemm<<<gg, 256, GEMM_SMEM>>>(xh, xl, wh[2], wl[2], nullptr, 2);

    rope_split<<<(2*NBATCH*NHEAD*SEQ*64) / 256, 256>>>(freqs);

    flash_mma<<<dim3(SEQ/BQ, NBATCH*NHEAD), 256, FLASH_SMEM>>>(mask, alibi);

    mma_gemm<<<gg, 256, GEMM_SMEM>>>(ch, cl, wh[3], wl[3], out, 3);
}

// round 7
// speedup vs baseline: 2.5909x; 1.1040x over previous
#include <cuda_runtime.h>
#include <cuda_bf16.h>
#include <math.h>
#include <cstdint>

typedef __nv_bfloat16 bf16;

// Problem constants
#define NBATCH 2
#define SEQ    2048
#define NHEAD  16
#define DHEAD  128
#define HID    2048
#define NTOK   4096   // NBATCH*SEQ

// Scratch (device globals — no runtime allocation allowed)
__device__ float g_Q[NBATCH*NHEAD*SEQ*DHEAD];   // fp32, pre-RoPE
__device__ float g_K[NBATCH*NHEAD*SEQ*DHEAD];

__device__ bf16 g_Qh[NBATCH*NHEAD*SEQ*DHEAD];   // post-RoPE hi/lo
__device__ bf16 g_Ql[NBATCH*NHEAD*SEQ*DHEAD];
__device__ bf16 g_Kh[NBATCH*NHEAD*SEQ*DHEAD];
__device__ bf16 g_Kl[NBATCH*NHEAD*SEQ*DHEAD];
__device__ bf16 g_Vh[NBATCH*NHEAD*SEQ*DHEAD];
__device__ bf16 g_Vl[NBATCH*NHEAD*SEQ*DHEAD];

__device__ bf16 g_xh[(size_t)NTOK*HID];
__device__ bf16 g_xl[(size_t)NTOK*HID];
__device__ bf16 g_ch[(size_t)NTOK*HID];         // ctx hi/lo (flash output)
__device__ bf16 g_cl[(size_t)NTOK*HID];
__device__ bf16 g_wh[4][(size_t)HID*HID];
__device__ bf16 g_wl[4][(size_t)HID*HID];

// ---------------------------------------------------------------------------
// helpers
// ---------------------------------------------------------------------------
__device__ __forceinline__ uint32_t smem_u32(const void* p) {
    uint32_t a;
    asm("{ .reg .u64 t; cvta.to.shared.u64 t, %1; cvt.u32.u64 %0, t; }"
        : "=r"(a) : "l"(p));
    return a;
}
__device__ __forceinline__ void ldm4(uint32_t* r, uint32_t addr) {
    asm volatile("ldmatrix.sync.aligned.m8n8.x4.shared.b16 {%0,%1,%2,%3},[%4];"
                 : "=r"(r[0]), "=r"(r[1]), "=r"(r[2]), "=r"(r[3]) : "r"(addr));
}
__device__ __forceinline__ void ldm4t(uint32_t* r, uint32_t addr) {
    asm volatile("ldmatrix.sync.aligned.m8n8.x4.trans.shared.b16 {%0,%1,%2,%3},[%4];"
                 : "=r"(r[0]), "=r"(r[1]), "=r"(r[2]), "=r"(r[3]) : "r"(addr));
}
__device__ __forceinline__ void mma16816(float* d, const uint32_t* a,
                                         uint32_t b0, uint32_t b1) {
    asm volatile(
        "mma.sync.aligned.m16n8k16.row.col.f32.bf16.bf16.f32 "
        "{%0,%1,%2,%3},{%4,%5,%6,%7},{%8,%9},{%0,%1,%2,%3};"
        : "+f"(d[0]), "+f"(d[1]), "+f"(d[2]), "+f"(d[3])
        : "r"(a[0]), "r"(a[1]), "r"(a[2]), "r"(a[3]), "r"(b0), "r"(b1));
}
__device__ __forceinline__ void split1(float v, bf16& h, bf16& l) {
    h = __float2bfloat16_rn(v);
    l = __float2bfloat16_rn(v - __bfloat162float(h));
}
// split two floats, pack hi-pair and lo-pair
__device__ __forceinline__ void split2pack(float a, float b,
                                           uint32_t& hp, uint32_t& lp) {
    bf16 ha, la, hb, lb;
    split1(a, ha, la);
    split1(b, hb, lb);
    hp = ((uint32_t)__bfloat16_as_ushort(hb) << 16) | __bfloat16_as_ushort(ha);
    lp = ((uint32_t)__bfloat16_as_ushort(lb) << 16) | __bfloat16_as_ushort(la);
}
__device__ __forceinline__ void cpa16(uint32_t s, const void* g) {
    asm volatile("cp.async.cg.shared.global [%0], [%1], 16;" :: "r"(s), "l"(g));
}
#define CP_COMMIT() asm volatile("cp.async.commit_group;" ::: "memory")
#define CP_WAIT0()  asm volatile("cp.async.wait_group 0;" ::: "memory")
#define CP_WAIT1()  asm volatile("cp.async.wait_group 1;" ::: "memory")

// ---------------------------------------------------------------------------
// Split: fp32 -> bf16 hi + bf16 lo
// ---------------------------------------------------------------------------
__global__ __launch_bounds__(256)
void split_kernel(const float* __restrict__ src,
                  bf16* __restrict__ h, bf16* __restrict__ l, int n4)
{
    int i = blockIdx.x * 256 + threadIdx.x;
    if (i >= n4) return;
    float4 v = ((const float4*)src)[i];
    float vv[4] = {v.x, v.y, v.z, v.w};
    unsigned short hu[4], lu[4];
    #pragma unroll
    for (int j = 0; j < 4; j++) {
        bf16 hb, lb; split1(vv[j], hb, lb);
        hu[j] = __bfloat16_as_ushort(hb);
        lu[j] = __bfloat16_as_ushort(lb);
    }
    ((uint2*)h)[i] = make_uint2(((uint32_t)hu[1] << 16) | hu[0], ((uint32_t)hu[3] << 16) | hu[2]);
    ((uint2*)l)[i] = make_uint2(((uint32_t)lu[1] << 16) | lu[0], ((uint32_t)lu[3] << 16) | lu[2]);
}

// ---------------------------------------------------------------------------
// Tensor-core GEMM with cp.async 2-stage pipeline (R6, passing).
// sel = -1: fused QKV launch, weight index = blockIdx.x>>4 (0/1/2).
// sel = 3 : final projection, C fp32 row-major to Cout.
// Per-index output: 0/1 -> fp32 bhsd g_Q/g_K; 2 -> bf16 hi/lo bhsd g_Vh/g_Vl.
// ---------------------------------------------------------------------------
#define SPAD 40
#define ARR_B   (128*SPAD*2)          // bytes per operand array (10240)
#define STAGE_B (4*ARR_B)             // 40960
#define GEMM_SMEM (2*STAGE_B)         // 81920

__global__ __launch_bounds__(256)
void mma_gemm(const bf16* __restrict__ Ah, const bf16* __restrict__ Al,
              const bf16* __restrict__ BhBase, const bf16* __restrict__ BlBase,
              float* __restrict__ Cout, int sel)
{
    extern __shared__ char dsm[];
    const uint32_t ub = smem_u32(dsm);

    const int t    = threadIdx.x;
    const int wid  = t >> 5;
    const int lane = t & 31;
    const int m0   = blockIdx.y << 7;
    const int wm   = wid & 1;
    const int wn   = wid >> 1;

    int sel_, n0;
    const bf16 *Bh, *Bl;
    if (sel < 0) {
        int widx = blockIdx.x >> 4;
        sel_ = widx;
        n0   = (blockIdx.x & 15) << 7;
        Bh = BhBase + (size_t)widx * HID * HID;
        Bl = BlBase + (size_t)widx * HID * HID;
    } else {
        sel_ = sel;
        n0   = blockIdx.x << 7;
        Bh = BhBase;
        Bl = BlBase;
    }

    int rowL[2], qdL[2];
    #pragma unroll
    for (int r = 0; r < 2; r++) {
        int u = t + (r << 8);
        rowL[r] = u >> 2;
        qdL[r]  = u & 3;
    }

    const bf16* pAh = Ah + (size_t)m0 * HID;
    const bf16* pAl = Al + (size_t)m0 * HID;
    const bf16* pBh = Bh + (size_t)n0 * HID;
    const bf16* pBl = Bl + (size_t)n0 * HID;

    float acc[4][4][4];
    #pragma unroll
    for (int i = 0; i < 4; i++)
        #pragma unroll
        for (int j = 0; j < 4; j++)
            #pragma unroll
            for (int q = 0; q < 4; q++)
                acc[i][j][q] = 0.f;

    const int lrow = lane & 15, lcol = lane >> 4;
    const int NCH = HID / 32;   // 64 chunks

    auto issue = [&](int c, int buf) {
        uint32_t sb = ub + buf * STAGE_B;
        #pragma unroll
        for (int r = 0; r < 2; r++) {
            int row = rowL[r], qd = qdL[r];
            uint32_t so = (uint32_t)(row * SPAD + qd * 8) * 2;
            size_t   go = (size_t)row * HID + (size_t)c * 32 + qd * 8;
            cpa16(sb + so,             pAh + go);
            cpa16(sb + ARR_B + so,     pAl + go);
            cpa16(sb + 2*ARR_B + so,   pBh + go);
            cpa16(sb + 3*ARR_B + so,   pBl + go);
        }
        CP_COMMIT();
    };

    issue(0, 0);

    for (int c = 0; c < NCH; c++) {
        CP_WAIT0();
        __syncthreads();
        if (c + 1 < NCH) issue(c + 1, (c + 1) & 1);

        const uint32_t sb  = ub + (c & 1) * STAGE_B;
        const uint32_t uAh = sb;
        const uint32_t uAl = sb + ARR_B;
        const uint32_t uBh = sb + 2*ARR_B;
        const uint32_t uBl = sb + 3*ARR_B;

        #pragma unroll
        for (int kh = 0; kh < 2; kh++) {
            uint32_t ah[4][4], al[4][4], bh[2][4], bl[2][4];
            #pragma unroll
            for (int mt = 0; mt < 4; mt++) {
                uint32_t off = (uint32_t)((wm*64 + mt*16 + lrow) * SPAD + kh*16 + lcol*8) * 2;
                ldm4(ah[mt], uAh + off);
                ldm4(al[mt], uAl + off);
            }
            #pragma unroll
            for (int n2 = 0; n2 < 2; n2++) {
                uint32_t off = (uint32_t)((wn*32 + n2*16 + lrow) * SPAD + kh*16 + lcol*8) * 2;
                ldm4(bh[n2], uBh + off);
                ldm4(bl[n2], uBl + off);
            }
            #pragma unroll
            for (int mt = 0; mt < 4; mt++)
                #pragma unroll
                for (int nt = 0; nt < 4; nt++) {
                    int n2 = nt >> 1, hb = nt & 1;
                    mma16816(acc[mt][nt], ah[mt], bh[n2][hb], bh[n2][hb+2]);
                    mma16816(acc[mt][nt], ah[mt], bl[n2][hb], bl[n2][hb+2]);
                    mma16816(acc[mt][nt], al[mt], bh[n2][hb], bh[n2][hb+2]);
                }
        }
    }

    const int rbase = wm*64 + (lane >> 2);
    const int cbase = wn*32 + 2*(lane & 3);
    if (sel_ == 3) {
        #pragma unroll
        for (int mt = 0; mt < 4; mt++)
            #pragma unroll
            for (int nt = 0; nt < 4; nt++) {
                int r0 = m0 + rbase + mt*16;
                int cc = n0 + cbase + nt*8;
                *(float2*)&Cout[(size_t)r0 * HID + cc]       = make_float2(acc[mt][nt][0], acc[mt][nt][1]);
                *(float2*)&Cout[(size_t)(r0 + 8) * HID + cc] = make_float2(acc[mt][nt][2], acc[mt][nt][3]);
            }
    } else if (sel_ == 2) {
        const int h = n0 >> 7;
        #pragma unroll
        for (int mt = 0; mt < 4; mt++)
            #pragma unroll
            for (int nt = 0; nt < 4; nt++) {
                int r0 = m0 + rbase + mt*16;
                int b  = r0 >> 11;
                int s  = r0 & (SEQ - 1);
                int d  = cbase + nt*8;
                size_t base = (((size_t)(b*NHEAD + h))*SEQ + s)*DHEAD + d;
                uint32_t hp, lp;
                split2pack(acc[mt][nt][0], acc[mt][nt][1], hp, lp);
                *(uint32_t*)&g_Vh[base] = hp;
                *(uint32_t*)&g_Vl[base] = lp;
                split2pack(acc[mt][nt][2], acc[mt][nt][3], hp, lp);
                *(uint32_t*)&g_Vh[base + 8*DHEAD] = hp;
                *(uint32_t*)&g_Vl[base + 8*DHEAD] = lp;
            }
    } else {
        float* outp = (sel_ == 0) ? g_Q : g_K;
        const int h = n0 >> 7;
        #pragma unroll
        for (int mt = 0; mt < 4; mt++)
            #pragma unroll
            for (int nt = 0; nt < 4; nt++) {
                int r0 = m0 + rbase + mt*16;
                int b  = r0 >> 11;
                int s  = r0 & (SEQ - 1);
                int d  = cbase + nt*8;
                size_t base = (((size_t)(b*NHEAD + h))*SEQ + s)*DHEAD + d;
                *(float2*)&outp[base]           = make_float2(acc[mt][nt][0], acc[mt][nt][1]);
                *(float2*)&outp[base + 8*DHEAD] = make_float2(acc[mt][nt][2], acc[mt][nt][3]);
            }
    }
}

// ---------------------------------------------------------------------------
// RoPE + split: read fp32 g_Q/g_K, rotate, write bf16 hi/lo.
// ---------------------------------------------------------------------------
__global__ __launch_bounds__(256)
void rope_split(const float* __restrict__ freqs)
{
    int tid = blockIdx.x * 256 + threadIdx.x;
    bool isK = (tid >> 22) != 0;
    const float* src = isK ? g_K : g_Q;
    bf16* dh = isK ? g_Kh : g_Qh;
    bf16* dl = isK ? g_Kl : g_Ql;
    int rem = tid & ((1 << 22) - 1);
    int d   = rem & 63;
    int s   = (rem >> 6) & (SEQ - 1);
    int bh  = rem >> 17;
    size_t base = ((size_t)bh * SEQ + s) * DHEAD;
    float f1 = freqs[s*DHEAD + d];
    float f2 = freqs[s*DHEAD + d + 64];
    float x1 = src[base + d];
    float x2 = src[base + d + 64];
    float y1 = x1 * cosf(f1) - x2 * sinf(f1);
    float y2 = x2 * cosf(f2) + x1 * sinf(f2);
    bf16 h, l;
    split1(y1, h, l); dh[base + d]      = h; dl[base + d]      = l;
    split1(y2, h, l); dh[base + d + 64] = h; dl[base + d + 64] = l;
}

// ---------------------------------------------------------------------------
// Flash attention v2: warp owns 16 q-rows x full Bk=64. P stays in registers
// (S C-fragment == PV A-fragment). Intra-warp softmax only. K/V cp.async
// double-buffered: ONE __syncthreads per iteration.
// ---------------------------------------------------------------------------
#define BQ 128
#define BK 64
#define QSTR 136
#define KSTR 136
#define QARR (128*QSTR*2)        // 34816 bytes per Q array
#define KARR (64*KSTR*2)         // 17408 bytes per KV array
#define KVSTAGE (4*KARR)         // 69632
#define OFF_KV (2*QARR)          // 69632
#define FLASH_SMEM (2*QARR + 2*KVSTAGE)   // 208896

__global__ __launch_bounds__(256, 1)
void flash_mma(const float* __restrict__ mask, const float* __restrict__ alibi)
{
    extern __shared__ char sm[];
    const uint32_t ub  = smem_u32(sm);
    const uint32_t uQh = ub, uQl = ub + QARR;
    bf16* sQh = (bf16*)sm;
    bf16* sQl = (bf16*)(sm + QARR);

    const int t    = threadIdx.x;
    const int lane = t & 31;
    const int wid  = t >> 5;
    const int qb   = blockIdx.x;
    const int bhid = blockIdx.y;
    const int h    = bhid & (NHEAD - 1);
    const int b    = bhid >> 4;
    const int qi0  = qb * BQ;
    const size_t hbase = (size_t)bhid * SEQ * DHEAD;

    const int lrow = lane & 15, lcol = lane >> 4;
    const int g = lane >> 2, tq = lane & 3;
    const float SCALE = 0.08838834764831845f;  // 1/sqrt(128)

    // Q tile load (sync)
    #pragma unroll
    for (int rep = 0; rep < 8; rep++) {
        int u = t + rep * 256;
        int row = u >> 4, c8 = (u & 15) * 8;
        size_t go = hbase + (size_t)(qi0 + row) * DHEAD + c8;
        *(uint4*)&sQh[row*QSTR + c8] = *(const uint4*)(g_Qh + go);
        *(uint4*)&sQl[row*QSTR + c8] = *(const uint4*)(g_Ql + go);
    }

    // KV async stage loader
    auto issueKV = [&](int kt) {
        uint32_t sb = ub + OFF_KV + (kt & 1) * KVSTAGE;
        const int kj0 = kt * BK;
        #pragma unroll
        for (int rep = 0; rep < 4; rep++) {
            int u = t + rep * 256;
            int row = u >> 4, c8 = (u & 15) * 8;
            uint32_t so = (uint32_t)(row * KSTR + c8) * 2;
            size_t   go = hbase + (size_t)(kj0 + row) * DHEAD + c8;
            cpa16(sb + so,          g_Kh + go);
            cpa16(sb + KARR + so,   g_Kl + go);
            cpa16(sb + 2*KARR + so, g_Vh + go);
            cpa16(sb + 3*KARR + so, g_Vl + go);
        }
        CP_COMMIT();
    };
    issueKV(0);

    // per-thread state: rows (wid*16+g) and (+8)
    float o[16][4];
    #pragma unroll
    for (int nt = 0; nt < 16; nt++)
        #pragma unroll
        for (int q = 0; q < 4; q++)
            o[nt][q] = 0.f;
    float m0r = -1e30f, m8r = -1e30f, l0r = 0.f, l8r = 0.f;
    const int r0g = qi0 + wid*16 + g;   // global q row for "g" lanes

    for (int kt = 0; kt < SEQ / BK; kt++) {
        const int kj0 = kt * BK;
        CP_WAIT0();
        __syncthreads();
        if (kt + 1 < SEQ / BK) issueKV(kt + 1);

        const uint32_t sb  = ub + OFF_KV + (kt & 1) * KVSTAGE;
        const uint32_t uKh = sb, uKl = sb + KARR;
        const uint32_t uVh = sb + 2*KARR, uVl = sb + 3*KARR;

        // ---- S = Q K^T : warp tile 16 x 64, 3-product ----
        float sacc[8][4];
        #pragma unroll
        for (int nt = 0; nt < 8; nt++)
            #pragma unroll
            for (int q = 0; q < 4; q++)
                sacc[nt][q] = 0.f;

        #pragma unroll
        for (int kk = 0; kk < 8; kk++) {
            uint32_t ah[4], al[4], kbh[4][4], kbl[4][4];
            uint32_t qoff = (uint32_t)((wid*16 + lrow)*QSTR + kk*16 + lcol*8) * 2;
            ldm4(ah, uQh + qoff);
            ldm4(al, uQl + qoff);
            #pragma unroll
            for (int n2 = 0; n2 < 4; n2++) {
                uint32_t koff = (uint32_t)((n2*16 + lrow)*KSTR + kk*16 + lcol*8) * 2;
                ldm4(kbh[n2], uKh + koff);
                ldm4(kbl[n2], uKl + koff);
            }
            #pragma unroll
            for (int nt = 0; nt < 8; nt++) {
                int n2 = nt >> 1, hb = nt & 1;
                mma16816(sacc[nt], ah, kbh[n2][hb], kbh[n2][hb+2]);
                mma16816(sacc[nt], ah, kbl[n2][hb], kbl[n2][hb+2]);
                mma16816(sacc[nt], al, kbh[n2][hb], kbh[n2][hb+2]);
            }
        }

        // ---- scale + mask + alibi, row max (intra-warp only) ----
        float rmax0 = -1e30f, rmax8 = -1e30f;
        #pragma unroll
        for (int nt = 0; nt < 8; nt++) {
            int col = kj0 + nt*8 + 2*tq;
            float2 av  = *(const float2*)(alibi + (size_t)h * SEQ + col);
            float2 mv0 = *(const float2*)(mask + (size_t)r0g * SEQ + col);
            float2 mv1 = *(const float2*)(mask + (size_t)(r0g + 8) * SEQ + col);
            sacc[nt][0] = fmaf(sacc[nt][0], SCALE, mv0.x + av.x);
            sacc[nt][1] = fmaf(sacc[nt][1], SCALE, mv0.y + av.y);
            sacc[nt][2] = fmaf(sacc[nt][2], SCALE, mv1.x + av.x);
            sacc[nt][3] = fmaf(sacc[nt][3], SCALE, mv1.y + av.y);
            rmax0 = fmaxf(rmax0, fmaxf(sacc[nt][0], sacc[nt][1]));
            rmax8 = fmaxf(rmax8, fmaxf(sacc[nt][2], sacc[nt][3]));
        }
        #pragma unroll
        for (int off = 1; off <= 2; off <<= 1) {
            rmax0 = fmaxf(rmax0, __shfl_xor_sync(0xffffffffu, rmax0, off));
            rmax8 = fmaxf(rmax8, __shfl_xor_sync(0xffffffffu, rmax8, off));
        }

        float nm0 = fmaxf(m0r, rmax0), nm8 = fmaxf(m8r, rmax8);
        float c0 = __expf(m0r - nm0),  c8 = __expf(m8r - nm8);
        m0r = nm0; m8r = nm8;

        // ---- exp + pack P fragments in registers ----
        float rs0 = 0.f, rs8 = 0.f;
        uint32_t ph[4][4], pl[4][4];
        #pragma unroll
        for (int kk = 0; kk < 4; kk++) {
            #pragma unroll
            for (int half = 0; half < 2; half++) {
                int nt = 2*kk + half;
                float p0 = __expf(sacc[nt][0] - nm0);
                float p1 = __expf(sacc[nt][1] - nm0);
                float p2 = __expf(sacc[nt][2] - nm8);
                float p3 = __expf(sacc[nt][3] - nm8);
                rs0 += p0 + p1; rs8 += p2 + p3;
                split2pack(p0, p1, ph[kk][half*2+0], pl[kk][half*2+0]);
                split2pack(p2, p3, ph[kk][half*2+1], pl[kk][half*2+1]);
            }
        }
        #pragma unroll
        for (int off = 1; off <= 2; off <<= 1) {
            rs0 += __shfl_xor_sync(0xffffffffu, rs0, off);
            rs8 += __shfl_xor_sync(0xffffffffu, rs8, off);
        }
        l0r = l0r * c0 + rs0;
        l8r = l8r * c8 + rs8;

        // ---- rescale O ----
        #pragma unroll
        for (int nt = 0; nt < 16; nt++) {
            o[nt][0] *= c0; o[nt][1] *= c0;
            o[nt][2] *= c8; o[nt][3] *= c8;
        }

        // ---- O += P V : warp tile 16 x 128, 3-product ----
        #pragma unroll
        for (int kk = 0; kk < 4; kk++) {
            #pragma unroll
            for (int dd = 0; dd < 8; dd++) {
                uint32_t vh_[4], vl_[4];
                uint32_t voff = (uint32_t)((kk*16 + lrow)*KSTR + dd*16 + lcol*8) * 2;
                ldm4t(vh_, uVh + voff);
                ldm4t(vl_, uVl + voff);
                mma16816(o[dd*2+0], ph[kk], vh_[0], vh_[1]);
                mma16816(o[dd*2+0], ph[kk], vl_[0], vl_[1]);
                mma16816(o[dd*2+0], pl[kk], vh_[0], vh_[1]);
                mma16816(o[dd*2+1], ph[kk], vh_[2], vh_[3]);
                mma16816(o[dd*2+1], ph[kk], vl_[2], vl_[3]);
                mma16816(o[dd*2+1], pl[kk], vh_[2], vh_[3]);
            }
        }
    }

    // ---- epilogue: normalize, split, write ctx [tok][h*128+d] ----
    float inv0 = 1.f / l0r, inv8 = 1.f / l8r;
    size_t tok0 = ((size_t)(b*SEQ + qi0 + wid*16 + g)) * HID + h * DHEAD;
    size_t tok8 = tok0 + (size_t)8 * HID;
    #pragma unroll
    for (int nt = 0; nt < 16; nt++) {
        int d = nt*8 + 2*tq;
        uint32_t hp, lp;
        split2pack(o[nt][0]*inv0, o[nt][1]*inv0, hp, lp);
        *(uint32_t*)&g_ch[tok0 + d] = hp;
        *(uint32_t*)&g_cl[tok0 + d] = lp;
        split2pack(o[nt][2]*inv8, o[nt][3]*inv8, hp, lp);
        *(uint32_t*)&g_ch[tok8 + d] = hp;
        *(uint32_t*)&g_cl[tok8 + d] = lp;
    }
}

// ---------------------------------------------------------------------------
extern "C" void kernel_launch(void* const* d_in, const int* in_sizes, int n_in,
                              void* d_out, int out_size)
{
    const float* x     = (const float*)d_in[0];
    const float* mask  = (const float*)d_in[1];
    const float* alibi = (const float*)d_in[2];
    const float* freqs = (const float*)d_in[3];
    const float* W[4]  = { (const float*)d_in[4], (const float*)d_in[5],
                           (const float*)d_in[6], (const float*)d_in[7] };
    float* out = (float*)d_out;
    (void)in_sizes; (void)n_in; (void)out_size;

    cudaFuncSetAttribute(flash_mma,
                         cudaFuncAttributeMaxDynamicSharedMemorySize, FLASH_SMEM);
    cudaFuncSetAttribute(mma_gemm,
                         cudaFuncAttributeMaxDynamicSharedMemorySize, GEMM_SMEM);

    bf16 *xh, *xl, *ch, *cl, *whbase, *wlbase;
    cudaGetSymbolAddress((void**)&xh, g_xh);
    cudaGetSymbolAddress((void**)&xl, g_xl);
    cudaGetSymbolAddress((void**)&ch, g_ch);
    cudaGetSymbolAddress((void**)&cl, g_cl);
    cudaGetSymbolAddress((void**)&whbase, g_wh);
    cudaGetSymbolAddress((void**)&wlbase, g_wl);

    {
        int n4 = NTOK * HID / 4;
        split_kernel<<<(n4 + 255) / 256, 256>>>(x, xh, xl, n4);
        int w4 = HID * HID / 4;
        for (int i = 0; i < 4; i++)
            split_kernel<<<(w4 + 255) / 256, 256>>>(
                W[i], whbase + (size_t)i*HID*HID, wlbase + (size_t)i*HID*HID, w4);
    }

    // fused Q/K/V projections: grid.x = 3 weight sets x 16 col-tiles
    mma_gemm<<<dim3(48, NTOK/128), 256, GEMM_SMEM>>>(xh, xl, whbase, wlbase, nullptr, -1);

    rope_split<<<(2*NBATCH*NHEAD*SEQ*64) / 256, 256>>>(freqs);

    flash_mma<<<dim3(SEQ/BQ, NBATCH*NHEAD), 256, FLASH_SMEM>>>(mask, alibi);

    mma_gemm<<<dim3(16, NTOK/128), 256, GEMM_SMEM>>>(
        ch, cl, whbase + 3*(size_t)HID*HID, wlbase + 3*(size_t)HID*HID, out, 3);
}

// round 8
// speedup vs baseline: 3.6753x; 1.4185x over previous
#include <cuda_runtime.h>
#include <cuda_fp16.h>
#include <math.h>
#include <cstdint>

typedef __half h16;

// Problem constants
#define NBATCH 2
#define SEQ    2048
#define NHEAD  16
#define DHEAD  128
#define HID    2048
#define NTOK   4096   // NBATCH*SEQ

// Scratch (device globals — no runtime allocation allowed)
__device__ float g_Q[NBATCH*NHEAD*SEQ*DHEAD];   // fp32, pre-RoPE
__device__ float g_K[NBATCH*NHEAD*SEQ*DHEAD];

__device__ h16 g_Qf[NBATCH*NHEAD*SEQ*DHEAD];    // post-RoPE, single fp16
__device__ h16 g_Kf[NBATCH*NHEAD*SEQ*DHEAD];
__device__ h16 g_Vh[NBATCH*NHEAD*SEQ*DHEAD];    // V hi/lo fp16 (direct path)
__device__ h16 g_Vl[NBATCH*NHEAD*SEQ*DHEAD];

__device__ h16 g_xh[(size_t)NTOK*HID];
__device__ h16 g_xl[(size_t)NTOK*HID];
__device__ h16 g_ch[(size_t)NTOK*HID];          // ctx hi/lo (flash output)
__device__ h16 g_cl[(size_t)NTOK*HID];
__device__ h16 g_wh[4][(size_t)HID*HID];
__device__ h16 g_wl[4][(size_t)HID*HID];

// ---------------------------------------------------------------------------
// helpers
// ---------------------------------------------------------------------------
__device__ __forceinline__ uint32_t smem_u32(const void* p) {
    uint32_t a;
    asm("{ .reg .u64 t; cvta.to.shared.u64 t, %1; cvt.u32.u64 %0, t; }"
        : "=r"(a) : "l"(p));
    return a;
}
__device__ __forceinline__ void ldm4(uint32_t* r, uint32_t addr) {
    asm volatile("ldmatrix.sync.aligned.m8n8.x4.shared.b16 {%0,%1,%2,%3},[%4];"
                 : "=r"(r[0]), "=r"(r[1]), "=r"(r[2]), "=r"(r[3]) : "r"(addr));
}
__device__ __forceinline__ void ldm4t(uint32_t* r, uint32_t addr) {
    asm volatile("ldmatrix.sync.aligned.m8n8.x4.trans.shared.b16 {%0,%1,%2,%3},[%4];"
                 : "=r"(r[0]), "=r"(r[1]), "=r"(r[2]), "=r"(r[3]) : "r"(addr));
}
__device__ __forceinline__ void mma16816(float* d, const uint32_t* a,
                                         uint32_t b0, uint32_t b1) {
    asm volatile(
        "mma.sync.aligned.m16n8k16.row.col.f32.f16.f16.f32 "
        "{%0,%1,%2,%3},{%4,%5,%6,%7},{%8,%9},{%0,%1,%2,%3};"
        : "+f"(d[0]), "+f"(d[1]), "+f"(d[2]), "+f"(d[3])
        : "r"(a[0]), "r"(a[1]), "r"(a[2]), "r"(a[3]), "r"(b0), "r"(b1));
}
__device__ __forceinline__ uint32_t packh2(h16 a, h16 b) {
    return ((uint32_t)__half_as_ushort(b) << 16) | __half_as_ushort(a);
}
__device__ __forceinline__ void split1h(float v, h16& h, h16& l) {
    h = __float2half_rn(v);
    l = __float2half_rn(v - __half2float(h));
}
__device__ __forceinline__ void split2packh(float a, float b,
                                            uint32_t& hp, uint32_t& lp) {
    h16 ha, la, hb, lb;
    split1h(a, ha, la);
    split1h(b, hb, lb);
    hp = packh2(ha, hb);
    lp = packh2(la, lb);
}
__device__ __forceinline__ void cpa16(uint32_t s, const void* g) {
    asm volatile("cp.async.cg.shared.global [%0], [%1], 16;" :: "r"(s), "l"(g));
}
#define CP_COMMIT() asm volatile("cp.async.commit_group;" ::: "memory")
#define CP_WAIT0()  asm volatile("cp.async.wait_group 0;" ::: "memory")

// ---------------------------------------------------------------------------
// Split: fp32 -> fp16 hi + fp16 lo
// ---------------------------------------------------------------------------
__global__ __launch_bounds__(256)
void split_kernel(const float* __restrict__ src,
                  h16* __restrict__ h, h16* __restrict__ l, int n4)
{
    int i = blockIdx.x * 256 + threadIdx.x;
    if (i >= n4) return;
    float4 v = ((const float4*)src)[i];
    float vv[4] = {v.x, v.y, v.z, v.w};
    h16 hh[4], ll[4];
    #pragma unroll
    for (int j = 0; j < 4; j++) split1h(vv[j], hh[j], ll[j]);
    ((uint2*)h)[i] = make_uint2(packh2(hh[0], hh[1]), packh2(hh[2], hh[3]));
    ((uint2*)l)[i] = make_uint2(packh2(ll[0], ll[1]), packh2(ll[2], ll[3]));
}

// ---------------------------------------------------------------------------
// Tensor-core GEMM, cp.async 2-stage, NPROD products (1 or 3).
// NPROD=3: D = Ah*(Bh+Bl) + Al*Bh (fp16 hi/lo, ~22-bit exact)
// NPROD=1: D = Ah*Bh            (fp16 single; use only where error washes)
// sel = -1: fused multi-weight launch, weight idx = blockIdx.x>>4.
// Epilogues by resolved index: 0/1 -> fp32 bhsd g_Q/g_K; 2 -> h16 hi/lo g_Vh/g_Vl;
// 3 -> fp32 row-major Cout.
// ---------------------------------------------------------------------------
#define SPAD 40
#define ARR_B   (128*SPAD*2)          // bytes per operand array (10240)

template<int NPROD>
__global__ __launch_bounds__(256)
void mma_gemm(const h16* __restrict__ Ah, const h16* __restrict__ Al,
              const h16* __restrict__ BhBase, const h16* __restrict__ BlBase,
              float* __restrict__ Cout, int sel)
{
    extern __shared__ char dsm[];
    const uint32_t ub = smem_u32(dsm);
    constexpr int NARR  = (NPROD == 3) ? 4 : 2;
    constexpr int STB   = NARR * ARR_B;

    const int t    = threadIdx.x;
    const int wid  = t >> 5;
    const int lane = t & 31;
    const int m0   = blockIdx.y << 7;
    const int wm   = wid & 1;
    const int wn   = wid >> 1;

    int sel_, n0;
    const h16 *Bh, *Bl;
    if (sel < 0) {
        int widx = blockIdx.x >> 4;
        sel_ = widx;
        n0   = (blockIdx.x & 15) << 7;
        Bh = BhBase + (size_t)widx * HID * HID;
        Bl = BlBase + (size_t)widx * HID * HID;
    } else {
        sel_ = sel;
        n0   = blockIdx.x << 7;
        Bh = BhBase;
        Bl = BlBase;
    }

    int rowL[2], qdL[2];
    #pragma unroll
    for (int r = 0; r < 2; r++) {
        int u = t + (r << 8);
        rowL[r] = u >> 2;
        qdL[r]  = u & 3;
    }

    const h16* pAh = Ah + (size_t)m0 * HID;
    const h16* pAl = (NPROD == 3) ? (Al + (size_t)m0 * HID) : nullptr;
    const h16* pBh = Bh + (size_t)n0 * HID;
    const h16* pBl = (NPROD == 3) ? (Bl + (size_t)n0 * HID) : nullptr;

    float acc[4][4][4];
    #pragma unroll
    for (int i = 0; i < 4; i++)
        #pragma unroll
        for (int j = 0; j < 4; j++)
            #pragma unroll
            for (int q = 0; q < 4; q++)
                acc[i][j][q] = 0.f;

    const int lrow = lane & 15, lcol = lane >> 4;
    const int NCH = HID / 32;

    auto issue = [&](int c, int buf) {
        uint32_t sb = ub + buf * STB;
        #pragma unroll
        for (int r = 0; r < 2; r++) {
            int row = rowL[r], qd = qdL[r];
            uint32_t so = (uint32_t)(row * SPAD + qd * 8) * 2;
            size_t   go = (size_t)row * HID + (size_t)c * 32 + qd * 8;
            if (NPROD == 3) {
                cpa16(sb + so,             pAh + go);
                cpa16(sb + ARR_B + so,     pAl + go);
                cpa16(sb + 2*ARR_B + so,   pBh + go);
                cpa16(sb + 3*ARR_B + so,   pBl + go);
            } else {
                cpa16(sb + so,             pAh + go);
                cpa16(sb + ARR_B + so,     pBh + go);
            }
        }
        CP_COMMIT();
    };

    issue(0, 0);

    for (int c = 0; c < NCH; c++) {
        CP_WAIT0();
        __syncthreads();
        if (c + 1 < NCH) issue(c + 1, (c + 1) & 1);

        const uint32_t sb  = ub + (c & 1) * STB;
        const uint32_t uAh = sb;
        const uint32_t uAl = sb + ARR_B;                      // NPROD==3 only
        const uint32_t uBh = (NPROD == 3) ? sb + 2*ARR_B : sb + ARR_B;
        const uint32_t uBl = sb + 3*ARR_B;                    // NPROD==3 only

        #pragma unroll
        for (int kh = 0; kh < 2; kh++) {
            uint32_t ah[4][4], al[4][4], bh[2][4], bl[2][4];
            #pragma unroll
            for (int mt = 0; mt < 4; mt++) {
                uint32_t off = (uint32_t)((wm*64 + mt*16 + lrow) * SPAD + kh*16 + lcol*8) * 2;
                ldm4(ah[mt], uAh + off);
                if (NPROD == 3) ldm4(al[mt], uAl + off);
            }
            #pragma unroll
            for (int n2 = 0; n2 < 2; n2++) {
                uint32_t off = (uint32_t)((wn*32 + n2*16 + lrow) * SPAD + kh*16 + lcol*8) * 2;
                ldm4(bh[n2], uBh + off);
                if (NPROD == 3) ldm4(bl[n2], uBl + off);
            }
            #pragma unroll
            for (int mt = 0; mt < 4; mt++)
                #pragma unroll
                for (int nt = 0; nt < 4; nt++) {
                    int n2 = nt >> 1, hb = nt & 1;
                    mma16816(acc[mt][nt], ah[mt], bh[n2][hb], bh[n2][hb+2]);
                    if (NPROD == 3) {
                        mma16816(acc[mt][nt], ah[mt], bl[n2][hb], bl[n2][hb+2]);
                        mma16816(acc[mt][nt], al[mt], bh[n2][hb], bh[n2][hb+2]);
                    }
                }
        }
    }

    const int rbase = wm*64 + (lane >> 2);
    const int cbase = wn*32 + 2*(lane & 3);
    if (sel_ == 3) {
        #pragma unroll
        for (int mt = 0; mt < 4; mt++)
            #pragma unroll
            for (int nt = 0; nt < 4; nt++) {
                int r0 = m0 + rbase + mt*16;
                int cc = n0 + cbase + nt*8;
                *(float2*)&Cout[(size_t)r0 * HID + cc]       = make_float2(acc[mt][nt][0], acc[mt][nt][1]);
                *(float2*)&Cout[(size_t)(r0 + 8) * HID + cc] = make_float2(acc[mt][nt][2], acc[mt][nt][3]);
            }
    } else if (sel_ == 2) {
        const int h = n0 >> 7;
        #pragma unroll
        for (int mt = 0; mt < 4; mt++)
            #pragma unroll
            for (int nt = 0; nt < 4; nt++) {
                int r0 = m0 + rbase + mt*16;
                int b  = r0 >> 11;
                int s  = r0 & (SEQ - 1);
                int d  = cbase + nt*8;
                size_t base = (((size_t)(b*NHEAD + h))*SEQ + s)*DHEAD + d;
                uint32_t hp, lp;
                split2packh(acc[mt][nt][0], acc[mt][nt][1], hp, lp);
                *(uint32_t*)&g_Vh[base] = hp;
                *(uint32_t*)&g_Vl[base] = lp;
                split2packh(acc[mt][nt][2], acc[mt][nt][3], hp, lp);
                *(uint32_t*)&g_Vh[base + 8*DHEAD] = hp;
                *(uint32_t*)&g_Vl[base + 8*DHEAD] = lp;
            }
    } else {
        float* outp = (sel_ == 0) ? g_Q : g_K;
        const int h = n0 >> 7;
        #pragma unroll
        for (int mt = 0; mt < 4; mt++)
            #pragma unroll
            for (int nt = 0; nt < 4; nt++) {
                int r0 = m0 + rbase + mt*16;
                int b  = r0 >> 11;
                int s  = r0 & (SEQ - 1);
                int d  = cbase + nt*8;
                size_t base = (((size_t)(b*NHEAD + h))*SEQ + s)*DHEAD + d;
                *(float2*)&outp[base]           = make_float2(acc[mt][nt][0], acc[mt][nt][1]);
                *(float2*)&outp[base + 8*DHEAD] = make_float2(acc[mt][nt][2], acc[mt][nt][3]);
            }
    }
}

#define GEMM_SMEM3 (2 * 4 * ARR_B)   // 81920
#define GEMM_SMEM1 (2 * 2 * ARR_B)   // 40960

// ---------------------------------------------------------------------------
// RoPE + round: read fp32 g_Q/g_K, rotate, write SINGLE fp16 (errors wash).
// ---------------------------------------------------------------------------
__global__ __launch_bounds__(256)
void rope_round(const float* __restrict__ freqs)
{
    int tid = blockIdx.x * 256 + threadIdx.x;
    bool isK = (tid >> 22) != 0;
    const float* src = isK ? g_K : g_Q;
    h16* dst = isK ? g_Kf : g_Qf;
    int rem = tid & ((1 << 22) - 1);
    int d   = rem & 63;
    int s   = (rem >> 6) & (SEQ - 1);
    int bh  = rem >> 17;
    size_t base = ((size_t)bh * SEQ + s) * DHEAD;
    float f1 = freqs[s*DHEAD + d];
    float f2 = freqs[s*DHEAD + d + 64];
    float x1 = src[base + d];
    float x2 = src[base + d + 64];
    dst[base + d]      = __float2half_rn(x1 * cosf(f1) - x2 * sinf(f1));
    dst[base + d + 64] = __float2half_rn(x2 * cosf(f2) + x1 * sinf(f2));
}

// ---------------------------------------------------------------------------
// Flash attention: S = Qf·Kf^T single-product; PV = P(single)·(Vh+Vl) 2-product.
// Warp owns 16 q-rows x full Bk=64; P in registers; intra-warp softmax;
// K/V cp.async double-buffered, one __syncthreads per iteration.
// ---------------------------------------------------------------------------
#define BQ 128
#define BK 64
#define QSTR 136
#define KSTR 136
#define QARR (128*QSTR*2)        // 34816 bytes (single Q array)
#define KARR (64*KSTR*2)         // 17408 bytes per KV array
#define KVSTAGE (3*KARR)         // K, Vh, Vl = 52224
#define OFF_KV QARR
#define FLASH_SMEM (QARR + 2*KVSTAGE)   // 139264

__global__ __launch_bounds__(256, 1)
void flash_mma(const float* __restrict__ mask, const float* __restrict__ alibi)
{
    extern __shared__ char sm[];
    const uint32_t ub = smem_u32(sm);
    const uint32_t uQ = ub;
    h16* sQ = (h16*)sm;

    const int t    = threadIdx.x;
    const int lane = t & 31;
    const int wid  = t >> 5;
    const int qb   = blockIdx.x;
    const int bhid = blockIdx.y;
    const int h    = bhid & (NHEAD - 1);
    const int b    = bhid >> 4;
    const int qi0  = qb * BQ;
    const size_t hbase = (size_t)bhid * SEQ * DHEAD;

    const int lrow = lane & 15, lcol = lane >> 4;
    const int g = lane >> 2, tq = lane & 3;
    const float SCALE = 0.08838834764831845f;  // 1/sqrt(128)

    // Q tile load (sync)
    #pragma unroll
    for (int rep = 0; rep < 8; rep++) {
        int u = t + rep * 256;
        int row = u >> 4, c8 = (u & 15) * 8;
        *(uint4*)&sQ[row*QSTR + c8] =
            *(const uint4*)(g_Qf + hbase + (size_t)(qi0 + row) * DHEAD + c8);
    }

    // KV async stage loader: K single, V hi/lo
    auto issueKV = [&](int kt) {
        uint32_t sb = ub + OFF_KV + (kt & 1) * KVSTAGE;
        const int kj0 = kt * BK;
        #pragma unroll
        for (int rep = 0; rep < 4; rep++) {
            int u = t + rep * 256;
            int row = u >> 4, c8 = (u & 15) * 8;
            uint32_t so = (uint32_t)(row * KSTR + c8) * 2;
            size_t   go = hbase + (size_t)(kj0 + row) * DHEAD + c8;
            cpa16(sb + so,          g_Kf + go);
            cpa16(sb + KARR + so,   g_Vh + go);
            cpa16(sb + 2*KARR + so, g_Vl + go);
        }
        CP_COMMIT();
    };
    issueKV(0);

    float o[16][4];
    #pragma unroll
    for (int nt = 0; nt < 16; nt++)
        #pragma unroll
        for (int q = 0; q < 4; q++)
            o[nt][q] = 0.f;
    float m0r = -1e30f, m8r = -1e30f, l0r = 0.f, l8r = 0.f;
    const int r0g = qi0 + wid*16 + g;

    for (int kt = 0; kt < SEQ / BK; kt++) {
        const int kj0 = kt * BK;
        CP_WAIT0();
        __syncthreads();
        if (kt + 1 < SEQ / BK) issueKV(kt + 1);

        const uint32_t sb  = ub + OFF_KV + (kt & 1) * KVSTAGE;
        const uint32_t uK  = sb;
        const uint32_t uVh = sb + KARR, uVl = sb + 2*KARR;

        // ---- S = Q K^T : warp tile 16 x 64, single product ----
        float sacc[8][4];
        #pragma unroll
        for (int nt = 0; nt < 8; nt++)
            #pragma unroll
            for (int q = 0; q < 4; q++)
                sacc[nt][q] = 0.f;

        #pragma unroll
        for (int kk = 0; kk < 8; kk++) {
            uint32_t ah[4], kb[4][4];
            uint32_t qoff = (uint32_t)((wid*16 + lrow)*QSTR + kk*16 + lcol*8) * 2;
            ldm4(ah, uQ + qoff);
            #pragma unroll
            for (int n2 = 0; n2 < 4; n2++) {
                uint32_t koff = (uint32_t)((n2*16 + lrow)*KSTR + kk*16 + lcol*8) * 2;
                ldm4(kb[n2], uK + koff);
            }
            #pragma unroll
            for (int nt = 0; nt < 8; nt++) {
                int n2 = nt >> 1, hb = nt & 1;
                mma16816(sacc[nt], ah, kb[n2][hb], kb[n2][hb+2]);
            }
        }

        // ---- scale + mask + alibi, row max (intra-warp only) ----
        float rmax0 = -1e30f, rmax8 = -1e30f;
        #pragma unroll
        for (int nt = 0; nt < 8; nt++) {
            int col = kj0 + nt*8 + 2*tq;
            float2 av  = *(const float2*)(alibi + (size_t)h * SEQ + col);
            float2 mv0 = *(const float2*)(mask + (size_t)r0g * SEQ + col);
            float2 mv1 = *(const float2*)(mask + (size_t)(r0g + 8) * SEQ + col);
            sacc[nt][0] = fmaf(sacc[nt][0], SCALE, mv0.x + av.x);
            sacc[nt][1] = fmaf(sacc[nt][1], SCALE, mv0.y + av.y);
            sacc[nt][2] = fmaf(sacc[nt][2], SCALE, mv1.x + av.x);
            sacc[nt][3] = fmaf(sacc[nt][3], SCALE, mv1.y + av.y);
            rmax0 = fmaxf(rmax0, fmaxf(sacc[nt][0], sacc[nt][1]));
            rmax8 = fmaxf(rmax8, fmaxf(sacc[nt][2], sacc[nt][3]));
        }
        #pragma unroll
        for (int off = 1; off <= 2; off <<= 1) {
            rmax0 = fmaxf(rmax0, __shfl_xor_sync(0xffffffffu, rmax0, off));
            rmax8 = fmaxf(rmax8, __shfl_xor_sync(0xffffffffu, rmax8, off));
        }

        float nm0 = fmaxf(m0r, rmax0), nm8 = fmaxf(m8r, rmax8);
        float c0 = __expf(m0r - nm0),  c8 = __expf(m8r - nm8);
        m0r = nm0; m8r = nm8;

        // ---- exp + pack P fragments (single fp16, errors wash out) ----
        float rs0 = 0.f, rs8 = 0.f;
        uint32_t ph[4][4];
        #pragma unroll
        for (int kk = 0; kk < 4; kk++) {
            #pragma unroll
            for (int half = 0; half < 2; half++) {
                int nt = 2*kk + half;
                float p0 = __expf(sacc[nt][0] - nm0);
                float p1 = __expf(sacc[nt][1] - nm0);
                float p2 = __expf(sacc[nt][2] - nm8);
                float p3 = __expf(sacc[nt][3] - nm8);
                rs0 += p0 + p1; rs8 += p2 + p3;
                ph[kk][half*2+0] = packh2(__float2half_rn(p0), __float2half_rn(p1));
                ph[kk][half*2+1] = packh2(__float2half_rn(p2), __float2half_rn(p3));
            }
        }
        #pragma unroll
        for (int off = 1; off <= 2; off <<= 1) {
            rs0 += __shfl_xor_sync(0xffffffffu, rs0, off);
            rs8 += __shfl_xor_sync(0xffffffffu, rs8, off);
        }
        l0r = l0r * c0 + rs0;
        l8r = l8r * c8 + rs8;

        // ---- rescale O ----
        #pragma unroll
        for (int nt = 0; nt < 16; nt++) {
            o[nt][0] *= c0; o[nt][1] *= c0;
            o[nt][2] *= c8; o[nt][3] *= c8;
        }

        // ---- O += P (Vh + Vl) : 2-product ----
        #pragma unroll
        for (int kk = 0; kk < 4; kk++) {
            #pragma unroll
            for (int dd = 0; dd < 8; dd++) {
                uint32_t vh_[4], vl_[4];
                uint32_t voff = (uint32_t)((kk*16 + lrow)*KSTR + dd*16 + lcol*8) * 2;
                ldm4t(vh_, uVh + voff);
                ldm4t(vl_, uVl + voff);
                mma16816(o[dd*2+0], ph[kk], vh_[0], vh_[1]);
                mma16816(o[dd*2+0], ph[kk], vl_[0], vl_[1]);
                mma16816(o[dd*2+1], ph[kk], vh_[2], vh_[3]);
                mma16816(o[dd*2+1], ph[kk], vl_[2], vl_[3]);
            }
        }
    }

    // ---- epilogue: normalize, split to fp16 hi/lo ctx [tok][h*128+d] ----
    float inv0 = 1.f / l0r, inv8 = 1.f / l8r;
    size_t tok0 = ((size_t)(b*SEQ + qi0 + wid*16 + g)) * HID + h * DHEAD;
    size_t tok8 = tok0 + (size_t)8 * HID;
    #pragma unroll
    for (int nt = 0; nt < 16; nt++) {
        int d = nt*8 + 2*tq;
        uint32_t hp, lp;
        split2packh(o[nt][0]*inv0, o[nt][1]*inv0, hp, lp);
        *(uint32_t*)&g_ch[tok0 + d] = hp;
        *(uint32_t*)&g_cl[tok0 + d] = lp;
        split2packh(o[nt][2]*inv8, o[nt][3]*inv8, hp, lp);
        *(uint32_t*)&g_ch[tok8 + d] = hp;
        *(uint32_t*)&g_cl[tok8 + d] = lp;
    }
}

// ---------------------------------------------------------------------------
extern "C" void kernel_launch(void* const* d_in, const int* in_sizes, int n_in,
                              void* d_out, int out_size)
{
    const float* x     = (const float*)d_in[0];
    const float* mask  = (const float*)d_in[1];
    const float* alibi = (const float*)d_in[2];
    const float* freqs = (const float*)d_in[3];
    const float* W[4]  = { (const float*)d_in[4], (const float*)d_in[5],
                           (const float*)d_in[6], (const float*)d_in[7] };
    float* out = (float*)d_out;
    (void)in_sizes; (void)n_in; (void)out_size;

    cudaFuncSetAttribute(flash_mma,
                         cudaFuncAttributeMaxDynamicSharedMemorySize, FLASH_SMEM);
    cudaFuncSetAttribute(mma_gemm<3>,
                         cudaFuncAttributeMaxDynamicSharedMemorySize, GEMM_SMEM3);
    cudaFuncSetAttribute(mma_gemm<1>,
                         cudaFuncAttributeMaxDynamicSharedMemorySize, GEMM_SMEM1);

    h16 *xh, *xl, *ch, *cl, *whbase, *wlbase;
    cudaGetSymbolAddress((void**)&xh, g_xh);
    cudaGetSymbolAddress((void**)&xl, g_xl);
    cudaGetSymbolAddress((void**)&ch, g_ch);
    cudaGetSymbolAddress((void**)&cl, g_cl);
    cudaGetSymbolAddress((void**)&whbase, g_wh);
    cudaGetSymbolAddress((void**)&wlbase, g_wl);

    {
        int n4 = NTOK * HID / 4;
        split_kernel<<<(n4 + 255) / 256, 256>>>(x, xh, xl, n4);
        int w4 = HID * HID / 4;
        for (int i = 0; i < 4; i++)
            split_kernel<<<(w4 + 255) / 256, 256>>>(
                W[i], whbase + (size_t)i*HID*HID, wlbase + (size_t)i*HID*HID, w4);
    }

    // Q,K projections: fused, 1-product (errors wash through softmax)
    mma_gemm<1><<<dim3(32, NTOK/128), 256, GEMM_SMEM1>>>(
        xh, nullptr, whbase, nullptr, nullptr, -1);

    // V projection: 3-product (direct path)
    mma_gemm<3><<<dim3(16, NTOK/128), 256, GEMM_SMEM3>>>(
        xh, xl, whbase + 2*(size_t)HID*HID, wlbase + 2*(size_t)HID*HID, nullptr, 2);

    rope_round<<<(2*NBATCH*NHEAD*SEQ*64) / 256, 256>>>(freqs);

    flash_mma<<<dim3(SEQ/BQ, NBATCH*NHEAD), 256, FLASH_SMEM>>>(mask, alibi);

    // O projection: 3-product (direct path)
    mma_gemm<3><<<dim3(16, NTOK/128), 256, GEMM_SMEM3>>>(
        ch, cl, whbase + 3*(size_t)HID*HID, wlbase + 3*(size_t)HID*HID, out, 3);
}

// round 9
// speedup vs baseline: 3.7118x; 1.0099x over previous
#include <cuda_runtime.h>
#include <cuda_fp16.h>
#include <math.h>
#include <cstdint>

typedef __half h16;

// Problem constants
#define NBATCH 2
#define SEQ    2048
#define NHEAD  16
#define DHEAD  128
#define HID    2048
#define NTOK   4096   // NBATCH*SEQ

// Scratch (device globals — no runtime allocation allowed)
__device__ h16 g_Qf[NBATCH*NHEAD*SEQ*DHEAD];    // post-RoPE, single fp16
__device__ h16 g_Kf[NBATCH*NHEAD*SEQ*DHEAD];
__device__ h16 g_Vh[NBATCH*NHEAD*SEQ*DHEAD];    // V hi/lo fp16 (direct path)
__device__ h16 g_Vl[NBATCH*NHEAD*SEQ*DHEAD];

__device__ h16 g_xh[(size_t)NTOK*HID];
__device__ h16 g_xl[(size_t)NTOK*HID];
__device__ h16 g_ch[(size_t)NTOK*HID];          // ctx hi/lo (flash output)
__device__ h16 g_cl[(size_t)NTOK*HID];
__device__ h16 g_wh[4][(size_t)HID*HID];
__device__ h16 g_wl[4][(size_t)HID*HID];

__device__ float2 g_cs[SEQ*DHEAD];              // (cos, sin) of freqs

// ---------------------------------------------------------------------------
// helpers
// ---------------------------------------------------------------------------
__device__ __forceinline__ uint32_t smem_u32(const void* p) {
    uint32_t a;
    asm("{ .reg .u64 t; cvta.to.shared.u64 t, %1; cvt.u32.u64 %0, t; }"
        : "=r"(a) : "l"(p));
    return a;
}
__device__ __forceinline__ void ldm4(uint32_t* r, uint32_t addr) {
    asm volatile("ldmatrix.sync.aligned.m8n8.x4.shared.b16 {%0,%1,%2,%3},[%4];"
                 : "=r"(r[0]), "=r"(r[1]), "=r"(r[2]), "=r"(r[3]) : "r"(addr));
}
__device__ __forceinline__ void ldm4t(uint32_t* r, uint32_t addr) {
    asm volatile("ldmatrix.sync.aligned.m8n8.x4.trans.shared.b16 {%0,%1,%2,%3},[%4];"
                 : "=r"(r[0]), "=r"(r[1]), "=r"(r[2]), "=r"(r[3]) : "r"(addr));
}
__device__ __forceinline__ void mma16816(float* d, const uint32_t* a,
                                         uint32_t b0, uint32_t b1) {
    asm volatile(
        "mma.sync.aligned.m16n8k16.row.col.f32.f16.f16.f32 "
        "{%0,%1,%2,%3},{%4,%5,%6,%7},{%8,%9},{%0,%1,%2,%3};"
        : "+f"(d[0]), "+f"(d[1]), "+f"(d[2]), "+f"(d[3])
        : "r"(a[0]), "r"(a[1]), "r"(a[2]), "r"(a[3]), "r"(b0), "r"(b1));
}
__device__ __forceinline__ uint32_t packh2(h16 a, h16 b) {
    return ((uint32_t)__half_as_ushort(b) << 16) | __half_as_ushort(a);
}
__device__ __forceinline__ void split1h(float v, h16& h, h16& l) {
    h = __float2half_rn(v);
    l = __float2half_rn(v - __half2float(h));
}
__device__ __forceinline__ void split2packh(float a, float b,
                                            uint32_t& hp, uint32_t& lp) {
    h16 ha, la, hb, lb;
    split1h(a, ha, la);
    split1h(b, hb, lb);
    hp = packh2(ha, hb);
    lp = packh2(la, lb);
}
__device__ __forceinline__ void cpa16(uint32_t s, const void* g) {
    asm volatile("cp.async.cg.shared.global [%0], [%1], 16;" :: "r"(s), "l"(g));
}
#define CP_COMMIT() asm volatile("cp.async.commit_group;" ::: "memory")
#define CP_WAIT0()  asm volatile("cp.async.wait_group 0;" ::: "memory")

// ---------------------------------------------------------------------------
// cos/sin table from freqs
// ---------------------------------------------------------------------------
__global__ __launch_bounds__(256)
void build_cs(const float* __restrict__ freqs)
{
    int i = blockIdx.x * 256 + threadIdx.x;   // SEQ*DHEAD = 262144
    float f = freqs[i];
    g_cs[i] = make_float2(cosf(f), sinf(f));
}

// ---------------------------------------------------------------------------
// Fused split: x + 4 weights, fp32 -> fp16 hi + fp16 lo, one launch.
// ---------------------------------------------------------------------------
__global__ __launch_bounds__(256)
void split_all(const float* __restrict__ x,
               const float* __restrict__ w0, const float* __restrict__ w1,
               const float* __restrict__ w2, const float* __restrict__ w3,
               h16* __restrict__ xh, h16* __restrict__ xl,
               h16* __restrict__ whb, h16* __restrict__ wlb)
{
    const int XQ = NTOK * HID / 4;    // 2^21
    const int WQ = HID * HID / 4;     // 2^20
    int i = blockIdx.x * 256 + threadIdx.x;
    const float* src; h16 *dh, *dl; int off;
    if (i < XQ) { src = x; dh = xh; dl = xl; off = i; }
    else {
        int j = i - XQ;
        int widx = j >> 20;
        off = j & (WQ - 1);
        src = (widx == 0) ? w0 : (widx == 1) ? w1 : (widx == 2) ? w2 : w3;
        dh = whb + (size_t)widx * HID * HID;
        dl = wlb + (size_t)widx * HID * HID;
    }
    float4 v = ((const float4*)src)[off];
    float vv[4] = {v.x, v.y, v.z, v.w};
    h16 hh[4], ll[4];
    #pragma unroll
    for (int j = 0; j < 4; j++) split1h(vv[j], hh[j], ll[j]);
    ((uint2*)dh)[off] = make_uint2(packh2(hh[0], hh[1]), packh2(hh[2], hh[3]));
    ((uint2*)dl)[off] = make_uint2(packh2(ll[0], ll[1]), packh2(ll[2], ll[3]));
}

// ---------------------------------------------------------------------------
// Tensor-core GEMM, cp.async 2-stage, NPROD products (1 or 3).
// ROPE=true (QK fused launch, sel=-1): B smem rows permuted so each warp's
// accumulator holds rotation pairs (d, d+64); epilogue applies RoPE from
// g_cs and writes single fp16 to g_Qf/g_Kf.
// ROPE=false: sel 2 -> h16 hi/lo g_Vh/g_Vl; sel 3 -> fp32 row-major Cout.
// ---------------------------------------------------------------------------
#define SPAD 40
#define ARR_B   (128*SPAD*2)          // bytes per operand array (10240)

template<int NPROD, bool ROPE>
__global__ __launch_bounds__(256)
void mma_gemm(const h16* __restrict__ Ah, const h16* __restrict__ Al,
              const h16* __restrict__ BhBase, const h16* __restrict__ BlBase,
              float* __restrict__ Cout, int sel)
{
    extern __shared__ char dsm[];
    const uint32_t ub = smem_u32(dsm);
    constexpr int NARR  = (NPROD == 3) ? 4 : 2;
    constexpr int STB   = NARR * ARR_B;

    const int t    = threadIdx.x;
    const int wid  = t >> 5;
    const int lane = t & 31;
    const int m0   = blockIdx.y << 7;
    const int wm   = wid & 1;
    const int wn   = wid >> 1;

    int sel_, n0;
    const h16 *Bh, *Bl;
    if (sel < 0) {
        int widx = blockIdx.x >> 4;
        sel_ = widx;
        n0   = (blockIdx.x & 15) << 7;
        Bh = BhBase + (size_t)widx * HID * HID;
        Bl = BlBase ? BlBase + (size_t)widx * HID * HID : nullptr;
    } else {
        sel_ = sel;
        n0   = blockIdx.x << 7;
        Bh = BhBase;
        Bl = BlBase;
    }

    int rowL[2], qdL[2];
    #pragma unroll
    for (int r = 0; r < 2; r++) {
        int u = t + (r << 8);
        rowL[r] = u >> 2;
        qdL[r]  = u & 3;
    }

    const h16* pAh = Ah + (size_t)m0 * HID;
    const h16* pAl = (NPROD == 3) ? (Al + (size_t)m0 * HID) : nullptr;
    const h16* pBh = Bh + (size_t)n0 * HID;
    const h16* pBl = (NPROD == 3) ? (Bl + (size_t)n0 * HID) : nullptr;

    float acc[4][4][4];
    #pragma unroll
    for (int i = 0; i < 4; i++)
        #pragma unroll
        for (int j = 0; j < 4; j++)
            #pragma unroll
            for (int q = 0; q < 4; q++)
                acc[i][j][q] = 0.f;

    const int lrow = lane & 15, lcol = lane >> 4;
    const int NCH = HID / 32;

    auto issue = [&](int c, int buf) {
        uint32_t sb = ub + buf * STB;
        #pragma unroll
        for (int r = 0; r < 2; r++) {
            int row = rowL[r], qd = qdL[r];
            // B row permutation for ROPE: smem row -> weight row, pairing d/d+64
            int brow = row;
            if (ROPE) {
                int gg = row >> 5, ss = row & 31;
                brow = (ss < 16) ? gg*16 + ss : 64 + gg*16 + (ss - 16);
            }
            uint32_t so = (uint32_t)(row * SPAD + qd * 8) * 2;
            size_t   goA = (size_t)row  * HID + (size_t)c * 32 + qd * 8;
            size_t   goB = (size_t)brow * HID + (size_t)c * 32 + qd * 8;
            if (NPROD == 3) {
                cpa16(sb + so,             pAh + goA);
                cpa16(sb + ARR_B + so,     pAl + goA);
                cpa16(sb + 2*ARR_B + so,   pBh + goB);
                cpa16(sb + 3*ARR_B + so,   pBl + goB);
            } else {
                cpa16(sb + so,             pAh + goA);
                cpa16(sb + ARR_B + so,     pBh + goB);
            }
        }
        CP_COMMIT();
    };

    issue(0, 0);

    for (int c = 0; c < NCH; c++) {
        CP_WAIT0();
        __syncthreads();
        if (c + 1 < NCH) issue(c + 1, (c + 1) & 1);

        const uint32_t sb  = ub + (c & 1) * STB;
        const uint32_t uAh = sb;
        const uint32_t uAl = sb + ARR_B;                      // NPROD==3 only
        const uint32_t uBh = (NPROD == 3) ? sb + 2*ARR_B : sb + ARR_B;
        const uint32_t uBl = sb + 3*ARR_B;                    // NPROD==3 only

        #pragma unroll
        for (int kh = 0; kh < 2; kh++) {
            uint32_t ah[4][4], al[4][4], bh[2][4], bl[2][4];
            #pragma unroll
            for (int mt = 0; mt < 4; mt++) {
                uint32_t off = (uint32_t)((wm*64 + mt*16 + lrow) * SPAD + kh*16 + lcol*8) * 2;
                ldm4(ah[mt], uAh + off);
                if (NPROD == 3) ldm4(al[mt], uAl + off);
            }
            #pragma unroll
            for (int n2 = 0; n2 < 2; n2++) {
                uint32_t off = (uint32_t)((wn*32 + n2*16 + lrow) * SPAD + kh*16 + lcol*8) * 2;
                ldm4(bh[n2], uBh + off);
                if (NPROD == 3) ldm4(bl[n2], uBl + off);
            }
            #pragma unroll
            for (int mt = 0; mt < 4; mt++)
                #pragma unroll
                for (int nt = 0; nt < 4; nt++) {
                    int n2 = nt >> 1, hb = nt & 1;
                    mma16816(acc[mt][nt], ah[mt], bh[n2][hb], bh[n2][hb+2]);
                    if (NPROD == 3) {
                        mma16816(acc[mt][nt], ah[mt], bl[n2][hb], bl[n2][hb+2]);
                        mma16816(acc[mt][nt], al[mt], bh[n2][hb], bh[n2][hb+2]);
                    }
                }
        }
    }

    const int rbase = wm*64 + (lane >> 2);
    const int cbase = wn*32 + 2*(lane & 3);
    if (ROPE) {
        // sel_ 0 (Q) or 1 (K): apply RoPE in-register, write single fp16 bhsd.
        h16* outp = (sel_ == 0) ? g_Qf : g_Kf;
        const int h = n0 >> 7;
        const int dd0 = wn*16 + 2*(lane & 3);
        #pragma unroll
        for (int mt = 0; mt < 4; mt++)
            #pragma unroll
            for (int ntp = 0; ntp < 2; ntp++) {
                int d = dd0 + ntp*8;
                #pragma unroll
                for (int rr = 0; rr < 2; rr++) {
                    int r0 = m0 + rbase + mt*16 + rr*8;
                    int b  = r0 >> 11;
                    int s  = r0 & (SEQ - 1);
                    const float2* trow = g_cs + (size_t)s * DHEAD;
                    float2 cs1a = trow[d],      cs1b = trow[d+1];
                    float2 cs2a = trow[d+64],   cs2b = trow[d+65];
                    float x1a = acc[mt][ntp][rr*2+0],   x1b = acc[mt][ntp][rr*2+1];
                    float x2a = acc[mt][ntp+2][rr*2+0], x2b = acc[mt][ntp+2][rr*2+1];
                    float y1a = x1a*cs1a.x - x2a*cs1a.y;
                    float y1b = x1b*cs1b.x - x2b*cs1b.y;
                    float y2a = x2a*cs2a.x + x1a*cs2a.y;
                    float y2b = x2b*cs2b.x + x1b*cs2b.y;
                    size_t base = (((size_t)(b*NHEAD + h))*SEQ + s)*DHEAD;
                    *(uint32_t*)&outp[base + d] =
                        packh2(__float2half_rn(y1a), __float2half_rn(y1b));
                    *(uint32_t*)&outp[base + d + 64] =
                        packh2(__float2half_rn(y2a), __float2half_rn(y2b));
                }
            }
    } else if (sel_ == 3) {
        #pragma unroll
        for (int mt = 0; mt < 4; mt++)
            #pragma unroll
            for (int nt = 0; nt < 4; nt++) {
                int r0 = m0 + rbase + mt*16;
                int cc = n0 + cbase + nt*8;
                *(float2*)&Cout[(size_t)r0 * HID + cc]       = make_float2(acc[mt][nt][0], acc[mt][nt][1]);
                *(float2*)&Cout[(size_t)(r0 + 8) * HID + cc] = make_float2(acc[mt][nt][2], acc[mt][nt][3]);
            }
    } else {
        // sel_ == 2: V projection, h16 hi/lo bhsd
        const int h = n0 >> 7;
        #pragma unroll
        for (int mt = 0; mt < 4; mt++)
            #pragma unroll
            for (int nt = 0; nt < 4; nt++) {
                int r0 = m0 + rbase + mt*16;
                int b  = r0 >> 11;
                int s  = r0 & (SEQ - 1);
                int d  = cbase + nt*8;
                size_t base = (((size_t)(b*NHEAD + h))*SEQ + s)*DHEAD + d;
                uint32_t hp, lp;
                split2packh(acc[mt][nt][0], acc[mt][nt][1], hp, lp);
                *(uint32_t*)&g_Vh[base] = hp;
                *(uint32_t*)&g_Vl[base] = lp;
                split2packh(acc[mt][nt][2], acc[mt][nt][3], hp, lp);
                *(uint32_t*)&g_Vh[base + 8*DHEAD] = hp;
                *(uint32_t*)&g_Vl[base + 8*DHEAD] = lp;
            }
    }
}

#define GEMM_SMEM3 (2 * 4 * ARR_B)   // 81920
#define GEMM_SMEM1 (2 * 2 * ARR_B)   // 40960

// ---------------------------------------------------------------------------
// Flash attention: S = Qf·Kf^T single-product; PV = P(single)·(Vh+Vl).
// Warp owns 16 q-rows x full Bk=64; Q fragments hoisted into registers;
// P in registers; intra-warp softmax; K/V cp.async double-buffered.
// ---------------------------------------------------------------------------
#define BQ 128
#define BK 64
#define QSTR 136
#define KSTR 136
#define QARR (128*QSTR*2)        // 34816 bytes (single Q array)
#define KARR (64*KSTR*2)         // 17408 bytes per KV array
#define KVSTAGE (3*KARR)         // K, Vh, Vl = 52224
#define OFF_KV QARR
#define FLASH_SMEM (QARR + 2*KVSTAGE)   // 139264

__global__ __launch_bounds__(256, 1)
void flash_mma(const float* __restrict__ mask, const float* __restrict__ alibi)
{
    extern __shared__ char sm[];
    const uint32_t ub = smem_u32(sm);
    const uint32_t uQ = ub;
    h16* sQ = (h16*)sm;

    const int t    = threadIdx.x;
    const int lane = t & 31;
    const int wid  = t >> 5;
    const int qb   = blockIdx.x;
    const int bhid = blockIdx.y;
    const int h    = bhid & (NHEAD - 1);
    const int b    = bhid >> 4;
    const int qi0  = qb * BQ;
    const size_t hbase = (size_t)bhid * SEQ * DHEAD;

    const int lrow = lane & 15, lcol = lane >> 4;
    const int g = lane >> 2, tq = lane & 3;
    const float SCALE = 0.08838834764831845f;  // 1/sqrt(128)

    // Q tile load (sync stores)
    #pragma unroll
    for (int rep = 0; rep < 8; rep++) {
        int u = t + rep * 256;
        int row = u >> 4, c8 = (u & 15) * 8;
        *(uint4*)&sQ[row*QSTR + c8] =
            *(const uint4*)(g_Qf + hbase + (size_t)(qi0 + row) * DHEAD + c8);
    }

    // KV async stage loader: K single, V hi/lo
    auto issueKV = [&](int kt) {
        uint32_t sb = ub + OFF_KV + (kt & 1) * KVSTAGE;
        const int kj0 = kt * BK;
        #pragma unroll
        for (int rep = 0; rep < 4; rep++) {
            int u = t + rep * 256;
            int row = u >> 4, c8 = (u & 15) * 8;
            uint32_t so = (uint32_t)(row * KSTR + c8) * 2;
            size_t   go = hbase + (size_t)(kj0 + row) * DHEAD + c8;
            cpa16(sb + so,          g_Kf + go);
            cpa16(sb + KARR + so,   g_Vh + go);
            cpa16(sb + 2*KARR + so, g_Vl + go);
        }
        CP_COMMIT();
    };
    issueKV(0);

    // wait KV0 + Q stores, hoist Q fragments, start KV1 prefetch
    CP_WAIT0();
    __syncthreads();
    uint32_t qa[8][4];
    #pragma unroll
    for (int kk = 0; kk < 8; kk++) {
        uint32_t qoff = (uint32_t)((wid*16 + lrow)*QSTR + kk*16 + lcol*8) * 2;
        ldm4(qa[kk], uQ + qoff);
    }
    issueKV(1);

    float o[16][4];
    #pragma unroll
    for (int nt = 0; nt < 16; nt++)
        #pragma unroll
        for (int q = 0; q < 4; q++)
            o[nt][q] = 0.f;
    float m0r = -1e30f, m8r = -1e30f, l0r = 0.f, l8r = 0.f;
    const int r0g = qi0 + wid*16 + g;

    for (int kt = 0; kt < SEQ / BK; kt++) {
        const int kj0 = kt * BK;
        if (kt > 0) {
            CP_WAIT0();
            __syncthreads();
            if (kt + 1 < SEQ / BK) issueKV(kt + 1);
        }

        const uint32_t sb  = ub + OFF_KV + (kt & 1) * KVSTAGE;
        const uint32_t uK  = sb;
        const uint32_t uVh = sb + KARR, uVl = sb + 2*KARR;

        // ---- S = Q K^T : warp tile 16 x 64, single product ----
        float sacc[8][4];
        #pragma unroll
        for (int nt = 0; nt < 8; nt++)
            #pragma unroll
            for (int q = 0; q < 4; q++)
                sacc[nt][q] = 0.f;

        #pragma unroll
        for (int kk = 0; kk < 8; kk++) {
            uint32_t kb[4][4];
            #pragma unroll
            for (int n2 = 0; n2 < 4; n2++) {
                uint32_t koff = (uint32_t)((n2*16 + lrow)*KSTR + kk*16 + lcol*8) * 2;
                ldm4(kb[n2], uK + koff);
            }
            #pragma unroll
            for (int nt = 0; nt < 8; nt++) {
                int n2 = nt >> 1, hb = nt & 1;
                mma16816(sacc[nt], qa[kk], kb[n2][hb], kb[n2][hb+2]);
            }
        }

        // ---- scale + mask + alibi, row max (intra-warp only) ----
        float rmax0 = -1e30f, rmax8 = -1e30f;
        #pragma unroll
        for (int nt = 0; nt < 8; nt++) {
            int col = kj0 + nt*8 + 2*tq;
            float2 av  = *(const float2*)(alibi + (size_t)h * SEQ + col);
            float2 mv0 = *(const float2*)(mask + (size_t)r0g * SEQ + col);
            float2 mv1 = *(const float2*)(mask + (size_t)(r0g + 8) * SEQ + col);
            sacc[nt][0] = fmaf(sacc[nt][0], SCALE, mv0.x + av.x);
            sacc[nt][1] = fmaf(sacc[nt][1], SCALE, mv0.y + av.y);
            sacc[nt][2] = fmaf(sacc[nt][2], SCALE, mv1.x + av.x);
            sacc[nt][3] = fmaf(sacc[nt][3], SCALE, mv1.y + av.y);
            rmax0 = fmaxf(rmax0, fmaxf(sacc[nt][0], sacc[nt][1]));
            rmax8 = fmaxf(rmax8, fmaxf(sacc[nt][2], sacc[nt][3]));
        }
        #pragma unroll
        for (int off = 1; off <= 2; off <<= 1) {
            rmax0 = fmaxf(rmax0, __shfl_xor_sync(0xffffffffu, rmax0, off));
            rmax8 = fmaxf(rmax8, __shfl_xor_sync(0xffffffffu, rmax8, off));
        }

        float nm0 = fmaxf(m0r, rmax0), nm8 = fmaxf(m8r, rmax8);
        float c0 = __expf(m0r - nm0),  c8 = __expf(m8r - nm8);
        m0r = nm0; m8r = nm8;

        // ---- exp + pack P fragments (single fp16, errors wash out) ----
        float rs0 = 0.f, rs8 = 0.f;
        uint32_t ph[4][4];
        #pragma unroll
        for (int kk = 0; kk < 4; kk++) {
            #pragma unroll
            for (int half = 0; half < 2; half++) {
                int nt = 2*kk + half;
                float p0 = __expf(sacc[nt][0] - nm0);
                float p1 = __expf(sacc[nt][1] - nm0);
                float p2 = __expf(sacc[nt][2] - nm8);
                float p3 = __expf(sacc[nt][3] - nm8);
                rs0 += p0 + p1; rs8 += p2 + p3;
                ph[kk][half*2+0] = packh2(__float2half_rn(p0), __float2half_rn(p1));
                ph[kk][half*2+1] = packh2(__float2half_rn(p2), __float2half_rn(p3));
            }
        }
        #pragma unroll
        for (int off = 1; off <= 2; off <<= 1) {
            rs0 += __shfl_xor_sync(0xffffffffu, rs0, off);
            rs8 += __shfl_xor_sync(0xffffffffu, rs8, off);
        }
        l0r = l0r * c0 + rs0;
        l8r = l8r * c8 + rs8;

        // ---- rescale O ----
        #pragma unroll
        for (int nt = 0; nt < 16; nt++) {
            o[nt][0] *= c0; o[nt][1] *= c0;
            o[nt][2] *= c8; o[nt][3] *= c8;
        }

        // ---- O += P (Vh + Vl) : 2-product ----
        #pragma unroll
        for (int kk = 0; kk < 4; kk++) {
            #pragma unroll
            for (int dd = 0; dd < 8; dd++) {
                uint32_t vh_[4], vl_[4];
                uint32_t voff = (uint32_t)((kk*16 + lrow)*KSTR + dd*16 + lcol*8) * 2;
                ldm4t(vh_, uVh + voff);
                ldm4t(vl_, uVl + voff);
                mma16816(o[dd*2+0], ph[kk], vh_[0], vh_[1]);
                mma16816(o[dd*2+0], ph[kk], vl_[0], vl_[1]);
                mma16816(o[dd*2+1], ph[kk], vh_[2], vh_[3]);
                mma16816(o[dd*2+1], ph[kk], vl_[2], vl_[3]);
            }
        }
    }

    // ---- epilogue: normalize, split to fp16 hi/lo ctx [tok][h*128+d] ----
    float inv0 = 1.f / l0r, inv8 = 1.f / l8r;
    size_t tok0 = ((size_t)(b*SEQ + qi0 + wid*16 + g)) * HID + h * DHEAD;
    size_t tok8 = tok0 + (size_t)8 * HID;
    #pragma unroll
    for (int nt = 0; nt < 16; nt++) {
        int d = nt*8 + 2*tq;
        uint32_t hp, lp;
        split2packh(o[nt][0]*inv0, o[nt][1]*inv0, hp, lp);
        *(uint32_t*)&g_ch[tok0 + d] = hp;
        *(uint32_t*)&g_cl[tok0 + d] = lp;
        split2packh(o[nt][2]*inv8, o[nt][3]*inv8, hp, lp);
        *(uint32_t*)&g_ch[tok8 + d] = hp;
        *(uint32_t*)&g_cl[tok8 + d] = lp;
    }
}

// ---------------------------------------------------------------------------
extern "C" void kernel_launch(void* const* d_in, const int* in_sizes, int n_in,
                              void* d_out, int out_size)
{
    const float* x     = (const float*)d_in[0];
    const float* mask  = (const float*)d_in[1];
    const float* alibi = (const float*)d_in[2];
    const float* freqs = (const float*)d_in[3];
    const float* W[4]  = { (const float*)d_in[4], (const float*)d_in[5],
                           (const float*)d_in[6], (const float*)d_in[7] };
    float* out = (float*)d_out;
    (void)in_sizes; (void)n_in; (void)out_size;

    cudaFuncSetAttribute(flash_mma,
                         cudaFuncAttributeMaxDynamicSharedMemorySize, FLASH_SMEM);
    cudaFuncSetAttribute((mma_gemm<3, false>),
                         cudaFuncAttributeMaxDynamicSharedMemorySize, GEMM_SMEM3);
    cudaFuncSetAttribute((mma_gemm<1, true>),
                         cudaFuncAttributeMaxDynamicSharedMemorySize, GEMM_SMEM1);

    h16 *xh, *xl, *ch, *cl, *whbase, *wlbase;
    cudaGetSymbolAddress((void**)&xh, g_xh);
    cudaGetSymbolAddress((void**)&xl, g_xl);
    cudaGetSymbolAddress((void**)&ch, g_ch);
    cudaGetSymbolAddress((void**)&cl, g_cl);
    cudaGetSymbolAddress((void**)&whbase, g_wh);
    cudaGetSymbolAddress((void**)&wlbase, g_wl);

    // fused splits + cos/sin table
    {
        int total = (NTOK * HID + 4 * HID * HID) / 4;   // 6M quads
        split_all<<<(total + 255) / 256, 256>>>(
            x, W[0], W[1], W[2], W[3], xh, xl, whbase, wlbase);
        build_cs<<<(SEQ * DHEAD) / 256, 256>>>(freqs);
    }

    // Q,K projections: fused, 1-product, RoPE applied in epilogue
    mma_gemm<1, true><<<dim3(32, NTOK/128), 256, GEMM_SMEM1>>>(
        xh, nullptr, whbase, nullptr, nullptr, -1);

    // V projection: 3-product (direct path)
    mma_gemm<3, false><<<dim3(16, NTOK/128), 256, GEMM_SMEM3>>>(
        xh, xl, whbase + 2*(size_t)HID*HID, wlbase + 2*(size_t)HID*HID, nullptr, 2);

    flash_mma<<<dim3(SEQ/BQ, NBATCH*NHEAD), 256, FLASH_SMEM>>>(mask, alibi);

    // O projection: 3-product (direct path)
    mma_gemm<3, false><<<dim3(16, NTOK/128), 256, GEMM_SMEM3>>>(
        ch, cl, whbase + 3*(size_t)HID*HID, wlbase + 3*(size_t)HID*HID, out, 3);
}

// round 10
// speedup vs baseline: 3.8428x; 1.0353x over previous
#include <cuda_runtime.h>
#include <cuda_fp16.h>
#include <math.h>
#include <cstdint>

typedef __half h16;

// Problem constants
#define NBATCH 2
#define SEQ    2048
#define NHEAD  16
#define DHEAD  128
#define HID    2048
#define NTOK   4096   // NBATCH*SEQ

// Scratch (device globals — no runtime allocation allowed)
__device__ h16 g_Qf[NBATCH*NHEAD*SEQ*DHEAD];    // post-RoPE, single fp16
__device__ h16 g_Kf[NBATCH*NHEAD*SEQ*DHEAD];
__device__ h16 g_Vh[NBATCH*NHEAD*SEQ*DHEAD];    // V hi/lo fp16 (direct path)
__device__ h16 g_Vl[NBATCH*NHEAD*SEQ*DHEAD];

__device__ h16 g_xh[(size_t)NTOK*HID];
__device__ h16 g_xl[(size_t)NTOK*HID];
__device__ h16 g_ch[(size_t)NTOK*HID];          // ctx hi/lo (flash output)
__device__ h16 g_cl[(size_t)NTOK*HID];
__device__ h16 g_wh[4][(size_t)HID*HID];
__device__ h16 g_wl[4][(size_t)HID*HID];

__device__ float2 g_cs[SEQ*DHEAD];              // (cos, sin) of freqs

// ---------------------------------------------------------------------------
// helpers
// ---------------------------------------------------------------------------
__device__ __forceinline__ uint32_t smem_u32(const void* p) {
    uint32_t a;
    asm("{ .reg .u64 t; cvta.to.shared.u64 t, %1; cvt.u32.u64 %0, t; }"
        : "=r"(a) : "l"(p));
    return a;
}
__device__ __forceinline__ void ldm4(uint32_t* r, uint32_t addr) {
    asm volatile("ldmatrix.sync.aligned.m8n8.x4.shared.b16 {%0,%1,%2,%3},[%4];"
                 : "=r"(r[0]), "=r"(r[1]), "=r"(r[2]), "=r"(r[3]) : "r"(addr));
}
__device__ __forceinline__ void ldm4t(uint32_t* r, uint32_t addr) {
    asm volatile("ldmatrix.sync.aligned.m8n8.x4.trans.shared.b16 {%0,%1,%2,%3},[%4];"
                 : "=r"(r[0]), "=r"(r[1]), "=r"(r[2]), "=r"(r[3]) : "r"(addr));
}
__device__ __forceinline__ void mma16816(float* d, const uint32_t* a,
                                         uint32_t b0, uint32_t b1) {
    asm volatile(
        "mma.sync.aligned.m16n8k16.row.col.f32.f16.f16.f32 "
        "{%0,%1,%2,%3},{%4,%5,%6,%7},{%8,%9},{%0,%1,%2,%3};"
        : "+f"(d[0]), "+f"(d[1]), "+f"(d[2]), "+f"(d[3])
        : "r"(a[0]), "r"(a[1]), "r"(a[2]), "r"(a[3]), "r"(b0), "r"(b1));
}
__device__ __forceinline__ uint32_t packh2(h16 a, h16 b) {
    return ((uint32_t)__half_as_ushort(b) << 16) | __half_as_ushort(a);
}
__device__ __forceinline__ void split1h(float v, h16& h, h16& l) {
    h = __float2half_rn(v);
    l = __float2half_rn(v - __half2float(h));
}
__device__ __forceinline__ void split2packh(float a, float b,
                                            uint32_t& hp, uint32_t& lp) {
    h16 ha, la, hb, lb;
    split1h(a, ha, la);
    split1h(b, hb, lb);
    hp = packh2(ha, hb);
    lp = packh2(la, lb);
}
__device__ __forceinline__ void cpa16(uint32_t s, const void* g) {
    asm volatile("cp.async.cg.shared.global [%0], [%1], 16;" :: "r"(s), "l"(g));
}
#define CP_COMMIT() asm volatile("cp.async.commit_group;" ::: "memory")
#define CP_WAIT0()  asm volatile("cp.async.wait_group 0;" ::: "memory")

// ---------------------------------------------------------------------------
// cos/sin table from freqs
// ---------------------------------------------------------------------------
__global__ __launch_bounds__(256)
void build_cs(const float* __restrict__ freqs)
{
    int i = blockIdx.x * 256 + threadIdx.x;
    float f = freqs[i];
    g_cs[i] = make_float2(cosf(f), sinf(f));
}

// ---------------------------------------------------------------------------
// Fused split: x + 4 weights, fp32 -> fp16 hi + fp16 lo, one launch.
// ---------------------------------------------------------------------------
__global__ __launch_bounds__(256)
void split_all(const float* __restrict__ x,
               const float* __restrict__ w0, const float* __restrict__ w1,
               const float* __restrict__ w2, const float* __restrict__ w3,
               h16* __restrict__ xh, h16* __restrict__ xl,
               h16* __restrict__ whb, h16* __restrict__ wlb)
{
    const int XQ = NTOK * HID / 4;
    const int WQ = HID * HID / 4;
    int i = blockIdx.x * 256 + threadIdx.x;
    const float* src; h16 *dh, *dl; int off;
    if (i < XQ) { src = x; dh = xh; dl = xl; off = i; }
    else {
        int j = i - XQ;
        int widx = j >> 20;
        off = j & (WQ - 1);
        src = (widx == 0) ? w0 : (widx == 1) ? w1 : (widx == 2) ? w2 : w3;
        dh = whb + (size_t)widx * HID * HID;
        dl = wlb + (size_t)widx * HID * HID;
    }
    float4 v = ((const float4*)src)[off];
    float vv[4] = {v.x, v.y, v.z, v.w};
    h16 hh[4], ll[4];
    #pragma unroll
    for (int j = 0; j < 4; j++) split1h(vv[j], hh[j], ll[j]);
    ((uint2*)dh)[off] = make_uint2(packh2(hh[0], hh[1]), packh2(hh[2], hh[3]));
    ((uint2*)dl)[off] = make_uint2(packh2(ll[0], ll[1]), packh2(ll[2], ll[3]));
}

// ---------------------------------------------------------------------------
// GEMM core: 128x128 tile, cp.async 2-stage, NPROD products (1 or 3).
// ropePerm permutes B smem rows so accumulators pair (d, d+64).
// ---------------------------------------------------------------------------
#define SPAD 40
#define ARR_B   (128*SPAD*2)          // 10240
#define GEMM_SMEM (2 * 4 * ARR_B)     // 81920 (max; NPROD=1 uses half)

template<int NPROD>
__device__ __forceinline__ void gemm_core(
    const h16* __restrict__ pAh, const h16* __restrict__ pAl,
    const h16* __restrict__ pBh, const h16* __restrict__ pBl,
    uint32_t ub, bool ropePerm, float acc[4][4][4])
{
    constexpr int STB = (NPROD == 3 ? 4 : 2) * ARR_B;
    const int t    = threadIdx.x;
    const int wid  = t >> 5;
    const int lane = t & 31;
    const int wm   = wid & 1;
    const int wn   = wid >> 1;
    const int lrow = lane & 15, lcol = lane >> 4;

    int rowL[2], qdL[2];
    #pragma unroll
    for (int r = 0; r < 2; r++) {
        int u = t + (r << 8);
        rowL[r] = u >> 2;
        qdL[r]  = u & 3;
    }

    #pragma unroll
    for (int i = 0; i < 4; i++)
        #pragma unroll
        for (int j = 0; j < 4; j++)
            #pragma unroll
            for (int q = 0; q < 4; q++)
                acc[i][j][q] = 0.f;

    const int NCH = HID / 32;

    auto issue = [&](int c, int buf) {
        uint32_t sb = ub + buf * STB;
        #pragma unroll
        for (int r = 0; r < 2; r++) {
            int row = rowL[r], qd = qdL[r];
            int brow = row;
            if (ropePerm) {
                int gg = row >> 5, ss = row & 31;
                brow = (ss < 16) ? gg*16 + ss : 64 + gg*16 + (ss - 16);
            }
            uint32_t so = (uint32_t)(row * SPAD + qd * 8) * 2;
            size_t   goA = (size_t)row  * HID + (size_t)c * 32 + qd * 8;
            size_t   goB = (size_t)brow * HID + (size_t)c * 32 + qd * 8;
            if (NPROD == 3) {
                cpa16(sb + so,             pAh + goA);
                cpa16(sb + ARR_B + so,     pAl + goA);
                cpa16(sb + 2*ARR_B + so,   pBh + goB);
                cpa16(sb + 3*ARR_B + so,   pBl + goB);
            } else {
                cpa16(sb + so,             pAh + goA);
                cpa16(sb + ARR_B + so,     pBh + goB);
            }
        }
        CP_COMMIT();
    };

    issue(0, 0);

    for (int c = 0; c < NCH; c++) {
        CP_WAIT0();
        __syncthreads();
        if (c + 1 < NCH) issue(c + 1, (c + 1) & 1);

        const uint32_t sb  = ub + (c & 1) * STB;
        const uint32_t uAh = sb;
        const uint32_t uAl = sb + ARR_B;
        const uint32_t uBh = (NPROD == 3) ? sb + 2*ARR_B : sb + ARR_B;
        const uint32_t uBl = sb + 3*ARR_B;

        #pragma unroll
        for (int kh = 0; kh < 2; kh++) {
            uint32_t ah[4][4], al[4][4], bh[2][4], bl[2][4];
            #pragma unroll
            for (int mt = 0; mt < 4; mt++) {
                uint32_t off = (uint32_t)((wm*64 + mt*16 + lrow) * SPAD + kh*16 + lcol*8) * 2;
                ldm4(ah[mt], uAh + off);
                if (NPROD == 3) ldm4(al[mt], uAl + off);
            }
            #pragma unroll
            for (int n2 = 0; n2 < 2; n2++) {
                uint32_t off = (uint32_t)((wn*32 + n2*16 + lrow) * SPAD + kh*16 + lcol*8) * 2;
                ldm4(bh[n2], uBh + off);
                if (NPROD == 3) ldm4(bl[n2], uBl + off);
            }
            #pragma unroll
            for (int mt = 0; mt < 4; mt++)
                #pragma unroll
                for (int nt = 0; nt < 4; nt++) {
                    int n2 = nt >> 1, hb = nt & 1;
                    mma16816(acc[mt][nt], ah[mt], bh[n2][hb], bh[n2][hb+2]);
                    if (NPROD == 3) {
                        mma16816(acc[mt][nt], ah[mt], bl[n2][hb], bl[n2][hb+2]);
                        mma16816(acc[mt][nt], al[mt], bh[n2][hb], bh[n2][hb+2]);
                    }
                }
        }
    }
}

// ---------------------------------------------------------------------------
// Fused QKV projection launch. grid (48, 32):
//   widx = bx>>4: 0 -> Q (1-product + RoPE), 1 -> K (same), 2 -> V (3-product).
// ---------------------------------------------------------------------------
__global__ __launch_bounds__(256)
void mma_gemm_qkv(const h16* __restrict__ xh, const h16* __restrict__ xl,
                  const h16* __restrict__ whb, const h16* __restrict__ wlb)
{
    extern __shared__ char dsm[];
    const uint32_t ub = smem_u32(dsm);

    const int t    = threadIdx.x;
    const int wid  = t >> 5;
    const int lane = t & 31;
    const int m0   = blockIdx.y << 7;
    const int wm   = wid & 1;
    const int wn   = wid >> 1;
    const int widx = blockIdx.x >> 4;
    const int n0   = (blockIdx.x & 15) << 7;
    const int h    = n0 >> 7;

    const h16* pAh = xh + (size_t)m0 * HID;
    const h16* pAl = xl + (size_t)m0 * HID;
    const h16* pBh = whb + (size_t)widx * HID * HID + (size_t)n0 * HID;
    const h16* pBl = wlb + (size_t)widx * HID * HID + (size_t)n0 * HID;

    float acc[4][4][4];
    const int rbase = wm*64 + (lane >> 2);

    if (widx < 2) {
        gemm_core<1>(pAh, nullptr, pBh, nullptr, ub, true, acc);
        // RoPE epilogue, write single fp16 bhsd
        h16* outp = (widx == 0) ? g_Qf : g_Kf;
        const int dd0 = wn*16 + 2*(lane & 3);
        #pragma unroll
        for (int mt = 0; mt < 4; mt++)
            #pragma unroll
            for (int ntp = 0; ntp < 2; ntp++) {
                int d = dd0 + ntp*8;
                #pragma unroll
                for (int rr = 0; rr < 2; rr++) {
                    int r0 = m0 + rbase + mt*16 + rr*8;
                    int b  = r0 >> 11;
                    int s  = r0 & (SEQ - 1);
                    const float2* trow = g_cs + (size_t)s * DHEAD;
                    float2 cs1a = trow[d],      cs1b = trow[d+1];
                    float2 cs2a = trow[d+64],   cs2b = trow[d+65];
                    float x1a = acc[mt][ntp][rr*2+0],   x1b = acc[mt][ntp][rr*2+1];
                    float x2a = acc[mt][ntp+2][rr*2+0], x2b = acc[mt][ntp+2][rr*2+1];
                    float y1a = x1a*cs1a.x - x2a*cs1a.y;
                    float y1b = x1b*cs1b.x - x2b*cs1b.y;
                    float y2a = x2a*cs2a.x + x1a*cs2a.y;
                    float y2b = x2b*cs2b.x + x1b*cs2b.y;
                    size_t base = (((size_t)(b*NHEAD + h))*SEQ + s)*DHEAD;
                    *(uint32_t*)&outp[base + d] =
                        packh2(__float2half_rn(y1a), __float2half_rn(y1b));
                    *(uint32_t*)&outp[base + d + 64] =
                        packh2(__float2half_rn(y2a), __float2half_rn(y2b));
                }
            }
    } else {
        gemm_core<3>(pAh, pAl, pBh, pBl, ub, false, acc);
        // V epilogue: h16 hi/lo bhsd
        const int cbase = wn*32 + 2*(lane & 3);
        #pragma unroll
        for (int mt = 0; mt < 4; mt++)
            #pragma unroll
            for (int nt = 0; nt < 4; nt++) {
                int r0 = m0 + rbase + mt*16;
                int b  = r0 >> 11;
                int s  = r0 & (SEQ - 1);
                int d  = cbase + nt*8;
                size_t base = (((size_t)(b*NHEAD + h))*SEQ + s)*DHEAD + d;
                uint32_t hp, lp;
                split2packh(acc[mt][nt][0], acc[mt][nt][1], hp, lp);
                *(uint32_t*)&g_Vh[base] = hp;
                *(uint32_t*)&g_Vl[base] = lp;
                split2packh(acc[mt][nt][2], acc[mt][nt][3], hp, lp);
                *(uint32_t*)&g_Vh[base + 8*DHEAD] = hp;
                *(uint32_t*)&g_Vl[base + 8*DHEAD] = lp;
            }
    }
}

// ---------------------------------------------------------------------------
// Final O projection: 3-product, fp32 row-major output.
// ---------------------------------------------------------------------------
__global__ __launch_bounds__(256)
void mma_gemm_o(const h16* __restrict__ ch, const h16* __restrict__ cl,
                const h16* __restrict__ wh, const h16* __restrict__ wl,
                float* __restrict__ Cout)
{
    extern __shared__ char dsm[];
    const uint32_t ub = smem_u32(dsm);

    const int t    = threadIdx.x;
    const int wid  = t >> 5;
    const int lane = t & 31;
    const int m0   = blockIdx.y << 7;
    const int n0   = blockIdx.x << 7;
    const int wm   = wid & 1;
    const int wn   = wid >> 1;

    float acc[4][4][4];
    gemm_core<3>(ch + (size_t)m0 * HID, cl + (size_t)m0 * HID,
                 wh + (size_t)n0 * HID, wl + (size_t)n0 * HID,
                 ub, false, acc);

    const int rbase = wm*64 + (lane >> 2);
    const int cbase = wn*32 + 2*(lane & 3);
    #pragma unroll
    for (int mt = 0; mt < 4; mt++)
        #pragma unroll
        for (int nt = 0; nt < 4; nt++) {
            int r0 = m0 + rbase + mt*16;
            int cc = n0 + cbase + nt*8;
            *(float2*)&Cout[(size_t)r0 * HID + cc]       = make_float2(acc[mt][nt][0], acc[mt][nt][1]);
            *(float2*)&Cout[(size_t)(r0 + 8) * HID + cc] = make_float2(acc[mt][nt][2], acc[mt][nt][3]);
        }
}

// ---------------------------------------------------------------------------
// Flash attention: BK=32, K/V cp.async double-buffered, smem 87KB -> 2 CTAs/SM.
// Warp owns 16 q-rows x full BK; P in registers; intra-warp softmax.
// ---------------------------------------------------------------------------
#define BQ 128
#define BK 32
#define QSTR 136
#define KSTR 136
#define QARR (128*QSTR*2)        // 34816
#define KARR (32*KSTR*2)         // 8704 per KV array
#define KVSTAGE (3*KARR)         // 26112
#define OFF_KV QARR
#define FLASH_SMEM (QARR + 2*KVSTAGE)   // 87040

__global__ __launch_bounds__(256, 2)
void flash_mma(const float* __restrict__ mask, const float* __restrict__ alibi)
{
    extern __shared__ char sm[];
    const uint32_t ub = smem_u32(sm);
    const uint32_t uQ = ub;
    h16* sQ = (h16*)sm;

    const int t    = threadIdx.x;
    const int lane = t & 31;
    const int wid  = t >> 5;
    const int qb   = blockIdx.x;
    const int bhid = blockIdx.y;
    const int h    = bhid & (NHEAD - 1);
    const int b    = bhid >> 4;
    const int qi0  = qb * BQ;
    const size_t hbase = (size_t)bhid * SEQ * DHEAD;

    const int lrow = lane & 15, lcol = lane >> 4;
    const int g = lane >> 2, tq = lane & 3;
    const float SCALE = 0.08838834764831845f;  // 1/sqrt(128)

    // Q tile load (sync stores)
    #pragma unroll
    for (int rep = 0; rep < 8; rep++) {
        int u = t + rep * 256;
        int row = u >> 4, c8 = (u & 15) * 8;
        *(uint4*)&sQ[row*QSTR + c8] =
            *(const uint4*)(g_Qf + hbase + (size_t)(qi0 + row) * DHEAD + c8);
    }

    // KV async stage loader: K single, V hi/lo (32 rows each)
    auto issueKV = [&](int kt) {
        uint32_t sb = ub + OFF_KV + (kt & 1) * KVSTAGE;
        const int kj0 = kt * BK;
        #pragma unroll
        for (int rep = 0; rep < 2; rep++) {
            int u = t + rep * 256;
            int row = u >> 4, c8 = (u & 15) * 8;
            uint32_t so = (uint32_t)(row * KSTR + c8) * 2;
            size_t   go = hbase + (size_t)(kj0 + row) * DHEAD + c8;
            cpa16(sb + so,          g_Kf + go);
            cpa16(sb + KARR + so,   g_Vh + go);
            cpa16(sb + 2*KARR + so, g_Vl + go);
        }
        CP_COMMIT();
    };
    issueKV(0);

    float o[16][4];
    #pragma unroll
    for (int nt = 0; nt < 16; nt++)
        #pragma unroll
        for (int q = 0; q < 4; q++)
            o[nt][q] = 0.f;
    float m0r = -1e30f, m8r = -1e30f, l0r = 0.f, l8r = 0.f;
    const int r0g = qi0 + wid*16 + g;

    for (int kt = 0; kt < SEQ / BK; kt++) {
        const int kj0 = kt * BK;
        CP_WAIT0();
        __syncthreads();
        if (kt + 1 < SEQ / BK) issueKV(kt + 1);

        const uint32_t sb  = ub + OFF_KV + (kt & 1) * KVSTAGE;
        const uint32_t uK  = sb;
        const uint32_t uVh = sb + KARR, uVl = sb + 2*KARR;

        // ---- S = Q K^T : warp tile 16 x 32, single product ----
        float sacc[4][4];
        #pragma unroll
        for (int nt = 0; nt < 4; nt++)
            #pragma unroll
            for (int q = 0; q < 4; q++)
                sacc[nt][q] = 0.f;

        #pragma unroll
        for (int kk = 0; kk < 8; kk++) {
            uint32_t qa[4], kb[2][4];
            uint32_t qoff = (uint32_t)((wid*16 + lrow)*QSTR + kk*16 + lcol*8) * 2;
            ldm4(qa, uQ + qoff);
            #pragma unroll
            for (int n2 = 0; n2 < 2; n2++) {
                uint32_t koff = (uint32_t)((n2*16 + lrow)*KSTR + kk*16 + lcol*8) * 2;
                ldm4(kb[n2], uK + koff);
            }
            #pragma unroll
            for (int nt = 0; nt < 4; nt++) {
                int n2 = nt >> 1, hb = nt & 1;
                mma16816(sacc[nt], qa, kb[n2][hb], kb[n2][hb+2]);
            }
        }

        // ---- scale + mask + alibi, row max (intra-warp only) ----
        float rmax0 = -1e30f, rmax8 = -1e30f;
        #pragma unroll
        for (int nt = 0; nt < 4; nt++) {
            int col = kj0 + nt*8 + 2*tq;
            float2 av  = *(const float2*)(alibi + (size_t)h * SEQ + col);
            float2 mv0 = *(const float2*)(mask + (size_t)r0g * SEQ + col);
            float2 mv1 = *(const float2*)(mask + (size_t)(r0g + 8) * SEQ + col);
            sacc[nt][0] = fmaf(sacc[nt][0], SCALE, mv0.x + av.x);
            sacc[nt][1] = fmaf(sacc[nt][1], SCALE, mv0.y + av.y);
            sacc[nt][2] = fmaf(sacc[nt][2], SCALE, mv1.x + av.x);
            sacc[nt][3] = fmaf(sacc[nt][3], SCALE, mv1.y + av.y);
            rmax0 = fmaxf(rmax0, fmaxf(sacc[nt][0], sacc[nt][1]));
            rmax8 = fmaxf(rmax8, fmaxf(sacc[nt][2], sacc[nt][3]));
        }
        #pragma unroll
        for (int off = 1; off <= 2; off <<= 1) {
            rmax0 = fmaxf(rmax0, __shfl_xor_sync(0xffffffffu, rmax0, off));
            rmax8 = fmaxf(rmax8, __shfl_xor_sync(0xffffffffu, rmax8, off));
        }

        float nm0 = fmaxf(m0r, rmax0), nm8 = fmaxf(m8r, rmax8);
        float c0 = __expf(m0r - nm0),  c8 = __expf(m8r - nm8);
        m0r = nm0; m8r = nm8;

        // ---- exp + pack P fragments (single fp16) ----
        float rs0 = 0.f, rs8 = 0.f;
        uint32_t ph[2][4];
        #pragma unroll
        for (int kk = 0; kk < 2; kk++) {
            #pragma unroll
            for (int half = 0; half < 2; half++) {
                int nt = 2*kk + half;
                float p0 = __expf(sacc[nt][0] - nm0);
                float p1 = __expf(sacc[nt][1] - nm0);
                float p2 = __expf(sacc[nt][2] - nm8);
                float p3 = __expf(sacc[nt][3] - nm8);
                rs0 += p0 + p1; rs8 += p2 + p3;
                ph[kk][half*2+0] = packh2(__float2half_rn(p0), __float2half_rn(p1));
                ph[kk][half*2+1] = packh2(__float2half_rn(p2), __float2half_rn(p3));
            }
        }
        #pragma unroll
        for (int off = 1; off <= 2; off <<= 1) {
            rs0 += __shfl_xor_sync(0xffffffffu, rs0, off);
            rs8 += __shfl_xor_sync(0xffffffffu, rs8, off);
        }
        l0r = l0r * c0 + rs0;
        l8r = l8r * c8 + rs8;

        // ---- rescale O ----
        #pragma unroll
        for (int nt = 0; nt < 16; nt++) {
            o[nt][0] *= c0; o[nt][1] *= c0;
            o[nt][2] *= c8; o[nt][3] *= c8;
        }

        // ---- O += P (Vh + Vl) : 2-product ----
        #pragma unroll
        for (int kk = 0; kk < 2; kk++) {
            #pragma unroll
            for (int dd = 0; dd < 8; dd++) {
                uint32_t vh_[4], vl_[4];
                uint32_t voff = (uint32_t)((kk*16 + lrow)*KSTR + dd*16 + lcol*8) * 2;
                ldm4t(vh_, uVh + voff);
                ldm4t(vl_, uVl + voff);
                mma16816(o[dd*2+0], ph[kk], vh_[0], vh_[1]);
                mma16816(o[dd*2+0], ph[kk], vl_[0], vl_[1]);
                mma16816(o[dd*2+1], ph[kk], vh_[2], vh_[3]);
                mma16816(o[dd*2+1], ph[kk], vl_[2], vl_[3]);
            }
        }
    }

    // ---- epilogue: normalize, split to fp16 hi/lo ctx [tok][h*128+d] ----
    float inv0 = 1.f / l0r, inv8 = 1.f / l8r;
    size_t tok0 = ((size_t)(b*SEQ + qi0 + wid*16 + g)) * HID + h * DHEAD;
    size_t tok8 = tok0 + (size_t)8 * HID;
    #pragma unroll
    for (int nt = 0; nt < 16; nt++) {
        int d = nt*8 + 2*tq;
        uint32_t hp, lp;
        split2packh(o[nt][0]*inv0, o[nt][1]*inv0, hp, lp);
        *(uint32_t*)&g_ch[tok0 + d] = hp;
        *(uint32_t*)&g_cl[tok0 + d] = lp;
        split2packh(o[nt][2]*inv8, o[nt][3]*inv8, hp, lp);
        *(uint32_t*)&g_ch[tok8 + d] = hp;
        *(uint32_t*)&g_cl[tok8 + d] = lp;
    }
}

// ---------------------------------------------------------------------------
extern "C" void kernel_launch(void* const* d_in, const int* in_sizes, int n_in,
                              void* d_out, int out_size)
{
    const float* x     = (const float*)d_in[0];
    const float* mask  = (const float*)d_in[1];
    const float* alibi = (const float*)d_in[2];
    const float* freqs = (const float*)d_in[3];
    const float* W[4]  = { (const float*)d_in[4], (const float*)d_in[5],
                           (const float*)d_in[6], (const float*)d_in[7] };
    float* out = (float*)d_out;
    (void)in_sizes; (void)n_in; (void)out_size;

    cudaFuncSetAttribute(flash_mma,
                         cudaFuncAttributeMaxDynamicSharedMemorySize, FLASH_SMEM);
    cudaFuncSetAttribute(mma_gemm_qkv,
                         cudaFuncAttributeMaxDynamicSharedMemorySize, GEMM_SMEM);
    cudaFuncSetAttribute(mma_gemm_o,
                         cudaFuncAttributeMaxDynamicSharedMemorySize, GEMM_SMEM);

    h16 *xh, *xl, *ch, *cl, *whbase, *wlbase;
    cudaGetSymbolAddress((void**)&xh, g_xh);
    cudaGetSymbolAddress((void**)&xl, g_xl);
    cudaGetSymbolAddress((void**)&ch, g_ch);
    cudaGetSymbolAddress((void**)&cl, g_cl);
    cudaGetSymbolAddress((void**)&whbase, g_wh);
    cudaGetSymbolAddress((void**)&wlbase, g_wl);

    {
        int total = (NTOK * HID + 4 * HID * HID) / 4;
        split_all<<<(total + 255) / 256, 256>>>(
            x, W[0], W[1], W[2], W[3], xh, xl, whbase, wlbase);
        build_cs<<<(SEQ * DHEAD) / 256, 256>>>(freqs);
    }

    // Fused Q/K (1-product + RoPE) and V (3-product) projections
    mma_gemm_qkv<<<dim3(48, NTOK/128), 256, GEMM_SMEM>>>(xh, xl, whbase, wlbase);

    flash_mma<<<dim3(SEQ/BQ, NBATCH*NHEAD), 256, FLASH_SMEM>>>(mask, alibi);

    // O projection: 3-product (direct path)
    mma_gemm_o<<<dim3(16, NTOK/128), 256, GEMM_SMEM>>>(
        ch, cl, whbase + 3*(size_t)HID*HID, wlbase + 3*(size_t)HID*HID, out);
}

// round 11
// speedup vs baseline: 4.6158x; 1.2011x over previous
#include <cuda_runtime.h>
#include <cuda_fp16.h>
#include <math.h>
#include <cstdint>

typedef __half h16;

// Problem constants
#define NBATCH 2
#define SEQ    2048
#define NHEAD  16
#define DHEAD  128
#define HID    2048
#define NTOK   4096   // NBATCH*SEQ

// Scratch (device globals — no runtime allocation allowed)
__device__ h16 g_Qf[NBATCH*NHEAD*SEQ*DHEAD];    // post-RoPE, single fp16
__device__ h16 g_Kf[NBATCH*NHEAD*SEQ*DHEAD];
__device__ h16 g_Vh[NBATCH*NHEAD*SEQ*DHEAD];    // V hi/lo fp16 (direct path)
__device__ h16 g_Vl[NBATCH*NHEAD*SEQ*DHEAD];

__device__ h16 g_xh[(size_t)NTOK*HID];          // x single fp16
__device__ h16 g_ch[(size_t)NTOK*HID];          // ctx single fp16 (flash output)
__device__ h16 g_wh[4][(size_t)HID*HID];        // weights hi/lo
__device__ h16 g_wl[4][(size_t)HID*HID];

__device__ float2 g_cs[SEQ*DHEAD];              // (cos, sin) of freqs

// ---------------------------------------------------------------------------
// helpers
// ---------------------------------------------------------------------------
__device__ __forceinline__ uint32_t smem_u32(const void* p) {
    uint32_t a;
    asm("{ .reg .u64 t; cvta.to.shared.u64 t, %1; cvt.u32.u64 %0, t; }"
        : "=r"(a) : "l"(p));
    return a;
}
__device__ __forceinline__ void ldm4(uint32_t* r, uint32_t addr) {
    asm volatile("ldmatrix.sync.aligned.m8n8.x4.shared.b16 {%0,%1,%2,%3},[%4];"
                 : "=r"(r[0]), "=r"(r[1]), "=r"(r[2]), "=r"(r[3]) : "r"(addr));
}
__device__ __forceinline__ void ldm4t(uint32_t* r, uint32_t addr) {
    asm volatile("ldmatrix.sync.aligned.m8n8.x4.trans.shared.b16 {%0,%1,%2,%3},[%4];"
                 : "=r"(r[0]), "=r"(r[1]), "=r"(r[2]), "=r"(r[3]) : "r"(addr));
}
__device__ __forceinline__ void mma16816(float* d, const uint32_t* a,
                                         uint32_t b0, uint32_t b1) {
    asm volatile(
        "mma.sync.aligned.m16n8k16.row.col.f32.f16.f16.f32 "
        "{%0,%1,%2,%3},{%4,%5,%6,%7},{%8,%9},{%0,%1,%2,%3};"
        : "+f"(d[0]), "+f"(d[1]), "+f"(d[2]), "+f"(d[3])
        : "r"(a[0]), "r"(a[1]), "r"(a[2]), "r"(a[3]), "r"(b0), "r"(b1));
}
__device__ __forceinline__ uint32_t packh2(h16 a, h16 b) {
    return ((uint32_t)__half_as_ushort(b) << 16) | __half_as_ushort(a);
}
__device__ __forceinline__ void split1h(float v, h16& h, h16& l) {
    h = __float2half_rn(v);
    l = __float2half_rn(v - __half2float(h));
}
__device__ __forceinline__ void split2packh(float a, float b,
                                            uint32_t& hp, uint32_t& lp) {
    h16 ha, la, hb, lb;
    split1h(a, ha, la);
    split1h(b, hb, lb);
    hp = packh2(ha, hb);
    lp = packh2(la, lb);
}
__device__ __forceinline__ void cpa16(uint32_t s, const void* g) {
    asm volatile("cp.async.cg.shared.global [%0], [%1], 16;" :: "r"(s), "l"(g));
}
#define CP_COMMIT() asm volatile("cp.async.commit_group;" ::: "memory")
#define CP_WAIT0()  asm volatile("cp.async.wait_group 0;" ::: "memory")

// ---------------------------------------------------------------------------
// cos/sin table from freqs
// ---------------------------------------------------------------------------
__global__ __launch_bounds__(256)
void build_cs(const float* __restrict__ freqs)
{
    int i = blockIdx.x * 256 + threadIdx.x;
    float f = freqs[i];
    g_cs[i] = make_float2(cosf(f), sinf(f));
}

// ---------------------------------------------------------------------------
// Fused split: x -> single fp16; 4 weights -> fp16 hi + lo. One launch.
// ---------------------------------------------------------------------------
__global__ __launch_bounds__(256)
void split_all(const float* __restrict__ x,
               const float* __restrict__ w0, const float* __restrict__ w1,
               const float* __restrict__ w2, const float* __restrict__ w3,
               h16* __restrict__ xh,
               h16* __restrict__ whb, h16* __restrict__ wlb)
{
    const int XQ = NTOK * HID / 4;
    const int WQ = HID * HID / 4;
    int i = blockIdx.x * 256 + threadIdx.x;
    if (i < XQ) {
        float4 v = ((const float4*)x)[i];
        ((uint2*)xh)[i] = make_uint2(
            packh2(__float2half_rn(v.x), __float2half_rn(v.y)),
            packh2(__float2half_rn(v.z), __float2half_rn(v.w)));
        return;
    }
    int j = i - XQ;
    int widx = j >> 20;
    int off = j & (WQ - 1);
    const float* src = (widx == 0) ? w0 : (widx == 1) ? w1 : (widx == 2) ? w2 : w3;
    h16* dh = whb + (size_t)widx * HID * HID;
    h16* dl = wlb + (size_t)widx * HID * HID;
    float4 v = ((const float4*)src)[off];
    float vv[4] = {v.x, v.y, v.z, v.w};
    h16 hh[4], ll[4];
    #pragma unroll
    for (int q = 0; q < 4; q++) split1h(vv[q], hh[q], ll[q]);
    ((uint2*)dh)[off] = make_uint2(packh2(hh[0], hh[1]), packh2(hh[2], hh[3]));
    ((uint2*)dl)[off] = make_uint2(packh2(ll[0], ll[1]), packh2(ll[2], ll[3]));
}

// ---------------------------------------------------------------------------
// GEMM core: 128x128 tile, cp.async 2-stage, NPROD in {1,2}.
// NPROD=1: D = A·Bh          (A single, B hi)
// NPROD=2: D = A·Bh + A·Bl   (A single, B hi/lo — weight-exact)
// ropePerm permutes B smem rows so accumulators pair (d, d+64).
// ---------------------------------------------------------------------------
#define SPAD 40
#define ARR_B   (128*SPAD*2)          // 10240
#define GEMM_SMEM (2 * 3 * ARR_B)     // 61440 (NPROD=2; NPROD=1 uses 2 arrays)

template<int NPROD>
__device__ __forceinline__ void gemm_core(
    const h16* __restrict__ pA,
    const h16* __restrict__ pBh, const h16* __restrict__ pBl,
    uint32_t ub, bool ropePerm, float acc[4][4][4])
{
    constexpr int STB = (NPROD == 2 ? 3 : 2) * ARR_B;
    const int t    = threadIdx.x;
    const int wid  = t >> 5;
    const int lane = t & 31;
    const int wm   = wid & 1;
    const int wn   = wid >> 1;
    const int lrow = lane & 15, lcol = lane >> 4;

    int rowL[2], qdL[2];
    #pragma unroll
    for (int r = 0; r < 2; r++) {
        int u = t + (r << 8);
        rowL[r] = u >> 2;
        qdL[r]  = u & 3;
    }

    #pragma unroll
    for (int i = 0; i < 4; i++)
        #pragma unroll
        for (int j = 0; j < 4; j++)
            #pragma unroll
            for (int q = 0; q < 4; q++)
                acc[i][j][q] = 0.f;

    const int NCH = HID / 32;

    auto issue = [&](int c, int buf) {
        uint32_t sb = ub + buf * STB;
        #pragma unroll
        for (int r = 0; r < 2; r++) {
            int row = rowL[r], qd = qdL[r];
            int brow = row;
            if (ropePerm) {
                int gg = row >> 5, ss = row & 31;
                brow = (ss < 16) ? gg*16 + ss : 64 + gg*16 + (ss - 16);
            }
            uint32_t so = (uint32_t)(row * SPAD + qd * 8) * 2;
            size_t   goA = (size_t)row  * HID + (size_t)c * 32 + qd * 8;
            size_t   goB = (size_t)brow * HID + (size_t)c * 32 + qd * 8;
            cpa16(sb + so,           pA + goA);
            cpa16(sb + ARR_B + so,   pBh + goB);
            if (NPROD == 2) cpa16(sb + 2*ARR_B + so, pBl + goB);
        }
        CP_COMMIT();
    };

    issue(0, 0);

    for (int c = 0; c < NCH; c++) {
        CP_WAIT0();
        __syncthreads();
        if (c + 1 < NCH) issue(c + 1, (c + 1) & 1);

        const uint32_t sb  = ub + (c & 1) * STB;
        const uint32_t uA  = sb;
        const uint32_t uBh = sb + ARR_B;
        const uint32_t uBl = sb + 2*ARR_B;

        #pragma unroll
        for (int kh = 0; kh < 2; kh++) {
            uint32_t ah[4][4], bh[2][4], bl[2][4];
            #pragma unroll
            for (int mt = 0; mt < 4; mt++) {
                uint32_t off = (uint32_t)((wm*64 + mt*16 + lrow) * SPAD + kh*16 + lcol*8) * 2;
                ldm4(ah[mt], uA + off);
            }
            #pragma unroll
            for (int n2 = 0; n2 < 2; n2++) {
                uint32_t off = (uint32_t)((wn*32 + n2*16 + lrow) * SPAD + kh*16 + lcol*8) * 2;
                ldm4(bh[n2], uBh + off);
                if (NPROD == 2) ldm4(bl[n2], uBl + off);
            }
            #pragma unroll
            for (int mt = 0; mt < 4; mt++)
                #pragma unroll
                for (int nt = 0; nt < 4; nt++) {
                    int n2 = nt >> 1, hb = nt & 1;
                    mma16816(acc[mt][nt], ah[mt], bh[n2][hb], bh[n2][hb+2]);
                    if (NPROD == 2)
                        mma16816(acc[mt][nt], ah[mt], bl[n2][hb], bl[n2][hb+2]);
                }
        }
    }
}

// ---------------------------------------------------------------------------
// Fused QKV projection launch. grid (48, 32):
//   widx = bx>>4: 0 -> Q (1-product + RoPE), 1 -> K (same), 2 -> V (2-product).
// ---------------------------------------------------------------------------
__global__ __launch_bounds__(256)
void mma_gemm_qkv(const h16* __restrict__ xh,
                  const h16* __restrict__ whb, const h16* __restrict__ wlb)
{
    extern __shared__ char dsm[];
    const uint32_t ub = smem_u32(dsm);

    const int t    = threadIdx.x;
    const int wid  = t >> 5;
    const int lane = t & 31;
    const int m0   = blockIdx.y << 7;
    const int wm   = wid & 1;
    const int wn   = wid >> 1;
    const int widx = blockIdx.x >> 4;
    const int n0   = (blockIdx.x & 15) << 7;
    const int h    = n0 >> 7;

    const h16* pA  = xh + (size_t)m0 * HID;
    const h16* pBh = whb + (size_t)widx * HID * HID + (size_t)n0 * HID;
    const h16* pBl = wlb + (size_t)widx * HID * HID + (size_t)n0 * HID;

    float acc[4][4][4];
    const int rbase = wm*64 + (lane >> 2);

    if (widx < 2) {
        gemm_core<1>(pA, pBh, nullptr, ub, true, acc);
        // RoPE epilogue, write single fp16 bhsd
        h16* outp = (widx == 0) ? g_Qf : g_Kf;
        const int dd0 = wn*16 + 2*(lane & 3);
        #pragma unroll
        for (int mt = 0; mt < 4; mt++)
            #pragma unroll
            for (int ntp = 0; ntp < 2; ntp++) {
                int d = dd0 + ntp*8;
                #pragma unroll
                for (int rr = 0; rr < 2; rr++) {
                    int r0 = m0 + rbase + mt*16 + rr*8;
                    int b  = r0 >> 11;
                    int s  = r0 & (SEQ - 1);
                    const float2* trow = g_cs + (size_t)s * DHEAD;
                    float2 cs1a = trow[d],      cs1b = trow[d+1];
                    float2 cs2a = trow[d+64],   cs2b = trow[d+65];
                    float x1a = acc[mt][ntp][rr*2+0],   x1b = acc[mt][ntp][rr*2+1];
                    float x2a = acc[mt][ntp+2][rr*2+0], x2b = acc[mt][ntp+2][rr*2+1];
                    float y1a = x1a*cs1a.x - x2a*cs1a.y;
                    float y1b = x1b*cs1b.x - x2b*cs1b.y;
                    float y2a = x2a*cs2a.x + x1a*cs2a.y;
                    float y2b = x2b*cs2b.x + x1b*cs2b.y;
                    size_t base = (((size_t)(b*NHEAD + h))*SEQ + s)*DHEAD;
                    *(uint32_t*)&outp[base + d] =
                        packh2(__float2half_rn(y1a), __float2half_rn(y1b));
                    *(uint32_t*)&outp[base + d + 64] =
                        packh2(__float2half_rn(y2a), __float2half_rn(y2b));
                }
            }
    } else {
        gemm_core<2>(pA, pBh, pBl, ub, false, acc);
        // V epilogue: h16 hi/lo bhsd (V tensor stays exact for PV)
        const int cbase = wn*32 + 2*(lane & 3);
        #pragma unroll
        for (int mt = 0; mt < 4; mt++)
            #pragma unroll
            for (int nt = 0; nt < 4; nt++) {
                int r0 = m0 + rbase + mt*16;
                int b  = r0 >> 11;
                int s  = r0 & (SEQ - 1);
                int d  = cbase + nt*8;
                size_t base = (((size_t)(b*NHEAD + h))*SEQ + s)*DHEAD + d;
                uint32_t hp, lp;
                split2packh(acc[mt][nt][0], acc[mt][nt][1], hp, lp);
                *(uint32_t*)&g_Vh[base] = hp;
                *(uint32_t*)&g_Vl[base] = lp;
                split2packh(acc[mt][nt][2], acc[mt][nt][3], hp, lp);
                *(uint32_t*)&g_Vh[base + 8*DHEAD] = hp;
                *(uint32_t*)&g_Vl[base + 8*DHEAD] = lp;
            }
    }
}

// ---------------------------------------------------------------------------
// Final O projection: 2-product (ctx single, Wo hi/lo), fp32 output.
// ---------------------------------------------------------------------------
__global__ __launch_bounds__(256)
void mma_gemm_o(const h16* __restrict__ ch,
                const h16* __restrict__ wh, const h16* __restrict__ wl,
                float* __restrict__ Cout)
{
    extern __shared__ char dsm[];
    const uint32_t ub = smem_u32(dsm);

    const int t    = threadIdx.x;
    const int wid  = t >> 5;
    const int lane = t & 31;
    const int m0   = blockIdx.y << 7;
    const int n0   = blockIdx.x << 7;
    const int wm   = wid & 1;
    const int wn   = wid >> 1;

    float acc[4][4][4];
    gemm_core<2>(ch + (size_t)m0 * HID,
                 wh + (size_t)n0 * HID, wl + (size_t)n0 * HID,
                 ub, false, acc);

    const int rbase = wm*64 + (lane >> 2);
    const int cbase = wn*32 + 2*(lane & 3);
    #pragma unroll
    for (int mt = 0; mt < 4; mt++)
        #pragma unroll
        for (int nt = 0; nt < 4; nt++) {
            int r0 = m0 + rbase + mt*16;
            int cc = n0 + cbase + nt*8;
            *(float2*)&Cout[(size_t)r0 * HID + cc]       = make_float2(acc[mt][nt][0], acc[mt][nt][1]);
            *(float2*)&Cout[(size_t)(r0 + 8) * HID + cc] = make_float2(acc[mt][nt][2], acc[mt][nt][3]);
        }
}

// ---------------------------------------------------------------------------
// Flash attention: BK=32, K/V cp.async double-buffered, 2 CTAs/SM.
// Warp owns 16 q-rows x full BK; P in registers; intra-warp softmax.
// Epilogue writes ctx as SINGLE fp16 (error washes via O-proj averaging).
// ---------------------------------------------------------------------------
#define BQ 128
#define BK 32
#define QSTR 136
#define KSTR 136
#define QARR (128*QSTR*2)        // 34816
#define KARR (32*KSTR*2)         // 8704 per KV array
#define KVSTAGE (3*KARR)         // 26112
#define OFF_KV QARR
#define FLASH_SMEM (QARR + 2*KVSTAGE)   // 87040

__global__ __launch_bounds__(256, 2)
void flash_mma(const float* __restrict__ mask, const float* __restrict__ alibi)
{
    extern __shared__ char sm[];
    const uint32_t ub = smem_u32(sm);
    const uint32_t uQ = ub;
    h16* sQ = (h16*)sm;

    const int t    = threadIdx.x;
    const int lane = t & 31;
    const int wid  = t >> 5;
    const int qb   = blockIdx.x;
    const int bhid = blockIdx.y;
    const int h    = bhid & (NHEAD - 1);
    const int b    = bhid >> 4;
    const int qi0  = qb * BQ;
    const size_t hbase = (size_t)bhid * SEQ * DHEAD;

    const int lrow = lane & 15, lcol = lane >> 4;
    const int g = lane >> 2, tq = lane & 3;
    const float SCALE = 0.08838834764831845f;  // 1/sqrt(128)

    // Q tile load (sync stores)
    #pragma unroll
    for (int rep = 0; rep < 8; rep++) {
        int u = t + rep * 256;
        int row = u >> 4, c8 = (u & 15) * 8;
        *(uint4*)&sQ[row*QSTR + c8] =
            *(const uint4*)(g_Qf + hbase + (size_t)(qi0 + row) * DHEAD + c8);
    }

    // KV async stage loader: K single, V hi/lo (32 rows each)
    auto issueKV = [&](int kt) {
        uint32_t sb = ub + OFF_KV + (kt & 1) * KVSTAGE;
        const int kj0 = kt * BK;
        #pragma unroll
        for (int rep = 0; rep < 2; rep++) {
            int u = t + rep * 256;
            int row = u >> 4, c8 = (u & 15) * 8;
            uint32_t so = (uint32_t)(row * KSTR + c8) * 2;
            size_t   go = hbase + (size_t)(kj0 + row) * DHEAD + c8;
            cpa16(sb + so,          g_Kf + go);
            cpa16(sb + KARR + so,   g_Vh + go);
            cpa16(sb + 2*KARR + so, g_Vl + go);
        }
        CP_COMMIT();
    };
    issueKV(0);

    float o[16][4];
    #pragma unroll
    for (int nt = 0; nt < 16; nt++)
        #pragma unroll
        for (int q = 0; q < 4; q++)
            o[nt][q] = 0.f;
    float m0r = -1e30f, m8r = -1e30f, l0r = 0.f, l8r = 0.f;
    const int r0g = qi0 + wid*16 + g;

    for (int kt = 0; kt < SEQ / BK; kt++) {
        const int kj0 = kt * BK;
        CP_WAIT0();
        __syncthreads();
        if (kt + 1 < SEQ / BK) issueKV(kt + 1);

        const uint32_t sb  = ub + OFF_KV + (kt & 1) * KVSTAGE;
        const uint32_t uK  = sb;
        const uint32_t uVh = sb + KARR, uVl = sb + 2*KARR;

        // ---- S = Q K^T : warp tile 16 x 32, single product ----
        float sacc[4][4];
        #pragma unroll
        for (int nt = 0; nt < 4; nt++)
            #pragma unroll
            for (int q = 0; q < 4; q++)
                sacc[nt][q] = 0.f;

        #pragma unroll
        for (int kk = 0; kk < 8; kk++) {
            uint32_t qa[4], kb[2][4];
            uint32_t qoff = (uint32_t)((wid*16 + lrow)*QSTR + kk*16 + lcol*8) * 2;
            ldm4(qa, uQ + qoff);
            #pragma unroll
            for (int n2 = 0; n2 < 2; n2++) {
                uint32_t koff = (uint32_t)((n2*16 + lrow)*KSTR + kk*16 + lcol*8) * 2;
                ldm4(kb[n2], uK + koff);
            }
            #pragma unroll
            for (int nt = 0; nt < 4; nt++) {
                int n2 = nt >> 1, hb = nt & 1;
                mma16816(sacc[nt], qa, kb[n2][hb], kb[n2][hb+2]);
            }
        }

        // ---- scale + mask + alibi, row max (intra-warp only) ----
        float rmax0 = -1e30f, rmax8 = -1e30f;
        #pragma unroll
        for (int nt = 0; nt < 4; nt++) {
            int col = kj0 + nt*8 + 2*tq;
            float2 av  = *(const float2*)(alibi + (size_t)h * SEQ + col);
            float2 mv0 = *(const float2*)(mask + (size_t)r0g * SEQ + col);
            float2 mv1 = *(const float2*)(mask + (size_t)(r0g + 8) * SEQ + col);
            sacc[nt][0] = fmaf(sacc[nt][0], SCALE, mv0.x + av.x);
            sacc[nt][1] = fmaf(sacc[nt][1], SCALE, mv0.y + av.y);
            sacc[nt][2] = fmaf(sacc[nt][2], SCALE, mv1.x + av.x);
            sacc[nt][3] = fmaf(sacc[nt][3], SCALE, mv1.y + av.y);
            rmax0 = fmaxf(rmax0, fmaxf(sacc[nt][0], sacc[nt][1]));
            rmax8 = fmaxf(rmax8, fmaxf(sacc[nt][2], sacc[nt][3]));
        }
        #pragma unroll
        for (int off = 1; off <= 2; off <<= 1) {
            rmax0 = fmaxf(rmax0, __shfl_xor_sync(0xffffffffu, rmax0, off));
            rmax8 = fmaxf(rmax8, __shfl_xor_sync(0xffffffffu, rmax8, off));
        }

        float nm0 = fmaxf(m0r, rmax0), nm8 = fmaxf(m8r, rmax8);
        float c0 = __expf(m0r - nm0),  c8 = __expf(m8r - nm8);
        m0r = nm0; m8r = nm8;

        // ---- exp + pack P fragments (single fp16) ----
        float rs0 = 0.f, rs8 = 0.f;
        uint32_t ph[2][4];
        #pragma unroll
        for (int kk = 0; kk < 2; kk++) {
            #pragma unroll
            for (int half = 0; half < 2; half++) {
                int nt = 2*kk + half;
                float p0 = __expf(sacc[nt][0] - nm0);
                float p1 = __expf(sacc[nt][1] - nm0);
                float p2 = __expf(sacc[nt][2] - nm8);
                float p3 = __expf(sacc[nt][3] - nm8);
                rs0 += p0 + p1; rs8 += p2 + p3;
                ph[kk][half*2+0] = packh2(__float2half_rn(p0), __float2half_rn(p1));
                ph[kk][half*2+1] = packh2(__float2half_rn(p2), __float2half_rn(p3));
            }
        }
        #pragma unroll
        for (int off = 1; off <= 2; off <<= 1) {
            rs0 += __shfl_xor_sync(0xffffffffu, rs0, off);
            rs8 += __shfl_xor_sync(0xffffffffu, rs8, off);
        }
        l0r = l0r * c0 + rs0;
        l8r = l8r * c8 + rs8;

        // ---- rescale O ----
        #pragma unroll
        for (int nt = 0; nt < 16; nt++) {
            o[nt][0] *= c0; o[nt][1] *= c0;
            o[nt][2] *= c8; o[nt][3] *= c8;
        }

        // ---- O += P (Vh + Vl) : 2-product ----
        #pragma unroll
        for (int kk = 0; kk < 2; kk++) {
            #pragma unroll
            for (int dd = 0; dd < 8; dd++) {
                uint32_t vh_[4], vl_[4];
                uint32_t voff = (uint32_t)((kk*16 + lrow)*KSTR + dd*16 + lcol*8) * 2;
                ldm4t(vh_, uVh + voff);
                ldm4t(vl_, uVl + voff);
                mma16816(o[dd*2+0], ph[kk], vh_[0], vh_[1]);
                mma16816(o[dd*2+0], ph[kk], vl_[0], vl_[1]);
                mma16816(o[dd*2+1], ph[kk], vh_[2], vh_[3]);
                mma16816(o[dd*2+1], ph[kk], vl_[2], vl_[3]);
            }
        }
    }

    // ---- epilogue: normalize, write ctx as single fp16 [tok][h*128+d] ----
    float inv0 = 1.f / l0r, inv8 = 1.f / l8r;
    size_t tok0 = ((size_t)(b*SEQ + qi0 + wid*16 + g)) * HID + h * DHEAD;
    size_t tok8 = tok0 + (size_t)8 * HID;
    #pragma unroll
    for (int nt = 0; nt < 16; nt++) {
        int d = nt*8 + 2*tq;
        *(uint32_t*)&g_ch[tok0 + d] =
            packh2(__float2half_rn(o[nt][0]*inv0), __float2half_rn(o[nt][1]*inv0));
        *(uint32_t*)&g_ch[tok8 + d] =
            packh2(__float2half_rn(o[nt][2]*inv8), __float2half_rn(o[nt][3]*inv8));
    }
}

// ---------------------------------------------------------------------------
extern "C" void kernel_launch(void* const* d_in, const int* in_sizes, int n_in,
                              void* d_out, int out_size)
{
    const float* x     = (const float*)d_in[0];
    const float* mask  = (const float*)d_in[1];
    const float* alibi = (const float*)d_in[2];
    const float* freqs = (const float*)d_in[3];
    const float* W[4]  = { (const float*)d_in[4], (const float*)d_in[5],
                           (const float*)d_in[6], (const float*)d_in[7] };
    float* out = (float*)d_out;
    (void)in_sizes; (void)n_in; (void)out_size;

    cudaFuncSetAttribute(flash_mma,
                         cudaFuncAttributeMaxDynamicSharedMemorySize, FLASH_SMEM);
    cudaFuncSetAttribute(mma_gemm_qkv,
                         cudaFuncAttributeMaxDynamicSharedMemorySize, GEMM_SMEM);
    cudaFuncSetAttribute(mma_gemm_o,
                         cudaFuncAttributeMaxDynamicSharedMemorySize, GEMM_SMEM);

    h16 *xh, *ch, *whbase, *wlbase;
    cudaGetSymbolAddress((void**)&xh, g_xh);
    cudaGetSymbolAddress((void**)&ch, g_ch);
    cudaGetSymbolAddress((void**)&whbase, g_wh);
    cudaGetSymbolAddress((void**)&wlbase, g_wl);

    {
        int total = (NTOK * HID + 4 * HID * HID) / 4;
        split_all<<<(total + 255) / 256, 256>>>(
            x, W[0], W[1], W[2], W[3], xh, whbase, wlbase);
        build_cs<<<(SEQ * DHEAD) / 256, 256>>>(freqs);
    }

    // Fused Q/K (1-product + RoPE) and V (2-product) projections
    mma_gemm_qkv<<<dim3(48, NTOK/128), 256, GEMM_SMEM>>>(xh, whbase, wlbase);

    flash_mma<<<dim3(SEQ/BQ, NBATCH*NHEAD), 256, FLASH_SMEM>>>(mask, alibi);

    // O projection: 2-product (ctx single, Wo hi/lo)
    mma_gemm_o<<<dim3(16, NTOK/128), 256, GEMM_SMEM>>>(
        ch, whbase + 3*(size_t)HID*HID, wlbase + 3*(size_t)HID*HID, out);
}